// round 5
// baseline (speedup 1.0000x reference)
#include <cuda_runtime.h>
#include <cuda_bf16.h>
#include <math.h>

#define NN 100000
#define EE 500000
#define BB 8192

// ---------------- scratch (device globals) ----------------------------------
__device__ float g_feat[2][NN * 64];       // per metapath
__device__ float g_z[4][NN * 64];          // [type*2 + m]
__device__ float g_el[2][NN];
__device__ float g_er[2][NN];
__device__ float g_den[2][NN];
__device__ float g_e[2][EE];
__device__ float g_w[4];
__device__ float g_beta[4];

typedef unsigned long long u64t;

// ---------------- helpers ----------------------------------------------------
__device__ __forceinline__ u64t ffma2(u64t a, u64t b, u64t c) {
    u64t d;
    asm("fma.rn.f32x2 %0, %1, %2, %3;" : "=l"(d) : "l"(a), "l"(b), "l"(c));
    return d;
}
__device__ __forceinline__ u64t pack2(float lo, float hi) {
    u64t r; asm("mov.b64 %0, {%1,%2};" : "=l"(r) : "f"(lo), "f"(hi)); return r;
}
__device__ __forceinline__ void unpack2(u64t v, float& lo, float& hi) {
    asm("mov.b64 {%0,%1}, %2;" : "=f"(lo), "=f"(hi) : "l"(v));
}
__device__ __forceinline__ float tanh_fast(float x) {
    float y; asm("tanh.approx.f32 %0, %1;" : "=f"(y) : "f"(x)); return y;
}
__device__ __forceinline__ float elu_fast(float x) {
    return x > 0.f ? x : (__expf(x) - 1.f);
}
__device__ __forceinline__ unsigned int bf2(float lo, float hi) {
    __nv_bfloat162 v = __floats2bfloat162_rn(lo, hi);
    return *reinterpret_cast<unsigned int*>(&v);
}
__device__ __forceinline__ void mma_bf16(
    float& c0, float& c1, float& c2, float& c3,
    unsigned int a0, unsigned int a1, unsigned int a2, unsigned int a3,
    unsigned int b0, unsigned int b1)
{
    asm("mma.sync.aligned.m16n8k16.row.col.f32.bf16.bf16.f32 "
        "{%0,%1,%2,%3}, {%4,%5,%6,%7}, {%8,%9}, {%0,%1,%2,%3};"
        : "+f"(c0), "+f"(c1), "+f"(c2), "+f"(c3)
        : "r"(a0), "r"(a1), "r"(a2), "r"(a3), "r"(b0), "r"(b1));
}

// ---------------- K1: feat GEMM, 4 threads/row (16 cols each), both m -------
// smem: W[2][4096] + al[2][64] + ar[2][64] + hs[64][68]
#define K1_SMEM ((8192 + 128 + 128 + 64 * 68) * 4)

__global__ void __launch_bounds__(256) k_gemm_feat(
    const float* __restrict__ h, const float* __restrict__ W,
    const float* __restrict__ al, const float* __restrict__ ar, int type)
{
    extern __shared__ float smem[];
    float* Ws  = smem;            // 2*4096
    float* als = Ws + 8192;       // 2*64
    float* ars = als + 128;       // 2*64
    float* hs  = ars + 128;       // 64*68

    int tid  = threadIdx.x;
    int row0 = blockIdx.x * 64;

    if (type == 0 && blockIdx.x == 0 && tid < 4) g_w[tid] = 0.0f;

    for (int i = tid; i < 8192; i += 256) Ws[i] = W[i];
    if (tid < 128) { als[tid] = al[tid]; ars[tid] = ar[tid]; }

    int nrows = NN - row0; if (nrows > 64) nrows = 64;
    for (int i = tid; i < nrows * 64; i += 256)
        hs[(i >> 6) * 68 + (i & 63)] = h[(size_t)row0 * 64 + i];
    __syncthreads();

    int r = tid >> 2;            // row in block 0..63
    int q = tid & 3;             // col quarter 0..3 (cols q*16..q*16+16)
    int row = row0 + r;
    bool valid = row < NN;
    const float* hrow = &hs[r * 68];

#pragma unroll
    for (int m = 0; m < 2; m++) {
        u64t acc2[8];
#pragma unroll
        for (int j = 0; j < 8; j++) acc2[j] = 0ull;

        const float* Wm = Ws + m * 4096 + q * 16;
#pragma unroll 2
        for (int k = 0; k < 64; k += 4) {
            float4 h4 = *(const float4*)&hrow[k];
#pragma unroll
            for (int kk = 0; kk < 4; kk++) {
                float hv = (&h4.x)[kk];
                u64t hv2 = pack2(hv, hv);
                const ulonglong2* Wk = (const ulonglong2*)&Wm[(k + kk) * 64];
#pragma unroll
                for (int j = 0; j < 4; j++) {
                    ulonglong2 w = Wk[j];
                    acc2[2 * j + 0] = ffma2(hv2, w.x, acc2[2 * j + 0]);
                    acc2[2 * j + 1] = ffma2(hv2, w.y, acc2[2 * j + 1]);
                }
            }
        }

        const float* alm = als + m * 64 + q * 16;
        const float* arm = ars + m * 64 + q * 16;
        float e_l = 0.0f, e_r = 0.0f;
        float vals[16];
#pragma unroll
        for (int j = 0; j < 8; j++) {
            float a0, a1;
            unpack2(acc2[j], a0, a1);
            vals[2 * j] = a0; vals[2 * j + 1] = a1;
            e_l += a0 * alm[2 * j] + a1 * alm[2 * j + 1];
            e_r += a0 * arm[2 * j] + a1 * arm[2 * j + 1];
        }
        // combine quarters (quad lanes q=0..3 of same row, same warp)
        e_l += __shfl_xor_sync(0xffffffffu, e_l, 1);
        e_r += __shfl_xor_sync(0xffffffffu, e_r, 1);
        e_l += __shfl_xor_sync(0xffffffffu, e_l, 2);
        e_r += __shfl_xor_sync(0xffffffffu, e_r, 2);

        if (valid) {
            float4* fout = (float4*)&g_feat[m][(size_t)row * 64 + q * 16];
            float4* zout = (float4*)&g_z[2 * type + m][(size_t)row * 64 + q * 16];
            float4 z4 = make_float4(0.f, 0.f, 0.f, 0.f);
#pragma unroll
            for (int i = 0; i < 4; i++) {
                fout[i] = make_float4(vals[4 * i], vals[4 * i + 1],
                                      vals[4 * i + 2], vals[4 * i + 3]);
                zout[i] = z4;
            }
            if (q == 0) {
                g_el[m][row] = e_l;
                g_er[m][row] = e_r;
                g_den[m][row] = 0.0f;
            }
        }
    }
}

// ---------------- K2: fused edge score + exp + segment sum (grid.y = m) -----
__global__ void k_edge_score(const int* __restrict__ src, const int* __restrict__ dst)
{
    int m = blockIdx.y;
    int i = blockIdx.x * blockDim.x + threadIdx.x;
    if (i >= EE) return;
    const int* srcm = src + (size_t)m * EE;
    const int* dstm = dst + (size_t)m * EE;
    int s = srcm[i], d = dstm[i];
    float e = g_el[m][s] + g_er[m][d];
    e = (e >= 0.0f) ? e : 0.2f * e;          // leaky_relu 0.2
    float ex = __expf(e);
    g_e[m][i] = ex;
    atomicAdd(&g_den[m][d], ex);
}

// ---------------- K3: alpha * feat[src] scatter-add into z (grid.y = m) -----
__global__ void __launch_bounds__(256) k_edge_aggr(
    const int* __restrict__ src, const int* __restrict__ dst, int type)
{
    int m = blockIdx.y;
    int t = blockIdx.x * 256 + threadIdx.x;
    int edge = t >> 4;
    int lane = t & 15;
    if (edge >= EE) return;
    const int* srcm = src + (size_t)m * EE;
    const int* dstm = dst + (size_t)m * EE;
    int s = srcm[edge], d = dstm[edge];
    float alpha = g_e[m][edge] / (g_den[m][d] + 1e-9f);
    float4 f = *(const float4*)&g_feat[m][(size_t)s * 64 + lane * 4];
    float4 v = make_float4(f.x * alpha, f.y * alpha, f.z * alpha, f.w * alpha);
    float* zp = &g_z[2 * type + m][(size_t)d * 64 + lane * 4];
    asm volatile("red.global.add.v4.f32 [%0], {%1,%2,%3,%4};"
                 :: "l"(zp), "f"(v.x), "f"(v.y), "f"(v.z), "f"(v.w)
                 : "memory");
}

// ---------------- K4: semantic logits via mma.sync bf16 ---------------------
// Per type: for each slot m, sum_n tanh(elu(z+gb) @ W1 + b1) @ W2.
// Block 256 thr = 8 warps. warp w: slot = w/4, cols nq=w%4 -> [nq*32, nq*32+32).
// 32 rows staged per iteration into 144B-stride smem tiles (conflict-free ldmatrix).
#define SEM_TILE_STRIDE 72   // bf16 elems per row (144 B, 9x16B -> conflict-free)

__global__ void __launch_bounds__(256) k_sem_mma(
    const float* __restrict__ uW1, const float* __restrict__ ub1,
    const float* __restrict__ uW2, const float* __restrict__ ugb,
    const float* __restrict__ iW1, const float* __restrict__ ib1,
    const float* __restrict__ iW2, const float* __restrict__ igb)
{
    __shared__ __align__(16) __nv_bfloat16 tile[2][32][SEM_TILE_STRIDE];
    __shared__ float gbs[128];
    __shared__ float wsum[8];

    int t = blockIdx.y;
    const float* W1 = t ? iW1 : uW1;
    const float* b1 = t ? ib1 : ub1;
    const float* W2 = t ? iW2 : uW2;
    const float* gb = t ? igb : ugb;

    int tid  = threadIdx.x;
    int warp = tid >> 5;
    int lane = tid & 31;
    int slot = warp >> 2;        // metapath 0/1
    int nq   = warp & 3;         // column quarter of H=128

    if (tid < 128) gbs[tid] = gb[tid];

    const float* zsl = g_z[2 * t + slot];

    // ---- preload B fragments of W1 (k-major 64x128): [kt][nt][2] ----
    unsigned int bfr[4][4][2];
    {
        int n = nq * 32 + (lane >> 2);   // +nt*8 added below
        int k0 = (lane & 3) * 2;         // +kt*16
#pragma unroll
        for (int kt = 0; kt < 4; kt++) {
            int k = kt * 16 + k0;
#pragma unroll
            for (int nt = 0; nt < 4; nt++) {
                int nn = n + nt * 8;
                bfr[kt][nt][0] = bf2(W1[(size_t)k * 128 + nn],
                                     W1[(size_t)(k + 1) * 128 + nn]);
                bfr[kt][nt][1] = bf2(W1[(size_t)(k + 8) * 128 + nn],
                                     W1[(size_t)(k + 9) * 128 + nn]);
            }
        }
    }
    // ---- per-lane W2 / b1 values for epilogue columns ----
    float w2v[4][2], bsv[4][2];
#pragma unroll
    for (int nt = 0; nt < 4; nt++) {
        int c = nq * 32 + nt * 8 + (lane & 3) * 2;
        w2v[nt][0] = W2[c];     w2v[nt][1] = W2[c + 1];
        bsv[nt][0] = b1[c];     bsv[nt][1] = b1[c + 1];
    }

    // staging coords (256 threads fill both slots: 32 rows x 64 cols)
    int s_slot = tid >> 7;           // 0/1
    int tid2   = tid & 127;
    int s_row  = tid2 >> 2;          // 0..31
    int s_colq = (tid2 & 3) * 16;    // 0,16,32,48

    // ldmatrix source coords
    int ld_row = lane & 15;
    int ld_off = (lane >> 4) * 16;   // bytes

    float s = 0.0f;

    const int NITER = NN / 32;       // 3125
    __syncthreads();
    for (int it = blockIdx.x; it < NITER; it += gridDim.x) {
        int row0 = it * 32;
        // ---- stage: load z, add GAT bias, ELU, convert bf16 ----
        const float* src = zsl;      // but staging covers slot s_slot:
        const float* zrow = (s_slot ? g_z[2 * t + 1] : g_z[2 * t])
                            + (size_t)(row0 + s_row) * 64 + s_colq;
        (void)src;
        unsigned int* drow = (unsigned int*)&tile[s_slot][s_row][0];
#pragma unroll
        for (int i = 0; i < 4; i++) {
            float4 v = *(const float4*)(zrow + 4 * i);
            int c = s_colq + 4 * i;
            unsigned int lo = bf2(elu_fast(v.x + gbs[s_slot * 64 + c]),
                                  elu_fast(v.y + gbs[s_slot * 64 + c + 1]));
            unsigned int hi = bf2(elu_fast(v.z + gbs[s_slot * 64 + c + 2]),
                                  elu_fast(v.w + gbs[s_slot * 64 + c + 3]));
            drow[(s_colq >> 1) + 2 * i]     = lo;
            drow[(s_colq >> 1) + 2 * i + 1] = hi;
        }
        __syncthreads();

        // ---- compute: 2 m-tiles of 16 rows ----
#pragma unroll
        for (int mt = 0; mt < 2; mt++) {
            unsigned int a[4][4];
            const __nv_bfloat16* ap = &tile[slot][mt * 16 + ld_row][0];
            unsigned int abase = (unsigned int)__cvta_generic_to_shared(ap) + ld_off;
#pragma unroll
            for (int kt = 0; kt < 4; kt++) {
                asm volatile(
                    "ldmatrix.sync.aligned.m8n8.x4.shared.b16 {%0,%1,%2,%3}, [%4];"
                    : "=r"(a[kt][0]), "=r"(a[kt][1]), "=r"(a[kt][2]), "=r"(a[kt][3])
                    : "r"(abase + kt * 32));
            }
#pragma unroll
            for (int nt = 0; nt < 4; nt++) {
                float c0 = 0.f, c1 = 0.f, c2 = 0.f, c3 = 0.f;
#pragma unroll
                for (int kt = 0; kt < 4; kt++)
                    mma_bf16(c0, c1, c2, c3,
                             a[kt][0], a[kt][1], a[kt][2], a[kt][3],
                             bfr[kt][nt][0], bfr[kt][nt][1]);
                s += tanh_fast(c0 + bsv[nt][0]) * w2v[nt][0];
                s += tanh_fast(c1 + bsv[nt][1]) * w2v[nt][1];
                s += tanh_fast(c2 + bsv[nt][0]) * w2v[nt][0];
                s += tanh_fast(c3 + bsv[nt][1]) * w2v[nt][1];
            }
        }
        __syncthreads();
    }

    // ---- reduce: per warp, then slot partials -> g_w ----
#pragma unroll
    for (int off = 16; off > 0; off >>= 1)
        s += __shfl_xor_sync(0xffffffffu, s, off);
    if (lane == 0) wsum[warp] = s;
    __syncthreads();
    if (tid < 2) {
        float tot = wsum[tid * 4] + wsum[tid * 4 + 1]
                  + wsum[tid * 4 + 2] + wsum[tid * 4 + 3];
        atomicAdd(&g_w[2 * t + tid], tot);
    }
}

// ---------------- K5: beta = softmax(w / NN) over metapaths -----------------
__global__ void k_beta()
{
    if (threadIdx.x != 0 || blockIdx.x != 0) return;
    for (int t = 0; t < 2; t++) {
        float w0 = g_w[2 * t] * (1.0f / NN);
        float w1 = g_w[2 * t + 1] * (1.0f / NN);
        float m = fmaxf(w0, w1);
        float e0 = __expf(w0 - m), e1 = __expf(w1 - m);
        float inv = 1.0f / (e0 + e1);
        g_beta[2 * t + 0] = e0 * inv;
        g_beta[2 * t + 1] = e1 * inv;
    }
}

// ---------------- K6: gather + bias/ELU + beta-combine + GEMM + ReLU + LN ----
__global__ void __launch_bounds__(256) k_final(
    const int* __restrict__ user_idx, const int* __restrict__ item_idx,
    const int* __restrict__ neg_idx,
    const float* __restrict__ u_gb, const float* __restrict__ i_gb,
    const float* __restrict__ userW, const float* __restrict__ userb,
    const float* __restrict__ itemW, const float* __restrict__ itemb,
    const float* __restrict__ ln_g, const float* __restrict__ ln_b,
    float* __restrict__ out)
{
    __shared__ float Ws[4096];
    __shared__ float bs[64], gs[64], lbs[64];
    __shared__ float gb0[64], gb1[64];
    __shared__ float embs[4][64];
    __shared__ float red[4][2];

    int tid = threadIdx.x;
    int tx = tid & 63, ty = tid >> 6;
    int r0 = blockIdx.x * 4;
    bool isUser = (r0 < BB);                 // uniform per block (BB % 4 == 0)
    const float* W    = isUser ? userW : itemW;
    const float* bias = isUser ? userb : itemb;
    const float* gbm  = isUser ? u_gb : i_gb;

    for (int i = tid; i < 4096; i += 256) Ws[i] = W[i];
    if (tid < 64) {
        bs[tid] = bias[tid]; gs[tid] = ln_g[tid]; lbs[tid] = ln_b[tid];
        gb0[tid] = gbm[tid]; gb1[tid] = gbm[64 + tid];
    }

    int r = r0 + ty;
    int type, idx;
    if (r < BB)            { type = 0; idx = user_idx[r]; }
    else if (r < 2 * BB)   { type = 1; idx = item_idx[r - BB]; }
    else                   { type = 1; idx = neg_idx[r - 2 * BB]; }

    float b0 = g_beta[2 * type], b1 = g_beta[2 * type + 1];
    __syncthreads();
    float zr0 = g_z[2 * type][(size_t)idx * 64 + tx] + gb0[tx];
    float zr1 = g_z[2 * type + 1][(size_t)idx * 64 + tx] + gb1[tx];
    float emb = b0 * elu_fast(zr0) + b1 * elu_fast(zr1);
    embs[ty][tx] = emb;
    __syncthreads();

    float y = bs[tx];
#pragma unroll 16
    for (int k = 0; k < 64; k++) y += embs[ty][k] * Ws[k * 64 + tx];
    y = fmaxf(y, 0.0f);

    float s = y;
#pragma unroll
    for (int off = 16; off > 0; off >>= 1) s += __shfl_xor_sync(0xffffffffu, s, off);
    int half = tx >> 5;
    if ((tx & 31) == 0) red[ty][half] = s;
    __syncthreads();
    float mu = (red[ty][0] + red[ty][1]) * (1.0f / 64.0f);
    float dv = y - mu;
    float s2 = dv * dv;
#pragma unroll
    for (int off = 16; off > 0; off >>= 1) s2 += __shfl_xor_sync(0xffffffffu, s2, off);
    __syncthreads();
    if ((tx & 31) == 0) red[ty][half] = s2;
    __syncthreads();
    float var = (red[ty][0] + red[ty][1]) * (1.0f / 64.0f);
    float o = gs[tx] * dv * rsqrtf(var + 1e-5f) + lbs[tx];
    out[(size_t)r * 64 + tx] = o;
}

// ---------------- host ------------------------------------------------------
extern "C" void kernel_launch(void* const* d_in, const int* in_sizes, int n_in,
                              void* d_out, int out_size)
{
    const int*   user_idx  = (const int*)d_in[0];
    const int*   item_idx  = (const int*)d_in[1];
    const int*   neg_idx   = (const int*)d_in[2];
    const float* user_feat = (const float*)d_in[3];
    const float* item_feat = (const float*)d_in[4];
    const int*   u_src = (const int*)d_in[5];
    const int*   u_dst = (const int*)d_in[6];
    const int*   i_src = (const int*)d_in[7];
    const int*   i_dst = (const int*)d_in[8];
    const float* u_W  = (const float*)d_in[9];
    const float* u_al = (const float*)d_in[10];
    const float* u_ar = (const float*)d_in[11];
    const float* u_b  = (const float*)d_in[12];
    const float* i_W  = (const float*)d_in[13];
    const float* i_al = (const float*)d_in[14];
    const float* i_ar = (const float*)d_in[15];
    const float* i_b  = (const float*)d_in[16];
    const float* u_saW1 = (const float*)d_in[17];
    const float* u_sab1 = (const float*)d_in[18];
    const float* u_saW2 = (const float*)d_in[19];
    const float* i_saW1 = (const float*)d_in[20];
    const float* i_sab1 = (const float*)d_in[21];
    const float* i_saW2 = (const float*)d_in[22];
    const float* userW = (const float*)d_in[23];
    const float* userb = (const float*)d_in[24];
    const float* itemW = (const float*)d_in[25];
    const float* itemb = (const float*)d_in[26];
    const float* ln_g  = (const float*)d_in[27];
    const float* ln_b  = (const float*)d_in[28];
    float* out = (float*)d_out;

    cudaFuncSetAttribute(k_gemm_feat,
                         cudaFuncAttributeMaxDynamicSharedMemorySize, K1_SMEM);

    const float* feats[2] = {user_feat, item_feat};
    const int*   srcs[2]  = {u_src, i_src};
    const int*   dsts[2]  = {u_dst, i_dst};
    const float* Wms[2]   = {u_W, i_W};
    const float* als[2]   = {u_al, i_al};
    const float* ars[2]   = {u_ar, i_ar};

    const int grid1 = (NN + 63) / 64;            // 1563
    dim3 gridE((EE + 255) / 256, 2);             // 1954 x 2
    dim3 gridA((EE * 16) / 256, 2);              // 31250 x 2

    for (int t = 0; t < 2; t++) {
        k_gemm_feat<<<grid1, 256, K1_SMEM>>>(feats[t], Wms[t], als[t], ars[t], t);
        k_edge_score<<<gridE, 256>>>(srcs[t], dsts[t]);
        k_edge_aggr<<<gridA, 256>>>(srcs[t], dsts[t], t);
    }

    dim3 semGrid(256, 2);
    k_sem_mma<<<semGrid, 256>>>(u_saW1, u_sab1, u_saW2, u_b,
                                i_saW1, i_sab1, i_saW2, i_b);
    k_beta<<<1, 1>>>();
    k_final<<<(3 * BB) / 4, 256>>>(user_idx, item_idx, neg_idx, u_b, i_b,
                                   userW, userb, itemW, itemb, ln_g, ln_b, out);
}

// round 6
// speedup vs baseline: 1.6576x; 1.6576x over previous
#include <cuda_runtime.h>
#include <cuda_bf16.h>
#include <math.h>

#define NN 100000
#define EE 500000
#define BB 8192

// ---------------- scratch (device globals) ----------------------------------
__device__ float g_feat[2][NN * 64];       // per metapath
__device__ float g_z[4][NN * 64];          // [type*2 + m]
__device__ float g_el[2][NN];
__device__ float g_er[2][NN];
__device__ float g_den[2][NN];
__device__ float g_e[2][EE];
__device__ float g_w[4];
__device__ float g_beta[4];

// ---------------- helpers ----------------------------------------------------
__device__ __forceinline__ float tanh_fast(float x) {
    float y; asm("tanh.approx.f32 %0, %1;" : "=f"(y) : "f"(x)); return y;
}
__device__ __forceinline__ float elu_fast(float x) {
    return x > 0.f ? x : (__expf(x) - 1.f);
}
__device__ __forceinline__ unsigned int bf2(float lo, float hi) {
    __nv_bfloat162 v = __floats2bfloat162_rn(lo, hi);
    return *reinterpret_cast<unsigned int*>(&v);
}
__device__ __forceinline__ void mma_bf16(
    float& c0, float& c1, float& c2, float& c3,
    unsigned int a0, unsigned int a1, unsigned int a2, unsigned int a3,
    unsigned int b0, unsigned int b1)
{
    asm("mma.sync.aligned.m16n8k16.row.col.f32.bf16.bf16.f32 "
        "{%0,%1,%2,%3}, {%4,%5,%6,%7}, {%8,%9}, {%0,%1,%2,%3};"
        : "+f"(c0), "+f"(c1), "+f"(c2), "+f"(c3)
        : "r"(a0), "r"(a1), "r"(a2), "r"(a3), "r"(b0), "r"(b1));
}

// ---------------- K1: register-blocked feat GEMM ----------------------------
// Tile 128 rows x 64 cols per block; thread = 8 rows x 4 cols (32 accs).
// grid: (ceil(NN/128), 2=metapath). h staged k-major for broadcast row reads.
#define WS_STRIDE 68
#define HT_STRIDE 132
#define K1_SMEM ((64 * WS_STRIDE + 64 * HT_STRIDE + 128) * 4)

__global__ void __launch_bounds__(256) k_gemm_feat(
    const float* __restrict__ h, const float* __restrict__ W,
    const float* __restrict__ al, const float* __restrict__ ar, int type)
{
    extern __shared__ float smem[];
    float* Ws  = smem;                       // 64 x 68
    float* hsT = Ws + 64 * WS_STRIDE;        // 64(k) x 132(row)
    float* als = hsT + 64 * HT_STRIDE;       // 64
    float* ars = als + 64;                   // 64

    int m    = blockIdx.y;
    int tid  = threadIdx.x;
    int row0 = blockIdx.x * 128;

    if (type == 0 && blockIdx.x == 0 && m == 0 && tid < 4) g_w[tid] = 0.0f;

    // load W[m] (64x64) into padded smem
    for (int i = tid; i < 4096; i += 256)
        Ws[(i >> 6) * WS_STRIDE + (i & 63)] = W[m * 4096 + i];
    if (tid < 64) { als[tid] = al[m * 64 + tid]; ars[tid] = ar[m * 64 + tid]; }

    // stage h transposed: thread handles row r, k-range kq..kq+31
    {
        int r  = tid >> 1;                   // 0..127
        int kq = (tid & 1) * 32;
        int grow = row0 + r;
        if (grow < NN) {
            const float4* hp = (const float4*)&h[(size_t)grow * 64 + kq];
#pragma unroll
            for (int j = 0; j < 8; j++) {
                float4 v = hp[j];
                int kb = kq + j * 4;
                hsT[(kb + 0) * HT_STRIDE + r] = v.x;
                hsT[(kb + 1) * HT_STRIDE + r] = v.y;
                hsT[(kb + 2) * HT_STRIDE + r] = v.z;
                hsT[(kb + 3) * HT_STRIDE + r] = v.w;
            }
        } else {
#pragma unroll
            for (int j = 0; j < 32; j++)
                hsT[(kq + j) * HT_STRIDE + r] = 0.0f;
        }
    }
    __syncthreads();

    int tx = tid & 15;          // col group: cols tx*4..tx*4+3
    int ty = tid >> 4;          // row group: rows ty*8..ty*8+7

    float acc[8][4];
#pragma unroll
    for (int r = 0; r < 8; r++)
#pragma unroll
        for (int c = 0; c < 4; c++) acc[r][c] = 0.0f;

#pragma unroll 4
    for (int k = 0; k < 64; k++) {
        float4 w4 = *(const float4*)&Ws[k * WS_STRIDE + tx * 4];
        float4 ha = *(const float4*)&hsT[k * HT_STRIDE + ty * 8];
        float4 hb = *(const float4*)&hsT[k * HT_STRIDE + ty * 8 + 4];
        float hv[8] = {ha.x, ha.y, ha.z, ha.w, hb.x, hb.y, hb.z, hb.w};
#pragma unroll
        for (int r = 0; r < 8; r++) {
            acc[r][0] += hv[r] * w4.x;
            acc[r][1] += hv[r] * w4.y;
            acc[r][2] += hv[r] * w4.z;
            acc[r][3] += hv[r] * w4.w;
        }
    }

    // el/er partials: per row, sum over this thread's 4 cols, reduce over tx
    float al4[4] = {als[tx * 4], als[tx * 4 + 1], als[tx * 4 + 2], als[tx * 4 + 3]};
    float ar4[4] = {ars[tx * 4], ars[tx * 4 + 1], ars[tx * 4 + 2], ars[tx * 4 + 3]};

    float elr[8], err[8];
#pragma unroll
    for (int r = 0; r < 8; r++) {
        elr[r] = acc[r][0] * al4[0] + acc[r][1] * al4[1]
               + acc[r][2] * al4[2] + acc[r][3] * al4[3];
        err[r] = acc[r][0] * ar4[0] + acc[r][1] * ar4[1]
               + acc[r][2] * ar4[2] + acc[r][3] * ar4[3];
    }
#pragma unroll
    for (int off = 8; off > 0; off >>= 1) {
#pragma unroll
        for (int r = 0; r < 8; r++) {
            elr[r] += __shfl_xor_sync(0xffffffffu, elr[r], off);
            err[r] += __shfl_xor_sync(0xffffffffu, err[r], off);
        }
    }

    // write outputs
    float* fbase = g_feat[m];
    float* zbase = g_z[2 * type + m];
    float4 z4 = make_float4(0.f, 0.f, 0.f, 0.f);
#pragma unroll
    for (int r = 0; r < 8; r++) {
        int row = row0 + ty * 8 + r;
        if (row < NN) {
            *(float4*)&fbase[(size_t)row * 64 + tx * 4] =
                make_float4(acc[r][0], acc[r][1], acc[r][2], acc[r][3]);
            *(float4*)&zbase[(size_t)row * 64 + tx * 4] = z4;
            if (tx == 0) {
                g_el[m][row] = elr[r];
                g_er[m][row] = err[r];
                g_den[m][row] = 0.0f;
            }
        }
    }
}

// ---------------- K2: fused edge score + exp + segment sum (grid.y = m) -----
__global__ void k_edge_score(const int* __restrict__ src, const int* __restrict__ dst)
{
    int m = blockIdx.y;
    int i = blockIdx.x * blockDim.x + threadIdx.x;
    if (i >= EE) return;
    const int* srcm = src + (size_t)m * EE;
    const int* dstm = dst + (size_t)m * EE;
    int s = srcm[i], d = dstm[i];
    float e = g_el[m][s] + g_er[m][d];
    e = (e >= 0.0f) ? e : 0.2f * e;          // leaky_relu 0.2
    float ex = __expf(e);
    g_e[m][i] = ex;
    atomicAdd(&g_den[m][d], ex);
}

// ---------------- K3: alpha * feat[src] scatter-add into z (grid.y = m) -----
__global__ void __launch_bounds__(256) k_edge_aggr(
    const int* __restrict__ src, const int* __restrict__ dst, int type)
{
    int m = blockIdx.y;
    int t = blockIdx.x * 256 + threadIdx.x;
    int edge = t >> 4;
    int lane = t & 15;
    if (edge >= EE) return;
    const int* srcm = src + (size_t)m * EE;
    const int* dstm = dst + (size_t)m * EE;
    int s = srcm[edge], d = dstm[edge];
    float alpha = g_e[m][edge] / (g_den[m][d] + 1e-9f);
    float4 f = *(const float4*)&g_feat[m][(size_t)s * 64 + lane * 4];
    float4 v = make_float4(f.x * alpha, f.y * alpha, f.z * alpha, f.w * alpha);
    float* zp = &g_z[2 * type + m][(size_t)d * 64 + lane * 4];
    asm volatile("red.global.add.v4.f32 [%0], {%1,%2,%3,%4};"
                 :: "l"(zp), "f"(v.x), "f"(v.y), "f"(v.z), "f"(v.w)
                 : "memory");
}

// ---------------- K4: semantic logits via mma.sync bf16 ---------------------
#define SEM_TILE_STRIDE 72   // bf16 elems per row (144 B)

__global__ void __launch_bounds__(256) k_sem_mma(
    const float* __restrict__ uW1, const float* __restrict__ ub1,
    const float* __restrict__ uW2, const float* __restrict__ ugb,
    const float* __restrict__ iW1, const float* __restrict__ ib1,
    const float* __restrict__ iW2, const float* __restrict__ igb)
{
    __shared__ __align__(16) __nv_bfloat16 tile[2][32][SEM_TILE_STRIDE];
    __shared__ float gbs[128];
    __shared__ float wsum[8];

    int t = blockIdx.y;
    const float* W1 = t ? iW1 : uW1;
    const float* b1 = t ? ib1 : ub1;
    const float* W2 = t ? iW2 : uW2;
    const float* gb = t ? igb : ugb;

    int tid  = threadIdx.x;
    int warp = tid >> 5;
    int lane = tid & 31;
    int slot = warp >> 2;        // metapath 0/1
    int nq   = warp & 3;         // column quarter of H=128

    if (tid < 128) gbs[tid] = gb[tid];

    // ---- preload B fragments of W1 (k-major 64x128): [kt][nt][2] ----
    unsigned int bfr[4][4][2];
    {
        int n = nq * 32 + (lane >> 2);
        int k0 = (lane & 3) * 2;
#pragma unroll
        for (int kt = 0; kt < 4; kt++) {
            int k = kt * 16 + k0;
#pragma unroll
            for (int nt = 0; nt < 4; nt++) {
                int nn = n + nt * 8;
                bfr[kt][nt][0] = bf2(W1[(size_t)k * 128 + nn],
                                     W1[(size_t)(k + 1) * 128 + nn]);
                bfr[kt][nt][1] = bf2(W1[(size_t)(k + 8) * 128 + nn],
                                     W1[(size_t)(k + 9) * 128 + nn]);
            }
        }
    }
    float w2v[4][2], bsv[4][2];
#pragma unroll
    for (int nt = 0; nt < 4; nt++) {
        int c = nq * 32 + nt * 8 + (lane & 3) * 2;
        w2v[nt][0] = W2[c];     w2v[nt][1] = W2[c + 1];
        bsv[nt][0] = b1[c];     bsv[nt][1] = b1[c + 1];
    }

    int s_slot = tid >> 7;
    int tid2   = tid & 127;
    int s_row  = tid2 >> 2;
    int s_colq = (tid2 & 3) * 16;

    int ld_row = lane & 15;
    int ld_off = (lane >> 4) * 16;

    float s = 0.0f;

    const int NITER = NN / 32;       // 3125
    __syncthreads();
    for (int it = blockIdx.x; it < NITER; it += gridDim.x) {
        int row0 = it * 32;
        const float* zrow = (s_slot ? g_z[2 * t + 1] : g_z[2 * t])
                            + (size_t)(row0 + s_row) * 64 + s_colq;
        unsigned int* drow = (unsigned int*)&tile[s_slot][s_row][0];
#pragma unroll
        for (int i = 0; i < 4; i++) {
            float4 v = *(const float4*)(zrow + 4 * i);
            int c = s_colq + 4 * i;
            unsigned int lo = bf2(elu_fast(v.x + gbs[s_slot * 64 + c]),
                                  elu_fast(v.y + gbs[s_slot * 64 + c + 1]));
            unsigned int hi = bf2(elu_fast(v.z + gbs[s_slot * 64 + c + 2]),
                                  elu_fast(v.w + gbs[s_slot * 64 + c + 3]));
            drow[(s_colq >> 1) + 2 * i]     = lo;
            drow[(s_colq >> 1) + 2 * i + 1] = hi;
        }
        __syncthreads();

#pragma unroll
        for (int mt = 0; mt < 2; mt++) {
            unsigned int a[4][4];
            const __nv_bfloat16* ap = &tile[slot][mt * 16 + ld_row][0];
            unsigned int abase = (unsigned int)__cvta_generic_to_shared(ap) + ld_off;
#pragma unroll
            for (int kt = 0; kt < 4; kt++) {
                asm volatile(
                    "ldmatrix.sync.aligned.m8n8.x4.shared.b16 {%0,%1,%2,%3}, [%4];"
                    : "=r"(a[kt][0]), "=r"(a[kt][1]), "=r"(a[kt][2]), "=r"(a[kt][3])
                    : "r"(abase + kt * 32));
            }
#pragma unroll
            for (int nt = 0; nt < 4; nt++) {
                float c0 = 0.f, c1 = 0.f, c2 = 0.f, c3 = 0.f;
#pragma unroll
                for (int kt = 0; kt < 4; kt++)
                    mma_bf16(c0, c1, c2, c3,
                             a[kt][0], a[kt][1], a[kt][2], a[kt][3],
                             bfr[kt][nt][0], bfr[kt][nt][1]);
                s += tanh_fast(c0 + bsv[nt][0]) * w2v[nt][0];
                s += tanh_fast(c1 + bsv[nt][1]) * w2v[nt][1];
                s += tanh_fast(c2 + bsv[nt][0]) * w2v[nt][0];
                s += tanh_fast(c3 + bsv[nt][1]) * w2v[nt][1];
            }
        }
        __syncthreads();
    }

#pragma unroll
    for (int off = 16; off > 0; off >>= 1)
        s += __shfl_xor_sync(0xffffffffu, s, off);
    if (lane == 0) wsum[warp] = s;
    __syncthreads();
    if (tid < 2) {
        float tot = wsum[tid * 4] + wsum[tid * 4 + 1]
                  + wsum[tid * 4 + 2] + wsum[tid * 4 + 3];
        atomicAdd(&g_w[2 * t + tid], tot);
    }
}

// ---------------- K5: beta = softmax(w / NN) over metapaths -----------------
__global__ void k_beta()
{
    if (threadIdx.x != 0 || blockIdx.x != 0) return;
    for (int t = 0; t < 2; t++) {
        float w0 = g_w[2 * t] * (1.0f / NN);
        float w1 = g_w[2 * t + 1] * (1.0f / NN);
        float m = fmaxf(w0, w1);
        float e0 = __expf(w0 - m), e1 = __expf(w1 - m);
        float inv = 1.0f / (e0 + e1);
        g_beta[2 * t + 0] = e0 * inv;
        g_beta[2 * t + 1] = e1 * inv;
    }
}

// ---------------- K6: gather + bias/ELU + beta-combine + GEMM + ReLU + LN ----
__global__ void __launch_bounds__(256) k_final(
    const int* __restrict__ user_idx, const int* __restrict__ item_idx,
    const int* __restrict__ neg_idx,
    const float* __restrict__ u_gb, const float* __restrict__ i_gb,
    const float* __restrict__ userW, const float* __restrict__ userb,
    const float* __restrict__ itemW, const float* __restrict__ itemb,
    const float* __restrict__ ln_g, const float* __restrict__ ln_b,
    float* __restrict__ out)
{
    __shared__ float Ws[4096];
    __shared__ float bs[64], gs[64], lbs[64];
    __shared__ float gb0[64], gb1[64];
    __shared__ float embs[4][64];
    __shared__ float red[4][2];

    int tid = threadIdx.x;
    int tx = tid & 63, ty = tid >> 6;
    int r0 = blockIdx.x * 4;
    bool isUser = (r0 < BB);
    const float* W    = isUser ? userW : itemW;
    const float* bias = isUser ? userb : itemb;
    const float* gbm  = isUser ? u_gb : i_gb;

    for (int i = tid; i < 4096; i += 256) Ws[i] = W[i];
    if (tid < 64) {
        bs[tid] = bias[tid]; gs[tid] = ln_g[tid]; lbs[tid] = ln_b[tid];
        gb0[tid] = gbm[tid]; gb1[tid] = gbm[64 + tid];
    }

    int r = r0 + ty;
    int type, idx;
    if (r < BB)            { type = 0; idx = user_idx[r]; }
    else if (r < 2 * BB)   { type = 1; idx = item_idx[r - BB]; }
    else                   { type = 1; idx = neg_idx[r - 2 * BB]; }

    float b0 = g_beta[2 * type], b1 = g_beta[2 * type + 1];
    __syncthreads();
    float zr0 = g_z[2 * type][(size_t)idx * 64 + tx] + gb0[tx];
    float zr1 = g_z[2 * type + 1][(size_t)idx * 64 + tx] + gb1[tx];
    float emb = b0 * elu_fast(zr0) + b1 * elu_fast(zr1);
    embs[ty][tx] = emb;
    __syncthreads();

    float y = bs[tx];
#pragma unroll 16
    for (int k = 0; k < 64; k++) y += embs[ty][k] * Ws[k * 64 + tx];
    y = fmaxf(y, 0.0f);

    float s = y;
#pragma unroll
    for (int off = 16; off > 0; off >>= 1) s += __shfl_xor_sync(0xffffffffu, s, off);
    int half = tx >> 5;
    if ((tx & 31) == 0) red[ty][half] = s;
    __syncthreads();
    float mu = (red[ty][0] + red[ty][1]) * (1.0f / 64.0f);
    float dv = y - mu;
    float s2 = dv * dv;
#pragma unroll
    for (int off = 16; off > 0; off >>= 1) s2 += __shfl_xor_sync(0xffffffffu, s2, off);
    __syncthreads();
    if ((tx & 31) == 0) red[ty][half] = s2;
    __syncthreads();
    float var = (red[ty][0] + red[ty][1]) * (1.0f / 64.0f);
    float o = gs[tx] * dv * rsqrtf(var + 1e-5f) + lbs[tx];
    out[(size_t)r * 64 + tx] = o;
}

// ---------------- host ------------------------------------------------------
extern "C" void kernel_launch(void* const* d_in, const int* in_sizes, int n_in,
                              void* d_out, int out_size)
{
    const int*   user_idx  = (const int*)d_in[0];
    const int*   item_idx  = (const int*)d_in[1];
    const int*   neg_idx   = (const int*)d_in[2];
    const float* user_feat = (const float*)d_in[3];
    const float* item_feat = (const float*)d_in[4];
    const int*   u_src = (const int*)d_in[5];
    const int*   u_dst = (const int*)d_in[6];
    const int*   i_src = (const int*)d_in[7];
    const int*   i_dst = (const int*)d_in[8];
    const float* u_W  = (const float*)d_in[9];
    const float* u_al = (const float*)d_in[10];
    const float* u_ar = (const float*)d_in[11];
    const float* u_b  = (const float*)d_in[12];
    const float* i_W  = (const float*)d_in[13];
    const float* i_al = (const float*)d_in[14];
    const float* i_ar = (const float*)d_in[15];
    const float* i_b  = (const float*)d_in[16];
    const float* u_saW1 = (const float*)d_in[17];
    const float* u_sab1 = (const float*)d_in[18];
    const float* u_saW2 = (const float*)d_in[19];
    const float* i_saW1 = (const float*)d_in[20];
    const float* i_sab1 = (const float*)d_in[21];
    const float* i_saW2 = (const float*)d_in[22];
    const float* userW = (const float*)d_in[23];
    const float* userb = (const float*)d_in[24];
    const float* itemW = (const float*)d_in[25];
    const float* itemb = (const float*)d_in[26];
    const float* ln_g  = (const float*)d_in[27];
    const float* ln_b  = (const float*)d_in[28];
    float* out = (float*)d_out;

    cudaFuncSetAttribute(k_gemm_feat,
                         cudaFuncAttributeMaxDynamicSharedMemorySize, K1_SMEM);

    const float* feats[2] = {user_feat, item_feat};
    const int*   srcs[2]  = {u_src, i_src};
    const int*   dsts[2]  = {u_dst, i_dst};
    const float* Wms[2]   = {u_W, i_W};
    const float* als[2]   = {u_al, i_al};
    const float* ars[2]   = {u_ar, i_ar};

    dim3 grid1((NN + 127) / 128, 2);             // 782 x 2
    dim3 gridE((EE + 255) / 256, 2);             // 1954 x 2
    dim3 gridA((EE * 16) / 256, 2);              // 31250 x 2

    for (int t = 0; t < 2; t++) {
        k_gemm_feat<<<grid1, 256, K1_SMEM>>>(feats[t], Wms[t], als[t], ars[t], t);
        k_edge_score<<<gridE, 256>>>(srcs[t], dsts[t]);
        k_edge_aggr<<<gridA, 256>>>(srcs[t], dsts[t], t);
    }

    dim3 semGrid(256, 2);
    k_sem_mma<<<semGrid, 256>>>(u_saW1, u_sab1, u_saW2, u_b,
                                i_saW1, i_sab1, i_saW2, i_b);
    k_beta<<<1, 1>>>();
    k_final<<<(3 * BB) / 4, 256>>>(user_idx, item_idx, neg_idx, u_b, i_b,
                                   userW, userb, itemW, itemb, ln_g, ln_b, out);
}

// round 7
// speedup vs baseline: 1.7972x; 1.0842x over previous
#include <cuda_runtime.h>
#include <cuda_bf16.h>
#include <cuda_fp16.h>
#include <math.h>

#define NN 100000
#define EE 500000
#define BB 8192

// ---------------- scratch (device globals) ----------------------------------
__device__ __half g_feat_h[4][NN * 64];    // fp16 feat per slot (type*2+m)
__device__ float g_z[4][NN * 64];          // unnormalized: sum ex*feat
__device__ float g_el[4][NN];
__device__ float g_er[4][NN];
__device__ float g_den[4][NN];             // sum ex per dst
__device__ float g_w[4];
__device__ float g_beta[4];

// ---------------- helpers ----------------------------------------------------
__device__ __forceinline__ float tanh_fast(float x) {
    float y; asm("tanh.approx.f32 %0, %1;" : "=f"(y) : "f"(x)); return y;
}
__device__ __forceinline__ float elu_fast(float x) {
    return x > 0.f ? x : (__expf(x) - 1.f);
}
__device__ __forceinline__ unsigned int bf2(float lo, float hi) {
    __nv_bfloat162 v = __floats2bfloat162_rn(lo, hi);
    return *reinterpret_cast<unsigned int*>(&v);
}
__device__ __forceinline__ void mma_bf16(
    float& c0, float& c1, float& c2, float& c3,
    unsigned int a0, unsigned int a1, unsigned int a2, unsigned int a3,
    unsigned int b0, unsigned int b1)
{
    asm("mma.sync.aligned.m16n8k16.row.col.f32.bf16.bf16.f32 "
        "{%0,%1,%2,%3}, {%4,%5,%6,%7}, {%8,%9}, {%0,%1,%2,%3};"
        : "+f"(c0), "+f"(c1), "+f"(c2), "+f"(c3)
        : "r"(a0), "r"(a1), "r"(a2), "r"(a3), "r"(b0), "r"(b1));
}

// ---------------- K1: register-blocked feat GEMM, all 4 slots ---------------
// grid (782, m, type). Tile 128 rows; thread = 8 rows x 4 cols.
#define WS_STRIDE 68
#define HT_STRIDE 132
#define K1_SMEM ((64 * WS_STRIDE + 64 * HT_STRIDE + 128) * 4)

__global__ void __launch_bounds__(256) k_gemm_feat(
    const float* __restrict__ h_u, const float* __restrict__ h_i,
    const float* __restrict__ W_u, const float* __restrict__ W_i,
    const float* __restrict__ al_u, const float* __restrict__ al_i,
    const float* __restrict__ ar_u, const float* __restrict__ ar_i)
{
    extern __shared__ float smem[];
    float* Ws  = smem;                       // 64 x 68
    float* hsT = Ws + 64 * WS_STRIDE;        // 64(k) x 132(row)
    float* als = hsT + 64 * HT_STRIDE;       // 64
    float* ars = als + 64;                   // 64

    int m    = blockIdx.y;
    int type = blockIdx.z;
    int slot = 2 * type + m;
    const float* h  = type ? h_i  : h_u;
    const float* W  = (type ? W_i  : W_u)  + m * 4096;
    const float* al = (type ? al_i : al_u) + m * 64;
    const float* ar = (type ? ar_i : ar_u) + m * 64;

    int tid  = threadIdx.x;
    int row0 = blockIdx.x * 128;

    if (blockIdx.x == 0 && m == 0 && type == 0 && tid < 4) g_w[tid] = 0.0f;

    for (int i = tid; i < 4096; i += 256)
        Ws[(i >> 6) * WS_STRIDE + (i & 63)] = W[i];
    if (tid < 64) { als[tid] = al[tid]; ars[tid] = ar[tid]; }

    {
        int r  = tid >> 1;                   // 0..127
        int kq = (tid & 1) * 32;
        int grow = row0 + r;
        if (grow < NN) {
            const float4* hp = (const float4*)&h[(size_t)grow * 64 + kq];
#pragma unroll
            for (int j = 0; j < 8; j++) {
                float4 v = hp[j];
                int kb = kq + j * 4;
                hsT[(kb + 0) * HT_STRIDE + r] = v.x;
                hsT[(kb + 1) * HT_STRIDE + r] = v.y;
                hsT[(kb + 2) * HT_STRIDE + r] = v.z;
                hsT[(kb + 3) * HT_STRIDE + r] = v.w;
            }
        } else {
#pragma unroll
            for (int j = 0; j < 32; j++)
                hsT[(kq + j) * HT_STRIDE + r] = 0.0f;
        }
    }
    __syncthreads();

    int tx = tid & 15;          // cols tx*4..tx*4+3
    int ty = tid >> 4;          // rows ty*8..ty*8+7

    float acc[8][4];
#pragma unroll
    for (int r = 0; r < 8; r++)
#pragma unroll
        for (int c = 0; c < 4; c++) acc[r][c] = 0.0f;

#pragma unroll 4
    for (int k = 0; k < 64; k++) {
        float4 w4 = *(const float4*)&Ws[k * WS_STRIDE + tx * 4];
        float4 ha = *(const float4*)&hsT[k * HT_STRIDE + ty * 8];
        float4 hb = *(const float4*)&hsT[k * HT_STRIDE + ty * 8 + 4];
        float hv[8] = {ha.x, ha.y, ha.z, ha.w, hb.x, hb.y, hb.z, hb.w};
#pragma unroll
        for (int r = 0; r < 8; r++) {
            acc[r][0] += hv[r] * w4.x;
            acc[r][1] += hv[r] * w4.y;
            acc[r][2] += hv[r] * w4.z;
            acc[r][3] += hv[r] * w4.w;
        }
    }

    float al4[4] = {als[tx * 4], als[tx * 4 + 1], als[tx * 4 + 2], als[tx * 4 + 3]};
    float ar4[4] = {ars[tx * 4], ars[tx * 4 + 1], ars[tx * 4 + 2], ars[tx * 4 + 3]};

    float elr[8], err[8];
#pragma unroll
    for (int r = 0; r < 8; r++) {
        elr[r] = acc[r][0] * al4[0] + acc[r][1] * al4[1]
               + acc[r][2] * al4[2] + acc[r][3] * al4[3];
        err[r] = acc[r][0] * ar4[0] + acc[r][1] * ar4[1]
               + acc[r][2] * ar4[2] + acc[r][3] * ar4[3];
    }
#pragma unroll
    for (int off = 8; off > 0; off >>= 1) {
#pragma unroll
        for (int r = 0; r < 8; r++) {
            elr[r] += __shfl_xor_sync(0xffffffffu, elr[r], off);
            err[r] += __shfl_xor_sync(0xffffffffu, err[r], off);
        }
    }

    __half* fbase = g_feat_h[slot];
    float*  zbase = g_z[slot];
    float4 z4 = make_float4(0.f, 0.f, 0.f, 0.f);
#pragma unroll
    for (int r = 0; r < 8; r++) {
        int row = row0 + ty * 8 + r;
        if (row < NN) {
            __half2 p0 = __floats2half2_rn(acc[r][0], acc[r][1]);
            __half2 p1 = __floats2half2_rn(acc[r][2], acc[r][3]);
            uint2 pk = make_uint2(*(unsigned int*)&p0, *(unsigned int*)&p1);
            *(uint2*)&fbase[(size_t)row * 64 + tx * 4] = pk;
            *(float4*)&zbase[(size_t)row * 64 + tx * 4] = z4;
            if (tx == 0) {
                g_el[slot][row] = elr[r];
                g_er[slot][row] = err[r];
                g_den[slot][row] = 0.0f;
            }
        }
    }
}

// ---------------- K2: fused edge score+exp+aggregate (all slots) ------------
// 8 lanes/edge; z += ex * feat_fp16[src]; den += ex. Normalization deferred.
__global__ void __launch_bounds__(256) k_edge(
    const int* __restrict__ u_src, const int* __restrict__ u_dst,
    const int* __restrict__ i_src, const int* __restrict__ i_dst)
{
    int m    = blockIdx.y;
    int type = blockIdx.z;
    int slot = 2 * type + m;
    const int* src = (type ? i_src : u_src) + (size_t)m * EE;
    const int* dst = (type ? i_dst : u_dst) + (size_t)m * EE;

    int t = blockIdx.x * 256 + threadIdx.x;
    int edge = t >> 3;
    int lane = t & 7;
    if (edge >= EE) return;

    int s = src[edge], d = dst[edge];
    float e = g_el[slot][s] + g_er[slot][d];
    e = (e >= 0.0f) ? e : 0.2f * e;          // leaky_relu 0.2
    float ex = __expf(e);
    if (lane == 0) atomicAdd(&g_den[slot][d], ex);

    uint4 hv = *(const uint4*)&g_feat_h[slot][(size_t)s * 64 + lane * 8];
    float2 f0 = __half22float2(*(__half2*)&hv.x);
    float2 f1 = __half22float2(*(__half2*)&hv.y);
    float2 f2 = __half22float2(*(__half2*)&hv.z);
    float2 f3 = __half22float2(*(__half2*)&hv.w);

    float* zp = &g_z[slot][(size_t)d * 64 + lane * 8];
    asm volatile("red.global.add.v4.f32 [%0], {%1,%2,%3,%4};"
                 :: "l"(zp), "f"(f0.x * ex), "f"(f0.y * ex),
                    "f"(f1.x * ex), "f"(f1.y * ex) : "memory");
    asm volatile("red.global.add.v4.f32 [%0], {%1,%2,%3,%4};"
                 :: "l"(zp + 4), "f"(f2.x * ex), "f"(f2.y * ex),
                    "f"(f3.x * ex), "f"(f3.y * ex) : "memory");
}

// ---------------- K4: semantic logits via mma.sync bf16 ---------------------
#define SEM_TILE_STRIDE 72   // bf16 elems per row (144 B)

__global__ void __launch_bounds__(256) k_sem_mma(
    const float* __restrict__ uW1, const float* __restrict__ ub1,
    const float* __restrict__ uW2, const float* __restrict__ ugb,
    const float* __restrict__ iW1, const float* __restrict__ ib1,
    const float* __restrict__ iW2, const float* __restrict__ igb)
{
    __shared__ __align__(16) __nv_bfloat16 tile[2][32][SEM_TILE_STRIDE];
    __shared__ float gbs[128];
    __shared__ float wsum[8];

    int t = blockIdx.y;
    const float* W1 = t ? iW1 : uW1;
    const float* b1 = t ? ib1 : ub1;
    const float* W2 = t ? iW2 : uW2;
    const float* gb = t ? igb : ugb;

    int tid  = threadIdx.x;
    int warp = tid >> 5;
    int lane = tid & 31;
    int slot = warp >> 2;        // metapath 0/1
    int nq   = warp & 3;         // column quarter of H=128

    if (tid < 128) gbs[tid] = gb[tid];

    unsigned int bfr[4][4][2];
    {
        int n = nq * 32 + (lane >> 2);
        int k0 = (lane & 3) * 2;
#pragma unroll
        for (int kt = 0; kt < 4; kt++) {
            int k = kt * 16 + k0;
#pragma unroll
            for (int nt = 0; nt < 4; nt++) {
                int nn = n + nt * 8;
                bfr[kt][nt][0] = bf2(W1[(size_t)k * 128 + nn],
                                     W1[(size_t)(k + 1) * 128 + nn]);
                bfr[kt][nt][1] = bf2(W1[(size_t)(k + 8) * 128 + nn],
                                     W1[(size_t)(k + 9) * 128 + nn]);
            }
        }
    }
    float w2v[4][2], bsv[4][2];
#pragma unroll
    for (int nt = 0; nt < 4; nt++) {
        int c = nq * 32 + nt * 8 + (lane & 3) * 2;
        w2v[nt][0] = W2[c];     w2v[nt][1] = W2[c + 1];
        bsv[nt][0] = b1[c];     bsv[nt][1] = b1[c + 1];
    }

    int s_slot = tid >> 7;
    int tid2   = tid & 127;
    int s_row  = tid2 >> 2;
    int s_colq = (tid2 & 3) * 16;

    int ld_row = lane & 15;
    int ld_off = (lane >> 4) * 16;

    float s = 0.0f;

    const int NITER = NN / 32;       // 3125
    __syncthreads();
    for (int it = blockIdx.x; it < NITER; it += gridDim.x) {
        int row0 = it * 32;
        int row = row0 + s_row;
        float inv = __fdividef(1.0f, g_den[2 * t + s_slot][row] + 1e-9f);
        const float* zrow = g_z[2 * t + s_slot] + (size_t)row * 64 + s_colq;
        unsigned int* drow = (unsigned int*)&tile[s_slot][s_row][0];
#pragma unroll
        for (int i = 0; i < 4; i++) {
            float4 v = *(const float4*)(zrow + 4 * i);
            int c = s_colq + 4 * i;
            unsigned int lo = bf2(elu_fast(v.x * inv + gbs[s_slot * 64 + c]),
                                  elu_fast(v.y * inv + gbs[s_slot * 64 + c + 1]));
            unsigned int hi = bf2(elu_fast(v.z * inv + gbs[s_slot * 64 + c + 2]),
                                  elu_fast(v.w * inv + gbs[s_slot * 64 + c + 3]));
            drow[(s_colq >> 1) + 2 * i]     = lo;
            drow[(s_colq >> 1) + 2 * i + 1] = hi;
        }
        __syncthreads();

#pragma unroll
        for (int mt = 0; mt < 2; mt++) {
            unsigned int a[4][4];
            const __nv_bfloat16* ap = &tile[slot][mt * 16 + ld_row][0];
            unsigned int abase = (unsigned int)__cvta_generic_to_shared(ap) + ld_off;
#pragma unroll
            for (int kt = 0; kt < 4; kt++) {
                asm volatile(
                    "ldmatrix.sync.aligned.m8n8.x4.shared.b16 {%0,%1,%2,%3}, [%4];"
                    : "=r"(a[kt][0]), "=r"(a[kt][1]), "=r"(a[kt][2]), "=r"(a[kt][3])
                    : "r"(abase + kt * 32));
            }
#pragma unroll
            for (int nt = 0; nt < 4; nt++) {
                float c0 = 0.f, c1 = 0.f, c2 = 0.f, c3 = 0.f;
#pragma unroll
                for (int kt = 0; kt < 4; kt++)
                    mma_bf16(c0, c1, c2, c3,
                             a[kt][0], a[kt][1], a[kt][2], a[kt][3],
                             bfr[kt][nt][0], bfr[kt][nt][1]);
                s += tanh_fast(c0 + bsv[nt][0]) * w2v[nt][0];
                s += tanh_fast(c1 + bsv[nt][1]) * w2v[nt][1];
                s += tanh_fast(c2 + bsv[nt][0]) * w2v[nt][0];
                s += tanh_fast(c3 + bsv[nt][1]) * w2v[nt][1];
            }
        }
        __syncthreads();
    }

#pragma unroll
    for (int off = 16; off > 0; off >>= 1)
        s += __shfl_xor_sync(0xffffffffu, s, off);
    if (lane == 0) wsum[warp] = s;
    __syncthreads();
    if (tid < 2) {
        float tot = wsum[tid * 4] + wsum[tid * 4 + 1]
                  + wsum[tid * 4 + 2] + wsum[tid * 4 + 3];
        atomicAdd(&g_w[2 * t + tid], tot);
    }
}

// ---------------- K5: beta = softmax(w / NN) over metapaths -----------------
__global__ void k_beta()
{
    if (threadIdx.x != 0 || blockIdx.x != 0) return;
    for (int t = 0; t < 2; t++) {
        float w0 = g_w[2 * t] * (1.0f / NN);
        float w1 = g_w[2 * t + 1] * (1.0f / NN);
        float m = fmaxf(w0, w1);
        float e0 = __expf(w0 - m), e1 = __expf(w1 - m);
        float inv = 1.0f / (e0 + e1);
        g_beta[2 * t + 0] = e0 * inv;
        g_beta[2 * t + 1] = e1 * inv;
    }
}

// ---------------- K6: gather + norm + bias/ELU + combine + GEMM + ReLU + LN --
__global__ void __launch_bounds__(256) k_final(
    const int* __restrict__ user_idx, const int* __restrict__ item_idx,
    const int* __restrict__ neg_idx,
    const float* __restrict__ u_gb, const float* __restrict__ i_gb,
    const float* __restrict__ userW, const float* __restrict__ userb,
    const float* __restrict__ itemW, const float* __restrict__ itemb,
    const float* __restrict__ ln_g, const float* __restrict__ ln_b,
    float* __restrict__ out)
{
    __shared__ float Ws[4096];
    __shared__ float bs[64], gs[64], lbs[64];
    __shared__ float gb0[64], gb1[64];
    __shared__ float embs[4][64];
    __shared__ float red[4][2];

    int tid = threadIdx.x;
    int tx = tid & 63, ty = tid >> 6;
    int r0 = blockIdx.x * 4;
    bool isUser = (r0 < BB);
    const float* W    = isUser ? userW : itemW;
    const float* bias = isUser ? userb : itemb;
    const float* gbm  = isUser ? u_gb : i_gb;

    for (int i = tid; i < 4096; i += 256) Ws[i] = W[i];
    if (tid < 64) {
        bs[tid] = bias[tid]; gs[tid] = ln_g[tid]; lbs[tid] = ln_b[tid];
        gb0[tid] = gbm[tid]; gb1[tid] = gbm[64 + tid];
    }

    int r = r0 + ty;
    int type, idx;
    if (r < BB)            { type = 0; idx = user_idx[r]; }
    else if (r < 2 * BB)   { type = 1; idx = item_idx[r - BB]; }
    else                   { type = 1; idx = neg_idx[r - 2 * BB]; }

    float b0 = g_beta[2 * type], b1 = g_beta[2 * type + 1];
    float inv0 = __fdividef(1.0f, g_den[2 * type][idx] + 1e-9f);
    float inv1 = __fdividef(1.0f, g_den[2 * type + 1][idx] + 1e-9f);
    __syncthreads();
    float zr0 = g_z[2 * type][(size_t)idx * 64 + tx] * inv0 + gb0[tx];
    float zr1 = g_z[2 * type + 1][(size_t)idx * 64 + tx] * inv1 + gb1[tx];
    float emb = b0 * elu_fast(zr0) + b1 * elu_fast(zr1);
    embs[ty][tx] = emb;
    __syncthreads();

    float y = bs[tx];
#pragma unroll 16
    for (int k = 0; k < 64; k++) y += embs[ty][k] * Ws[k * 64 + tx];
    y = fmaxf(y, 0.0f);

    float s = y;
#pragma unroll
    for (int off = 16; off > 0; off >>= 1) s += __shfl_xor_sync(0xffffffffu, s, off);
    int half = tx >> 5;
    if ((tx & 31) == 0) red[ty][half] = s;
    __syncthreads();
    float mu = (red[ty][0] + red[ty][1]) * (1.0f / 64.0f);
    float dv = y - mu;
    float s2 = dv * dv;
#pragma unroll
    for (int off = 16; off > 0; off >>= 1) s2 += __shfl_xor_sync(0xffffffffu, s2, off);
    __syncthreads();
    if ((tx & 31) == 0) red[ty][half] = s2;
    __syncthreads();
    float var = (red[ty][0] + red[ty][1]) * (1.0f / 64.0f);
    float o = gs[tx] * dv * rsqrtf(var + 1e-5f) + lbs[tx];
    out[(size_t)r * 64 + tx] = o;
}

// ---------------- host ------------------------------------------------------
extern "C" void kernel_launch(void* const* d_in, const int* in_sizes, int n_in,
                              void* d_out, int out_size)
{
    const int*   user_idx  = (const int*)d_in[0];
    const int*   item_idx  = (const int*)d_in[1];
    const int*   neg_idx   = (const int*)d_in[2];
    const float* user_feat = (const float*)d_in[3];
    const float* item_feat = (const float*)d_in[4];
    const int*   u_src = (const int*)d_in[5];
    const int*   u_dst = (const int*)d_in[6];
    const int*   i_src = (const int*)d_in[7];
    const int*   i_dst = (const int*)d_in[8];
    const float* u_W  = (const float*)d_in[9];
    const float* u_al = (const float*)d_in[10];
    const float* u_ar = (const float*)d_in[11];
    const float* u_b  = (const float*)d_in[12];
    const float* i_W  = (const float*)d_in[13];
    const float* i_al = (const float*)d_in[14];
    const float* i_ar = (const float*)d_in[15];
    const float* i_b  = (const float*)d_in[16];
    const float* u_saW1 = (const float*)d_in[17];
    const float* u_sab1 = (const float*)d_in[18];
    const float* u_saW2 = (const float*)d_in[19];
    const float* i_saW1 = (const float*)d_in[20];
    const float* i_sab1 = (const float*)d_in[21];
    const float* i_saW2 = (const float*)d_in[22];
    const float* userW = (const float*)d_in[23];
    const float* userb = (const float*)d_in[24];
    const float* itemW = (const float*)d_in[25];
    const float* itemb = (const float*)d_in[26];
    const float* ln_g  = (const float*)d_in[27];
    const float* ln_b  = (const float*)d_in[28];
    float* out = (float*)d_out;

    cudaFuncSetAttribute(k_gemm_feat,
                         cudaFuncAttributeMaxDynamicSharedMemorySize, K1_SMEM);

    dim3 grid1((NN + 127) / 128, 2, 2);          // 782 x m x type
    dim3 gridE((EE * 8 + 255) / 256, 2, 2);      // 15625 x m x type

    k_gemm_feat<<<grid1, 256, K1_SMEM>>>(user_feat, item_feat, u_W, i_W,
                                         u_al, i_al, u_ar, i_ar);
    k_edge<<<gridE, 256>>>(u_src, u_dst, i_src, i_dst);

    dim3 semGrid(256, 2);
    k_sem_mma<<<semGrid, 256>>>(u_saW1, u_sab1, u_saW2, u_b,
                                i_saW1, i_sab1, i_saW2, i_b);
    k_beta<<<1, 1>>>();
    k_final<<<(3 * BB) / 4, 256>>>(user_idx, item_idx, neg_idx, u_b, i_b,
                                   userW, userb, itemW, itemb, ln_g, ln_b, out);
}

// round 8
// speedup vs baseline: 2.0580x; 1.1451x over previous
#include <cuda_runtime.h>
#include <cuda_bf16.h>
#include <cuda_fp16.h>
#include <math.h>

#define NN 100000
#define EE 500000
#define BB 8192
#define NBLK 391                     // ceil(NN/256)

// ---------------- scratch (device globals) ----------------------------------
__device__ __half g_feat_h[4][NN * 64];        // fp16 feat per slot
__device__ float g_z[4][NN * 64];              // normalized GAT output
__device__ float g_el[4][NN];
__device__ float g_er[4][NN];
__device__ int   g_cnt[4][NN];                 // histogram, then cursor
__device__ int   g_rowptr[4][NN + 1];
__device__ int   g_bsum[4][NBLK];
__device__ unsigned long long g_csr[4][EE];    // (exp(score) << 32) | src
__device__ float g_w[4];

// ---------------- helpers ----------------------------------------------------
__device__ __forceinline__ float tanh_fast(float x) {
    float y; asm("tanh.approx.f32 %0, %1;" : "=f"(y) : "f"(x)); return y;
}
__device__ __forceinline__ float elu_fast(float x) {
    return x > 0.f ? x : (__expf(x) - 1.f);
}
__device__ __forceinline__ unsigned int bf2(float lo, float hi) {
    __nv_bfloat162 v = __floats2bfloat162_rn(lo, hi);
    return *reinterpret_cast<unsigned int*>(&v);
}
__device__ __forceinline__ void mma_bf16(
    float& c0, float& c1, float& c2, float& c3,
    unsigned int a0, unsigned int a1, unsigned int a2, unsigned int a3,
    unsigned int b0, unsigned int b1)
{
    asm("mma.sync.aligned.m16n8k16.row.col.f32.bf16.bf16.f32 "
        "{%0,%1,%2,%3}, {%4,%5,%6,%7}, {%8,%9}, {%0,%1,%2,%3};"
        : "+f"(c0), "+f"(c1), "+f"(c2), "+f"(c3)
        : "r"(a0), "r"(a1), "r"(a2), "r"(a3), "r"(b0), "r"(b1));
}

// ---------------- K1: register-blocked feat GEMM, all 4 slots ---------------
#define WS_STRIDE 68
#define HT_STRIDE 132
#define K1_SMEM ((64 * WS_STRIDE + 64 * HT_STRIDE + 128) * 4)

__global__ void __launch_bounds__(256) k_gemm_feat(
    const float* __restrict__ h_u, const float* __restrict__ h_i,
    const float* __restrict__ W_u, const float* __restrict__ W_i,
    const float* __restrict__ al_u, const float* __restrict__ al_i,
    const float* __restrict__ ar_u, const float* __restrict__ ar_i)
{
    extern __shared__ float smem[];
    float* Ws  = smem;
    float* hsT = Ws + 64 * WS_STRIDE;
    float* als = hsT + 64 * HT_STRIDE;
    float* ars = als + 64;

    int m    = blockIdx.y;
    int type = blockIdx.z;
    int slot = 2 * type + m;
    const float* h  = type ? h_i  : h_u;
    const float* W  = (type ? W_i  : W_u)  + m * 4096;
    const float* al = (type ? al_i : al_u) + m * 64;
    const float* ar = (type ? ar_i : ar_u) + m * 64;

    int tid  = threadIdx.x;
    int row0 = blockIdx.x * 128;

    if (blockIdx.x == 0 && m == 0 && type == 0 && tid < 4) g_w[tid] = 0.0f;

    for (int i = tid; i < 4096; i += 256)
        Ws[(i >> 6) * WS_STRIDE + (i & 63)] = W[i];
    if (tid < 64) { als[tid] = al[tid]; ars[tid] = ar[tid]; }

    {
        int r  = tid >> 1;
        int kq = (tid & 1) * 32;
        int grow = row0 + r;
        if (grow < NN) {
            const float4* hp = (const float4*)&h[(size_t)grow * 64 + kq];
#pragma unroll
            for (int j = 0; j < 8; j++) {
                float4 v = hp[j];
                int kb = kq + j * 4;
                hsT[(kb + 0) * HT_STRIDE + r] = v.x;
                hsT[(kb + 1) * HT_STRIDE + r] = v.y;
                hsT[(kb + 2) * HT_STRIDE + r] = v.z;
                hsT[(kb + 3) * HT_STRIDE + r] = v.w;
            }
        } else {
#pragma unroll
            for (int j = 0; j < 32; j++)
                hsT[(kq + j) * HT_STRIDE + r] = 0.0f;
        }
    }
    __syncthreads();

    int tx = tid & 15;
    int ty = tid >> 4;

    float acc[8][4];
#pragma unroll
    for (int r = 0; r < 8; r++)
#pragma unroll
        for (int c = 0; c < 4; c++) acc[r][c] = 0.0f;

#pragma unroll 4
    for (int k = 0; k < 64; k++) {
        float4 w4 = *(const float4*)&Ws[k * WS_STRIDE + tx * 4];
        float4 ha = *(const float4*)&hsT[k * HT_STRIDE + ty * 8];
        float4 hb = *(const float4*)&hsT[k * HT_STRIDE + ty * 8 + 4];
        float hv[8] = {ha.x, ha.y, ha.z, ha.w, hb.x, hb.y, hb.z, hb.w};
#pragma unroll
        for (int r = 0; r < 8; r++) {
            acc[r][0] += hv[r] * w4.x;
            acc[r][1] += hv[r] * w4.y;
            acc[r][2] += hv[r] * w4.z;
            acc[r][3] += hv[r] * w4.w;
        }
    }

    float al4[4] = {als[tx * 4], als[tx * 4 + 1], als[tx * 4 + 2], als[tx * 4 + 3]};
    float ar4[4] = {ars[tx * 4], ars[tx * 4 + 1], ars[tx * 4 + 2], ars[tx * 4 + 3]};

    float elr[8], err[8];
#pragma unroll
    for (int r = 0; r < 8; r++) {
        elr[r] = acc[r][0] * al4[0] + acc[r][1] * al4[1]
               + acc[r][2] * al4[2] + acc[r][3] * al4[3];
        err[r] = acc[r][0] * ar4[0] + acc[r][1] * ar4[1]
               + acc[r][2] * ar4[2] + acc[r][3] * ar4[3];
    }
#pragma unroll
    for (int off = 8; off > 0; off >>= 1) {
#pragma unroll
        for (int r = 0; r < 8; r++) {
            elr[r] += __shfl_xor_sync(0xffffffffu, elr[r], off);
            err[r] += __shfl_xor_sync(0xffffffffu, err[r], off);
        }
    }

    __half* fbase = g_feat_h[slot];
#pragma unroll
    for (int r = 0; r < 8; r++) {
        int row = row0 + ty * 8 + r;
        if (row < NN) {
            __half2 p0 = __floats2half2_rn(acc[r][0], acc[r][1]);
            __half2 p1 = __floats2half2_rn(acc[r][2], acc[r][3]);
            uint2 pk = make_uint2(*(unsigned int*)&p0, *(unsigned int*)&p1);
            *(uint2*)&fbase[(size_t)row * 64 + tx * 4] = pk;
            if (tx == 0) {
                g_el[slot][row] = elr[r];
                g_er[slot][row] = err[r];
                g_cnt[slot][row] = 0;
            }
        }
    }
}

// ---------------- K2a: in-degree histogram ----------------------------------
__global__ void k_hist(const int* __restrict__ u_dst, const int* __restrict__ i_dst)
{
    int slot = 2 * blockIdx.z + blockIdx.y;
    const int* dst = (blockIdx.z ? i_dst : u_dst) + (size_t)blockIdx.y * EE;
    int i = blockIdx.x * 256 + threadIdx.x;
    if (i < EE) atomicAdd(&g_cnt[slot][dst[i]], 1);
}

// ---------------- K2b: per-block sums ----------------------------------------
__global__ void __launch_bounds__(256) k_scanA()
{
    __shared__ int ws[8];
    int slot = blockIdx.y;
    int i = blockIdx.x * 256 + threadIdx.x;
    int v = (i < NN) ? g_cnt[slot][i] : 0;
#pragma unroll
    for (int off = 16; off > 0; off >>= 1) v += __shfl_xor_sync(~0u, v, off);
    if ((threadIdx.x & 31) == 0) ws[threadIdx.x >> 5] = v;
    __syncthreads();
    if (threadIdx.x == 0) {
        int s = 0;
#pragma unroll
        for (int w = 0; w < 8; w++) s += ws[w];
        g_bsum[slot][blockIdx.x] = s;
    }
}

// ---------------- K2c: scan block sums (1 block) -----------------------------
__global__ void __launch_bounds__(512) k_scanB()
{
    __shared__ int buf[512];
    int tid = threadIdx.x;
    for (int s = 0; s < 4; s++) {
        int v = (tid < NBLK) ? g_bsum[s][tid] : 0;
        buf[tid] = v;
        __syncthreads();
        for (int off = 1; off < 512; off <<= 1) {
            int x = (tid >= off) ? buf[tid - off] : 0;
            __syncthreads();
            buf[tid] += x;
            __syncthreads();
        }
        if (tid < NBLK) g_bsum[s][tid] = buf[tid] - v;   // exclusive
        if (tid == 0) g_rowptr[s][NN] = EE;
        __syncthreads();
    }
}

// ---------------- K2d: block-local exclusive scan -> rowptr; reset cnt ------
__global__ void __launch_bounds__(256) k_scanC()
{
    __shared__ int buf[256];
    int slot = blockIdx.y;
    int tid = threadIdx.x;
    int i = blockIdx.x * 256 + tid;
    int v = (i < NN) ? g_cnt[slot][i] : 0;
    buf[tid] = v;
    __syncthreads();
    for (int off = 1; off < 256; off <<= 1) {
        int x = (tid >= off) ? buf[tid - off] : 0;
        __syncthreads();
        buf[tid] += x;
        __syncthreads();
    }
    if (i < NN) {
        g_rowptr[slot][i] = g_bsum[slot][blockIdx.x] + buf[tid] - v;
        g_cnt[slot][i] = 0;
    }
}

// ---------------- K2e: scatter (src, exp(score)) into CSR --------------------
__global__ void k_scatter(
    const int* __restrict__ u_src, const int* __restrict__ u_dst,
    const int* __restrict__ i_src, const int* __restrict__ i_dst)
{
    int slot = 2 * blockIdx.z + blockIdx.y;
    const int* src = (blockIdx.z ? i_src : u_src) + (size_t)blockIdx.y * EE;
    const int* dst = (blockIdx.z ? i_dst : u_dst) + (size_t)blockIdx.y * EE;
    int i = blockIdx.x * 256 + threadIdx.x;
    if (i >= EE) return;
    int s = src[i], d = dst[i];
    float e = g_el[slot][s] + g_er[slot][d];
    e = (e >= 0.0f) ? e : 0.2f * e;          // leaky_relu 0.2
    float ex = __expf(e);
    int pos = g_rowptr[slot][d] + atomicAdd(&g_cnt[slot][d], 1);
    g_csr[slot][pos] =
        ((unsigned long long)__float_as_uint(ex) << 32) | (unsigned int)s;
}

// ---------------- K2f: node-parallel aggregate, write normalized z ----------
// 8 threads per node, each owns 8 columns.
__global__ void __launch_bounds__(256) k_aggr()
{
    int slot = blockIdx.y;
    int t = blockIdx.x * 256 + threadIdx.x;
    int node = t >> 3;
    int lane = t & 7;
    if (node >= NN) return;

    int start = g_rowptr[slot][node];
    int end   = g_rowptr[slot][node + 1];

    float acc[8] = {0.f, 0.f, 0.f, 0.f, 0.f, 0.f, 0.f, 0.f};
    float den = 0.0f;
    const __half* fb = g_feat_h[slot];
    const unsigned long long* csr = g_csr[slot];

    for (int p = start; p < end; p++) {
        unsigned long long pk = csr[p];
        int s = (int)(unsigned int)pk;
        float ex = __uint_as_float((unsigned int)(pk >> 32));
        den += ex;
        uint4 hv = *(const uint4*)&fb[(size_t)s * 64 + lane * 8];
        float2 f0 = __half22float2(*(__half2*)&hv.x);
        float2 f1 = __half22float2(*(__half2*)&hv.y);
        float2 f2 = __half22float2(*(__half2*)&hv.z);
        float2 f3 = __half22float2(*(__half2*)&hv.w);
        acc[0] += ex * f0.x; acc[1] += ex * f0.y;
        acc[2] += ex * f1.x; acc[3] += ex * f1.y;
        acc[4] += ex * f2.x; acc[5] += ex * f2.y;
        acc[6] += ex * f3.x; acc[7] += ex * f3.y;
    }

    float inv = __fdividef(1.0f, den + 1e-9f);
    float* zp = &g_z[slot][(size_t)node * 64 + lane * 8];
    *(float4*)zp       = make_float4(acc[0] * inv, acc[1] * inv,
                                     acc[2] * inv, acc[3] * inv);
    *(float4*)(zp + 4) = make_float4(acc[4] * inv, acc[5] * inv,
                                     acc[6] * inv, acc[7] * inv);
}

// ---------------- K4: semantic logits via mma.sync bf16 ---------------------
#define SEM_TILE_STRIDE 72

__global__ void __launch_bounds__(256) k_sem_mma(
    const float* __restrict__ uW1, const float* __restrict__ ub1,
    const float* __restrict__ uW2, const float* __restrict__ ugb,
    const float* __restrict__ iW1, const float* __restrict__ ib1,
    const float* __restrict__ iW2, const float* __restrict__ igb)
{
    __shared__ __align__(16) __nv_bfloat16 tile[2][32][SEM_TILE_STRIDE];
    __shared__ float gbs[128];
    __shared__ float wsum[8];

    int t = blockIdx.y;
    const float* W1 = t ? iW1 : uW1;
    const float* b1 = t ? ib1 : ub1;
    const float* W2 = t ? iW2 : uW2;
    const float* gb = t ? igb : ugb;

    int tid  = threadIdx.x;
    int warp = tid >> 5;
    int lane = tid & 31;
    int slot = warp >> 2;
    int nq   = warp & 3;

    if (tid < 128) gbs[tid] = gb[tid];

    unsigned int bfr[4][4][2];
    {
        int n = nq * 32 + (lane >> 2);
        int k0 = (lane & 3) * 2;
#pragma unroll
        for (int kt = 0; kt < 4; kt++) {
            int k = kt * 16 + k0;
#pragma unroll
            for (int nt = 0; nt < 4; nt++) {
                int nn = n + nt * 8;
                bfr[kt][nt][0] = bf2(W1[(size_t)k * 128 + nn],
                                     W1[(size_t)(k + 1) * 128 + nn]);
                bfr[kt][nt][1] = bf2(W1[(size_t)(k + 8) * 128 + nn],
                                     W1[(size_t)(k + 9) * 128 + nn]);
            }
        }
    }
    float w2v[4][2], bsv[4][2];
#pragma unroll
    for (int nt = 0; nt < 4; nt++) {
        int c = nq * 32 + nt * 8 + (lane & 3) * 2;
        w2v[nt][0] = W2[c];     w2v[nt][1] = W2[c + 1];
        bsv[nt][0] = b1[c];     bsv[nt][1] = b1[c + 1];
    }

    int s_slot = tid >> 7;
    int tid2   = tid & 127;
    int s_row  = tid2 >> 2;
    int s_colq = (tid2 & 3) * 16;

    int ld_row = lane & 15;
    int ld_off = (lane >> 4) * 16;

    float s = 0.0f;

    const int NITER = NN / 32;
    __syncthreads();
    for (int it = blockIdx.x; it < NITER; it += gridDim.x) {
        int row = it * 32 + s_row;
        const float* zrow = g_z[2 * t + s_slot] + (size_t)row * 64 + s_colq;
        unsigned int* drow = (unsigned int*)&tile[s_slot][s_row][0];
#pragma unroll
        for (int i = 0; i < 4; i++) {
            float4 v = *(const float4*)(zrow + 4 * i);
            int c = s_colq + 4 * i;
            unsigned int lo = bf2(elu_fast(v.x + gbs[s_slot * 64 + c]),
                                  elu_fast(v.y + gbs[s_slot * 64 + c + 1]));
            unsigned int hi = bf2(elu_fast(v.z + gbs[s_slot * 64 + c + 2]),
                                  elu_fast(v.w + gbs[s_slot * 64 + c + 3]));
            drow[(s_colq >> 1) + 2 * i]     = lo;
            drow[(s_colq >> 1) + 2 * i + 1] = hi;
        }
        __syncthreads();

#pragma unroll
        for (int mt = 0; mt < 2; mt++) {
            unsigned int a[4][4];
            const __nv_bfloat16* ap = &tile[slot][mt * 16 + ld_row][0];
            unsigned int abase = (unsigned int)__cvta_generic_to_shared(ap) + ld_off;
#pragma unroll
            for (int kt = 0; kt < 4; kt++) {
                asm volatile(
                    "ldmatrix.sync.aligned.m8n8.x4.shared.b16 {%0,%1,%2,%3}, [%4];"
                    : "=r"(a[kt][0]), "=r"(a[kt][1]), "=r"(a[kt][2]), "=r"(a[kt][3])
                    : "r"(abase + kt * 32));
            }
#pragma unroll
            for (int nt = 0; nt < 4; nt++) {
                float c0 = 0.f, c1 = 0.f, c2 = 0.f, c3 = 0.f;
#pragma unroll
                for (int kt = 0; kt < 4; kt++)
                    mma_bf16(c0, c1, c2, c3,
                             a[kt][0], a[kt][1], a[kt][2], a[kt][3],
                             bfr[kt][nt][0], bfr[kt][nt][1]);
                s += tanh_fast(c0 + bsv[nt][0]) * w2v[nt][0];
                s += tanh_fast(c1 + bsv[nt][1]) * w2v[nt][1];
                s += tanh_fast(c2 + bsv[nt][0]) * w2v[nt][0];
                s += tanh_fast(c3 + bsv[nt][1]) * w2v[nt][1];
            }
        }
        __syncthreads();
    }

#pragma unroll
    for (int off = 16; off > 0; off >>= 1)
        s += __shfl_xor_sync(0xffffffffu, s, off);
    if (lane == 0) wsum[warp] = s;
    __syncthreads();
    if (tid < 2) {
        float tot = wsum[tid * 4] + wsum[tid * 4 + 1]
                  + wsum[tid * 4 + 2] + wsum[tid * 4 + 3];
        atomicAdd(&g_w[2 * t + tid], tot);
    }
}

// ---------------- K6: gather + bias/ELU + beta + GEMM + ReLU + LN ------------
__global__ void __launch_bounds__(256) k_final(
    const int* __restrict__ user_idx, const int* __restrict__ item_idx,
    const int* __restrict__ neg_idx,
    const float* __restrict__ u_gb, const float* __restrict__ i_gb,
    const float* __restrict__ userW, const float* __restrict__ userb,
    const float* __restrict__ itemW, const float* __restrict__ itemb,
    const float* __restrict__ ln_g, const float* __restrict__ ln_b,
    float* __restrict__ out)
{
    __shared__ float Ws[4096];
    __shared__ float bs[64], gs[64], lbs[64];
    __shared__ float gb0[64], gb1[64];
    __shared__ float embs[4][64];
    __shared__ float red[4][2];

    int tid = threadIdx.x;
    int tx = tid & 63, ty = tid >> 6;
    int r0 = blockIdx.x * 4;
    bool isUser = (r0 < BB);
    const float* W    = isUser ? userW : itemW;
    const float* bias = isUser ? userb : itemb;
    const float* gbm  = isUser ? u_gb : i_gb;

    for (int i = tid; i < 4096; i += 256) Ws[i] = W[i];
    if (tid < 64) {
        bs[tid] = bias[tid]; gs[tid] = ln_g[tid]; lbs[tid] = ln_b[tid];
        gb0[tid] = gbm[tid]; gb1[tid] = gbm[64 + tid];
    }

    int r = r0 + ty;
    int type, idx;
    if (r < BB)            { type = 0; idx = user_idx[r]; }
    else if (r < 2 * BB)   { type = 1; idx = item_idx[r - BB]; }
    else                   { type = 1; idx = neg_idx[r - 2 * BB]; }

    // beta from semantic logits (folded former k_beta)
    float w0 = g_w[2 * type] * (1.0f / NN);
    float w1 = g_w[2 * type + 1] * (1.0f / NN);
    float mx = fmaxf(w0, w1);
    float e0 = __expf(w0 - mx), e1 = __expf(w1 - mx);
    float binv = 1.0f / (e0 + e1);
    float b0 = e0 * binv, b1 = e1 * binv;

    __syncthreads();
    float zr0 = g_z[2 * type][(size_t)idx * 64 + tx] + gb0[tx];
    float zr1 = g_z[2 * type + 1][(size_t)idx * 64 + tx] + gb1[tx];
    float emb = b0 * elu_fast(zr0) + b1 * elu_fast(zr1);
    embs[ty][tx] = emb;
    __syncthreads();

    float y = bs[tx];
#pragma unroll 16
    for (int k = 0; k < 64; k++) y += embs[ty][k] * Ws[k * 64 + tx];
    y = fmaxf(y, 0.0f);

    float s = y;
#pragma unroll
    for (int off = 16; off > 0; off >>= 1) s += __shfl_xor_sync(0xffffffffu, s, off);
    int half = tx >> 5;
    if ((tx & 31) == 0) red[ty][half] = s;
    __syncthreads();
    float mu = (red[ty][0] + red[ty][1]) * (1.0f / 64.0f);
    float dv = y - mu;
    float s2 = dv * dv;
#pragma unroll
    for (int off = 16; off > 0; off >>= 1) s2 += __shfl_xor_sync(0xffffffffu, s2, off);
    __syncthreads();
    if ((tx & 31) == 0) red[ty][half] = s2;
    __syncthreads();
    float var = (red[ty][0] + red[ty][1]) * (1.0f / 64.0f);
    float o = gs[tx] * dv * rsqrtf(var + 1e-5f) + lbs[tx];
    out[(size_t)r * 64 + tx] = o;
}

// ---------------- host ------------------------------------------------------
extern "C" void kernel_launch(void* const* d_in, const int* in_sizes, int n_in,
                              void* d_out, int out_size)
{
    const int*   user_idx  = (const int*)d_in[0];
    const int*   item_idx  = (const int*)d_in[1];
    const int*   neg_idx   = (const int*)d_in[2];
    const float* user_feat = (const float*)d_in[3];
    const float* item_feat = (const float*)d_in[4];
    const int*   u_src = (const int*)d_in[5];
    const int*   u_dst = (const int*)d_in[6];
    const int*   i_src = (const int*)d_in[7];
    const int*   i_dst = (const int*)d_in[8];
    const float* u_W  = (const float*)d_in[9];
    const float* u_al = (const float*)d_in[10];
    const float* u_ar = (const float*)d_in[11];
    const float* u_b  = (const float*)d_in[12];
    const float* i_W  = (const float*)d_in[13];
    const float* i_al = (const float*)d_in[14];
    const float* i_ar = (const float*)d_in[15];
    const float* i_b  = (const float*)d_in[16];
    const float* u_saW1 = (const float*)d_in[17];
    const float* u_sab1 = (const float*)d_in[18];
    const float* u_saW2 = (const float*)d_in[19];
    const float* i_saW1 = (const float*)d_in[20];
    const float* i_sab1 = (const float*)d_in[21];
    const float* i_saW2 = (const float*)d_in[22];
    const float* userW = (const float*)d_in[23];
    const float* userb = (const float*)d_in[24];
    const float* itemW = (const float*)d_in[25];
    const float* itemb = (const float*)d_in[26];
    const float* ln_g  = (const float*)d_in[27];
    const float* ln_b  = (const float*)d_in[28];
    float* out = (float*)d_out;

    cudaFuncSetAttribute(k_gemm_feat,
                         cudaFuncAttributeMaxDynamicSharedMemorySize, K1_SMEM);

    dim3 grid1((NN + 127) / 128, 2, 2);          // 782 x m x type
    dim3 gridE((EE + 255) / 256, 2, 2);          // 1954 x m x type
    dim3 gridS(NBLK, 4);                         // 391 x slot
    dim3 gridG((NN * 8 + 255) / 256, 4);         // 3125 x slot

    k_gemm_feat<<<grid1, 256, K1_SMEM>>>(user_feat, item_feat, u_W, i_W,
                                         u_al, i_al, u_ar, i_ar);
    k_hist<<<gridE, 256>>>(u_dst, i_dst);
    k_scanA<<<gridS, 256>>>();
    k_scanB<<<1, 512>>>();
    k_scanC<<<gridS, 256>>>();
    k_scatter<<<gridE, 256>>>(u_src, u_dst, i_src, i_dst);
    k_aggr<<<gridG, 256>>>();

    dim3 semGrid(256, 2);
    k_sem_mma<<<semGrid, 256>>>(u_saW1, u_sab1, u_saW2, u_b,
                                i_saW1, i_sab1, i_saW2, i_b);
    k_final<<<(3 * BB) / 4, 256>>>(user_idx, item_idx, neg_idx, u_b, i_b,
                                   userW, userb, itemW, itemb, ln_g, ln_b, out);
}

// round 9
// speedup vs baseline: 2.1794x; 1.0590x over previous
#include <cuda_runtime.h>
#include <cuda_bf16.h>
#include <cuda_fp16.h>
#include <math.h>

#define NN 100000
#define EE 500000
#define BB 8192
#define NBLK 391                     // ceil(NN/256)

// ---------------- scratch (device globals) ----------------------------------
__device__ __half g_feat_h[4][NN * 64];        // fp16 feat per slot
__device__ float g_z[4][NN * 64];              // normalized GAT output
__device__ float g_el[4][NN];
__device__ float g_er[4][NN];
__device__ int   g_cnt[4][NN];                 // histogram, then cursor
__device__ int   g_rowptr[4][NN + 1];
__device__ int   g_bsum[4][NBLK];
__device__ unsigned long long g_csr[4][EE];    // (exp(score) << 32) | src
__device__ float g_w[4];

// ---------------- helpers ----------------------------------------------------
__device__ __forceinline__ float tanh_fast(float x) {
    float y; asm("tanh.approx.f32 %0, %1;" : "=f"(y) : "f"(x)); return y;
}
__device__ __forceinline__ float elu_fast(float x) {
    return x > 0.f ? x : (__expf(x) - 1.f);
}
__device__ __forceinline__ unsigned int bf2(float lo, float hi) {
    __nv_bfloat162 v = __floats2bfloat162_rn(lo, hi);
    return *reinterpret_cast<unsigned int*>(&v);
}
__device__ __forceinline__ unsigned int to_tf32(float f) {
    unsigned int u; asm("cvt.rna.tf32.f32 %0, %1;" : "=r"(u) : "f"(f)); return u;
}
__device__ __forceinline__ void mma_bf16(
    float& c0, float& c1, float& c2, float& c3,
    unsigned int a0, unsigned int a1, unsigned int a2, unsigned int a3,
    unsigned int b0, unsigned int b1)
{
    asm("mma.sync.aligned.m16n8k16.row.col.f32.bf16.bf16.f32 "
        "{%0,%1,%2,%3}, {%4,%5,%6,%7}, {%8,%9}, {%0,%1,%2,%3};"
        : "+f"(c0), "+f"(c1), "+f"(c2), "+f"(c3)
        : "r"(a0), "r"(a1), "r"(a2), "r"(a3), "r"(b0), "r"(b1));
}
__device__ __forceinline__ void mma_tf32(
    float* c, unsigned int a0, unsigned int a1, unsigned int a2, unsigned int a3,
    unsigned int b0, unsigned int b1)
{
    asm("mma.sync.aligned.m16n8k8.row.col.f32.tf32.tf32.f32 "
        "{%0,%1,%2,%3}, {%4,%5,%6,%7}, {%8,%9}, {%0,%1,%2,%3};"
        : "+f"(c[0]), "+f"(c[1]), "+f"(c[2]), "+f"(c[3])
        : "r"(a0), "r"(a1), "r"(a2), "r"(a3), "r"(b0), "r"(b1));
}

// ---------------- K1: feat GEMM via tf32 mma.sync ---------------------------
// grid (ceil(NN/128), 4 slots). Block: 128 rows x 64 cols.
// Warp w: row-half mq=w&1 (64 rows), col-group nq=w>>1 (16 cols).
#define HS_STRIDE 68
#define K1M_SMEM ((128 * HS_STRIDE + 64 * 64 + 256) * 4)

__global__ void __launch_bounds__(256) k_gemm_feat_mma(
    const float* __restrict__ h_u, const float* __restrict__ h_i,
    const float* __restrict__ W_u, const float* __restrict__ W_i,
    const float* __restrict__ al_u, const float* __restrict__ al_i,
    const float* __restrict__ ar_u, const float* __restrict__ ar_i)
{
    extern __shared__ unsigned int smemu[];
    unsigned int* hsU = smemu;                  // 128 x 68 (tf32 bits)
    unsigned int* WsU = hsU + 128 * HS_STRIDE;  // 64 x 64  (tf32 bits)
    float* el_s = (float*)(WsU + 64 * 64);      // 128
    float* er_s = el_s + 128;                   // 128

    int slot = blockIdx.y;
    int type = slot >> 1, m = slot & 1;
    const float* h  = type ? h_i : h_u;
    const float* W  = (type ? W_i : W_u) + m * 4096;
    const float* al = (type ? al_i : al_u) + m * 64;
    const float* ar = (type ? ar_i : ar_u) + m * 64;

    int tid = threadIdx.x;
    int row0 = blockIdx.x * 128;

    if (blockIdx.x == 0 && slot == 0 && tid < 4) g_w[tid] = 0.0f;

    for (int i = tid; i < 4096; i += 256) WsU[i] = to_tf32(W[i]);

    {
        int r  = tid >> 1;
        int kq = (tid & 1) * 32;
        int grow = row0 + r;
        unsigned int* dst = &hsU[r * HS_STRIDE + kq];
        if (grow < NN) {
            const float4* hp = (const float4*)&h[(size_t)grow * 64 + kq];
#pragma unroll
            for (int j = 0; j < 8; j++) {
                float4 v = hp[j];
                dst[4 * j + 0] = to_tf32(v.x);
                dst[4 * j + 1] = to_tf32(v.y);
                dst[4 * j + 2] = to_tf32(v.z);
                dst[4 * j + 3] = to_tf32(v.w);
            }
        } else {
#pragma unroll
            for (int j = 0; j < 32; j++) dst[j] = 0u;
        }
    }
    if (tid < 128) { el_s[tid] = 0.0f; er_s[tid] = 0.0f; }
    __syncthreads();

    int lane = tid & 31, warp = tid >> 5;
    int g = lane >> 2, tig = lane & 3;
    int mq = warp & 1, nq = warp >> 1;

    // B fragments: all 8 k-steps x 2 n-tiles, held in registers
    unsigned int bfr[8][2][2];
#pragma unroll
    for (int kt = 0; kt < 8; kt++)
#pragma unroll
        for (int nt = 0; nt < 2; nt++) {
            int n = nq * 16 + nt * 8 + g;
            bfr[kt][nt][0] = WsU[(kt * 8 + tig) * 64 + n];
            bfr[kt][nt][1] = WsU[(kt * 8 + tig + 4) * 64 + n];
        }

    float alv[2][2], arv[2][2];
#pragma unroll
    for (int nt = 0; nt < 2; nt++) {
        int c = nq * 16 + nt * 8 + 2 * tig;
        alv[nt][0] = al[c]; alv[nt][1] = al[c + 1];
        arv[nt][0] = ar[c]; arv[nt][1] = ar[c + 1];
    }

    __half* fbase = g_feat_h[slot];

#pragma unroll
    for (int mt = 0; mt < 4; mt++) {
        int rb = mq * 64 + mt * 16;
        float acc[2][4];
#pragma unroll
        for (int nt = 0; nt < 2; nt++)
#pragma unroll
            for (int i = 0; i < 4; i++) acc[nt][i] = 0.0f;

#pragma unroll
        for (int kt = 0; kt < 8; kt++) {
            int cb = kt * 8;
            unsigned int a0 = hsU[(rb + g) * HS_STRIDE + cb + tig];
            unsigned int a1 = hsU[(rb + g + 8) * HS_STRIDE + cb + tig];
            unsigned int a2 = hsU[(rb + g) * HS_STRIDE + cb + tig + 4];
            unsigned int a3 = hsU[(rb + g + 8) * HS_STRIDE + cb + tig + 4];
            mma_tf32(acc[0], a0, a1, a2, a3, bfr[kt][0][0], bfr[kt][0][1]);
            mma_tf32(acc[1], a0, a1, a2, a3, bfr[kt][1][0], bfr[kt][1][1]);
        }

        int r0 = row0 + rb + g, r1 = r0 + 8;
        float pel0 = 0.f, pel1 = 0.f, per0 = 0.f, per1 = 0.f;
#pragma unroll
        for (int nt = 0; nt < 2; nt++) {
            int c0 = nq * 16 + nt * 8 + 2 * tig;
            if (r0 < NN)
                *(__half2*)&fbase[(size_t)r0 * 64 + c0] =
                    __floats2half2_rn(acc[nt][0], acc[nt][1]);
            if (r1 < NN)
                *(__half2*)&fbase[(size_t)r1 * 64 + c0] =
                    __floats2half2_rn(acc[nt][2], acc[nt][3]);
            pel0 += acc[nt][0] * alv[nt][0] + acc[nt][1] * alv[nt][1];
            pel1 += acc[nt][2] * alv[nt][0] + acc[nt][3] * alv[nt][1];
            per0 += acc[nt][0] * arv[nt][0] + acc[nt][1] * arv[nt][1];
            per1 += acc[nt][2] * arv[nt][0] + acc[nt][3] * arv[nt][1];
        }
        pel0 += __shfl_xor_sync(~0u, pel0, 1); pel0 += __shfl_xor_sync(~0u, pel0, 2);
        pel1 += __shfl_xor_sync(~0u, pel1, 1); pel1 += __shfl_xor_sync(~0u, pel1, 2);
        per0 += __shfl_xor_sync(~0u, per0, 1); per0 += __shfl_xor_sync(~0u, per0, 2);
        per1 += __shfl_xor_sync(~0u, per1, 1); per1 += __shfl_xor_sync(~0u, per1, 2);
        if (tig == 0) {
            atomicAdd(&el_s[rb + g], pel0);
            atomicAdd(&el_s[rb + g + 8], pel1);
            atomicAdd(&er_s[rb + g], per0);
            atomicAdd(&er_s[rb + g + 8], per1);
        }
    }

    __syncthreads();
    if (tid < 128) {
        int row = row0 + tid;
        if (row < NN) {
            g_el[slot][row] = el_s[tid];
            g_er[slot][row] = er_s[tid];
            g_cnt[slot][row] = 0;
        }
    }
}

// ---------------- K2a: in-degree histogram ----------------------------------
__global__ void k_hist(const int* __restrict__ u_dst, const int* __restrict__ i_dst)
{
    int slot = 2 * blockIdx.z + blockIdx.y;
    const int* dst = (blockIdx.z ? i_dst : u_dst) + (size_t)blockIdx.y * EE;
    int i = blockIdx.x * 256 + threadIdx.x;
    if (i < EE) atomicAdd(&g_cnt[slot][dst[i]], 1);
}

// ---------------- K2b: per-block sums ----------------------------------------
__global__ void __launch_bounds__(256) k_scanA()
{
    __shared__ int ws[8];
    int slot = blockIdx.y;
    int i = blockIdx.x * 256 + threadIdx.x;
    int v = (i < NN) ? g_cnt[slot][i] : 0;
#pragma unroll
    for (int off = 16; off > 0; off >>= 1) v += __shfl_xor_sync(~0u, v, off);
    if ((threadIdx.x & 31) == 0) ws[threadIdx.x >> 5] = v;
    __syncthreads();
    if (threadIdx.x == 0) {
        int s = 0;
#pragma unroll
        for (int w = 0; w < 8; w++) s += ws[w];
        g_bsum[slot][blockIdx.x] = s;
    }
}

// ---------------- K2c: scan block sums (grid = 4 slots) ----------------------
__global__ void __launch_bounds__(512) k_scanB()
{
    __shared__ int buf[512];
    int s = blockIdx.x;
    int tid = threadIdx.x;
    int v = (tid < NBLK) ? g_bsum[s][tid] : 0;
    buf[tid] = v;
    __syncthreads();
    for (int off = 1; off < 512; off <<= 1) {
        int x = (tid >= off) ? buf[tid - off] : 0;
        __syncthreads();
        buf[tid] += x;
        __syncthreads();
    }
    if (tid < NBLK) g_bsum[s][tid] = buf[tid] - v;   // exclusive
    if (tid == 0) g_rowptr[s][NN] = EE;
}

// ---------------- K2d: block-local exclusive scan -> rowptr; reset cnt ------
__global__ void __launch_bounds__(256) k_scanC()
{
    __shared__ int buf[256];
    int slot = blockIdx.y;
    int tid = threadIdx.x;
    int i = blockIdx.x * 256 + tid;
    int v = (i < NN) ? g_cnt[slot][i] : 0;
    buf[tid] = v;
    __syncthreads();
    for (int off = 1; off < 256; off <<= 1) {
        int x = (tid >= off) ? buf[tid - off] : 0;
        __syncthreads();
        buf[tid] += x;
        __syncthreads();
    }
    if (i < NN) {
        g_rowptr[slot][i] = g_bsum[slot][blockIdx.x] + buf[tid] - v;
        g_cnt[slot][i] = 0;
    }
}

// ---------------- K2e: scatter (src, exp(score)) into CSR --------------------
__global__ void k_scatter(
    const int* __restrict__ u_src, const int* __restrict__ u_dst,
    const int* __restrict__ i_src, const int* __restrict__ i_dst)
{
    int slot = 2 * blockIdx.z + blockIdx.y;
    const int* src = (blockIdx.z ? i_src : u_src) + (size_t)blockIdx.y * EE;
    const int* dst = (blockIdx.z ? i_dst : u_dst) + (size_t)blockIdx.y * EE;
    int i = blockIdx.x * 256 + threadIdx.x;
    if (i >= EE) return;
    int s = src[i], d = dst[i];
    float e = g_el[slot][s] + g_er[slot][d];
    e = (e >= 0.0f) ? e : 0.2f * e;          // leaky_relu 0.2
    float ex = __expf(e);
    int pos = g_rowptr[slot][d] + atomicAdd(&g_cnt[slot][d], 1);
    g_csr[slot][pos] =
        ((unsigned long long)__float_as_uint(ex) << 32) | (unsigned int)s;
}

// ---------------- K2f: node-parallel aggregate, write normalized z ----------
__global__ void __launch_bounds__(256) k_aggr()
{
    int slot = blockIdx.y;
    int t = blockIdx.x * 256 + threadIdx.x;
    int node = t >> 3;
    int lane = t & 7;
    if (node >= NN) return;

    int start = g_rowptr[slot][node];
    int end   = g_rowptr[slot][node + 1];

    float acc[8] = {0.f, 0.f, 0.f, 0.f, 0.f, 0.f, 0.f, 0.f};
    float den = 0.0f;
    const __half* fb = g_feat_h[slot];
    const unsigned long long* csr = g_csr[slot];

    for (int p = start; p < end; p++) {
        unsigned long long pk = csr[p];
        int s = (int)(unsigned int)pk;
        float ex = __uint_as_float((unsigned int)(pk >> 32));
        den += ex;
        uint4 hv = *(const uint4*)&fb[(size_t)s * 64 + lane * 8];
        float2 f0 = __half22float2(*(__half2*)&hv.x);
        float2 f1 = __half22float2(*(__half2*)&hv.y);
        float2 f2 = __half22float2(*(__half2*)&hv.z);
        float2 f3 = __half22float2(*(__half2*)&hv.w);
        acc[0] += ex * f0.x; acc[1] += ex * f0.y;
        acc[2] += ex * f1.x; acc[3] += ex * f1.y;
        acc[4] += ex * f2.x; acc[5] += ex * f2.y;
        acc[6] += ex * f3.x; acc[7] += ex * f3.y;
    }

    float inv = __fdividef(1.0f, den + 1e-9f);
    float* zp = &g_z[slot][(size_t)node * 64 + lane * 8];
    *(float4*)zp       = make_float4(acc[0] * inv, acc[1] * inv,
                                     acc[2] * inv, acc[3] * inv);
    *(float4*)(zp + 4) = make_float4(acc[4] * inv, acc[5] * inv,
                                     acc[6] * inv, acc[7] * inv);
}

// ---------------- K4: semantic logits via mma.sync bf16 ---------------------
#define SEM_TILE_STRIDE 72

__global__ void __launch_bounds__(256) k_sem_mma(
    const float* __restrict__ uW1, const float* __restrict__ ub1,
    const float* __restrict__ uW2, const float* __restrict__ ugb,
    const float* __restrict__ iW1, const float* __restrict__ ib1,
    const float* __restrict__ iW2, const float* __restrict__ igb)
{
    __shared__ __align__(16) __nv_bfloat16 tile[2][32][SEM_TILE_STRIDE];
    __shared__ float gbs[128];
    __shared__ float wsum[8];

    int t = blockIdx.y;
    const float* W1 = t ? iW1 : uW1;
    const float* b1 = t ? ib1 : ub1;
    const float* W2 = t ? iW2 : uW2;
    const float* gb = t ? igb : ugb;

    int tid  = threadIdx.x;
    int warp = tid >> 5;
    int lane = tid & 31;
    int slot = warp >> 2;
    int nq   = warp & 3;

    if (tid < 128) gbs[tid] = gb[tid];

    unsigned int bfr[4][4][2];
    {
        int n = nq * 32 + (lane >> 2);
        int k0 = (lane & 3) * 2;
#pragma unroll
        for (int kt = 0; kt < 4; kt++) {
            int k = kt * 16 + k0;
#pragma unroll
            for (int nt = 0; nt < 4; nt++) {
                int nn = n + nt * 8;
                bfr[kt][nt][0] = bf2(W1[(size_t)k * 128 + nn],
                                     W1[(size_t)(k + 1) * 128 + nn]);
                bfr[kt][nt][1] = bf2(W1[(size_t)(k + 8) * 128 + nn],
                                     W1[(size_t)(k + 9) * 128 + nn]);
            }
        }
    }
    float w2v[4][2], bsv[4][2];
#pragma unroll
    for (int nt = 0; nt < 4; nt++) {
        int c = nq * 32 + nt * 8 + (lane & 3) * 2;
        w2v[nt][0] = W2[c];     w2v[nt][1] = W2[c + 1];
        bsv[nt][0] = b1[c];     bsv[nt][1] = b1[c + 1];
    }

    int s_slot = tid >> 7;
    int tid2   = tid & 127;
    int s_row  = tid2 >> 2;
    int s_colq = (tid2 & 3) * 16;

    int ld_row = lane & 15;
    int ld_off = (lane >> 4) * 16;

    float s = 0.0f;

    const int NITER = NN / 32;
    __syncthreads();
    for (int it = blockIdx.x; it < NITER; it += gridDim.x) {
        int row = it * 32 + s_row;
        const float* zrow = g_z[2 * t + s_slot] + (size_t)row * 64 + s_colq;
        unsigned int* drow = (unsigned int*)&tile[s_slot][s_row][0];
#pragma unroll
        for (int i = 0; i < 4; i++) {
            float4 v = *(const float4*)(zrow + 4 * i);
            int c = s_colq + 4 * i;
            unsigned int lo = bf2(elu_fast(v.x + gbs[s_slot * 64 + c]),
                                  elu_fast(v.y + gbs[s_slot * 64 + c + 1]));
            unsigned int hi = bf2(elu_fast(v.z + gbs[s_slot * 64 + c + 2]),
                                  elu_fast(v.w + gbs[s_slot * 64 + c + 3]));
            drow[(s_colq >> 1) + 2 * i]     = lo;
            drow[(s_colq >> 1) + 2 * i + 1] = hi;
        }
        __syncthreads();

#pragma unroll
        for (int mt = 0; mt < 2; mt++) {
            unsigned int a[4][4];
            const __nv_bfloat16* ap = &tile[slot][mt * 16 + ld_row][0];
            unsigned int abase = (unsigned int)__cvta_generic_to_shared(ap) + ld_off;
#pragma unroll
            for (int kt = 0; kt < 4; kt++) {
                asm volatile(
                    "ldmatrix.sync.aligned.m8n8.x4.shared.b16 {%0,%1,%2,%3}, [%4];"
                    : "=r"(a[kt][0]), "=r"(a[kt][1]), "=r"(a[kt][2]), "=r"(a[kt][3])
                    : "r"(abase + kt * 32));
            }
#pragma unroll
            for (int nt = 0; nt < 4; nt++) {
                float c0 = 0.f, c1 = 0.f, c2 = 0.f, c3 = 0.f;
#pragma unroll
                for (int kt = 0; kt < 4; kt++)
                    mma_bf16(c0, c1, c2, c3,
                             a[kt][0], a[kt][1], a[kt][2], a[kt][3],
                             bfr[kt][nt][0], bfr[kt][nt][1]);
                s += tanh_fast(c0 + bsv[nt][0]) * w2v[nt][0];
                s += tanh_fast(c1 + bsv[nt][1]) * w2v[nt][1];
                s += tanh_fast(c2 + bsv[nt][0]) * w2v[nt][0];
                s += tanh_fast(c3 + bsv[nt][1]) * w2v[nt][1];
            }
        }
        __syncthreads();
    }

#pragma unroll
    for (int off = 16; off > 0; off >>= 1)
        s += __shfl_xor_sync(0xffffffffu, s, off);
    if (lane == 0) wsum[warp] = s;
    __syncthreads();
    if (tid < 2) {
        float tot = wsum[tid * 4] + wsum[tid * 4 + 1]
                  + wsum[tid * 4 + 2] + wsum[tid * 4 + 3];
        atomicAdd(&g_w[2 * t + tid], tot);
    }
}

// ---------------- K6: gather + bias/ELU + beta + GEMM + ReLU + LN ------------
__global__ void __launch_bounds__(256) k_final(
    const int* __restrict__ user_idx, const int* __restrict__ item_idx,
    const int* __restrict__ neg_idx,
    const float* __restrict__ u_gb, const float* __restrict__ i_gb,
    const float* __restrict__ userW, const float* __restrict__ userb,
    const float* __restrict__ itemW, const float* __restrict__ itemb,
    const float* __restrict__ ln_g, const float* __restrict__ ln_b,
    float* __restrict__ out)
{
    __shared__ float Ws[4096];
    __shared__ float bs[64], gs[64], lbs[64];
    __shared__ float gb0[64], gb1[64];
    __shared__ float embs[4][64];
    __shared__ float red[4][2];

    int tid = threadIdx.x;
    int tx = tid & 63, ty = tid >> 6;
    int r0 = blockIdx.x * 4;
    bool isUser = (r0 < BB);
    const float* W    = isUser ? userW : itemW;
    const float* bias = isUser ? userb : itemb;
    const float* gbm  = isUser ? u_gb : i_gb;

    for (int i = tid; i < 4096; i += 256) Ws[i] = W[i];
    if (tid < 64) {
        bs[tid] = bias[tid]; gs[tid] = ln_g[tid]; lbs[tid] = ln_b[tid];
        gb0[tid] = gbm[tid]; gb1[tid] = gbm[64 + tid];
    }

    int r = r0 + ty;
    int type, idx;
    if (r < BB)            { type = 0; idx = user_idx[r]; }
    else if (r < 2 * BB)   { type = 1; idx = item_idx[r - BB]; }
    else                   { type = 1; idx = neg_idx[r - 2 * BB]; }

    float w0 = g_w[2 * type] * (1.0f / NN);
    float w1 = g_w[2 * type + 1] * (1.0f / NN);
    float mx = fmaxf(w0, w1);
    float e0 = __expf(w0 - mx), e1 = __expf(w1 - mx);
    float binv = 1.0f / (e0 + e1);
    float b0 = e0 * binv, b1 = e1 * binv;

    __syncthreads();
    float zr0 = g_z[2 * type][(size_t)idx * 64 + tx] + gb0[tx];
    float zr1 = g_z[2 * type + 1][(size_t)idx * 64 + tx] + gb1[tx];
    float emb = b0 * elu_fast(zr0) + b1 * elu_fast(zr1);
    embs[ty][tx] = emb;
    __syncthreads();

    float y = bs[tx];
#pragma unroll 16
    for (int k = 0; k < 64; k++) y += embs[ty][k] * Ws[k * 64 + tx];
    y = fmaxf(y, 0.0f);

    float s = y;
#pragma unroll
    for (int off = 16; off > 0; off >>= 1) s += __shfl_xor_sync(0xffffffffu, s, off);
    int half = tx >> 5;
    if ((tx & 31) == 0) red[ty][half] = s;
    __syncthreads();
    float mu = (red[ty][0] + red[ty][1]) * (1.0f / 64.0f);
    float dv = y - mu;
    float s2 = dv * dv;
#pragma unroll
    for (int off = 16; off > 0; off >>= 1) s2 += __shfl_xor_sync(0xffffffffu, s2, off);
    __syncthreads();
    if ((tx & 31) == 0) red[ty][half] = s2;
    __syncthreads();
    float var = (red[ty][0] + red[ty][1]) * (1.0f / 64.0f);
    float o = gs[tx] * dv * rsqrtf(var + 1e-5f) + lbs[tx];
    out[(size_t)r * 64 + tx] = o;
}

// ---------------- host ------------------------------------------------------
extern "C" void kernel_launch(void* const* d_in, const int* in_sizes, int n_in,
                              void* d_out, int out_size)
{
    const int*   user_idx  = (const int*)d_in[0];
    const int*   item_idx  = (const int*)d_in[1];
    const int*   neg_idx   = (const int*)d_in[2];
    const float* user_feat = (const float*)d_in[3];
    const float* item_feat = (const float*)d_in[4];
    const int*   u_src = (const int*)d_in[5];
    const int*   u_dst = (const int*)d_in[6];
    const int*   i_src = (const int*)d_in[7];
    const int*   i_dst = (const int*)d_in[8];
    const float* u_W  = (const float*)d_in[9];
    const float* u_al = (const float*)d_in[10];
    const float* u_ar = (const float*)d_in[11];
    const float* u_b  = (const float*)d_in[12];
    const float* i_W  = (const float*)d_in[13];
    const float* i_al = (const float*)d_in[14];
    const float* i_ar = (const float*)d_in[15];
    const float* i_b  = (const float*)d_in[16];
    const float* u_saW1 = (const float*)d_in[17];
    const float* u_sab1 = (const float*)d_in[18];
    const float* u_saW2 = (const float*)d_in[19];
    const float* i_saW1 = (const float*)d_in[20];
    const float* i_sab1 = (const float*)d_in[21];
    const float* i_saW2 = (const float*)d_in[22];
    const float* userW = (const float*)d_in[23];
    const float* userb = (const float*)d_in[24];
    const float* itemW = (const float*)d_in[25];
    const float* itemb = (const float*)d_in[26];
    const float* ln_g  = (const float*)d_in[27];
    const float* ln_b  = (const float*)d_in[28];
    float* out = (float*)d_out;

    cudaFuncSetAttribute(k_gemm_feat_mma,
                         cudaFuncAttributeMaxDynamicSharedMemorySize, K1M_SMEM);

    dim3 grid1((NN + 127) / 128, 4);             // 782 x slot
    dim3 gridE((EE + 255) / 256, 2, 2);          // 1954 x m x type
    dim3 gridS(NBLK, 4);                         // 391 x slot
    dim3 gridG((NN * 8 + 255) / 256, 4);         // 3125 x slot

    k_gemm_feat_mma<<<grid1, 256, K1M_SMEM>>>(user_feat, item_feat, u_W, i_W,
                                              u_al, i_al, u_ar, i_ar);
    k_hist<<<gridE, 256>>>(u_dst, i_dst);
    k_scanA<<<gridS, 256>>>();
    k_scanB<<<4, 512>>>();
    k_scanC<<<gridS, 256>>>();
    k_scatter<<<gridE, 256>>>(u_src, u_dst, i_src, i_dst);
    k_aggr<<<gridG, 256>>>();

    dim3 semGrid(256, 2);
    k_sem_mma<<<semGrid, 256>>>(u_saW1, u_sab1, u_saW2, u_b,
                                i_saW1, i_sab1, i_saW2, i_b);
    k_final<<<(3 * BB) / 4, 256>>>(user_idx, item_idx, neg_idx, u_b, i_b,
                                   userW, userb, itemW, itemb, ln_g, ln_b, out);
}

// round 10
// speedup vs baseline: 2.3730x; 1.0889x over previous
#include <cuda_runtime.h>
#include <cuda_bf16.h>
#include <cuda_fp16.h>
#include <math.h>

#define NN 100000
#define EE 500000
#define BB 8192
#define NBLK 391                     // ceil(NN/256)
#define NGB 782                      // gemm blocks per type (ceil(NN/128))
#define NHB 977                      // hist blocks per metapath (512 edges each)

// ---------------- scratch (device globals) ----------------------------------
__device__ __half g_feat_h[4][NN * 64];        // fp16 feat per slot
__device__ float g_z[4][NN * 64];              // normalized GAT output
__device__ float g_el[4][NN];
__device__ float g_er[4][NN];
__device__ int   g_cnt[4][NN];                 // histogram (zero at call entry)
__device__ int   g_cur[4][NN];                 // scatter cursor
__device__ int   g_rowptr[4][NN + 1];
__device__ int   g_bsum[4][NBLK];
__device__ unsigned long long g_csr[4][EE];    // (exp(score) << 32) | src
__device__ float g_w[4];

// ---------------- helpers ----------------------------------------------------
__device__ __forceinline__ float tanh_fast(float x) {
    float y; asm("tanh.approx.f32 %0, %1;" : "=f"(y) : "f"(x)); return y;
}
__device__ __forceinline__ float elu_fast(float x) {
    return x > 0.f ? x : (__expf(x) - 1.f);
}
__device__ __forceinline__ unsigned int bf2(float lo, float hi) {
    __nv_bfloat162 v = __floats2bfloat162_rn(lo, hi);
    return *reinterpret_cast<unsigned int*>(&v);
}
__device__ __forceinline__ unsigned int to_tf32(float f) {
    unsigned int u; asm("cvt.rna.tf32.f32 %0, %1;" : "=r"(u) : "f"(f)); return u;
}
__device__ __forceinline__ void mma_bf16(
    float& c0, float& c1, float& c2, float& c3,
    unsigned int a0, unsigned int a1, unsigned int a2, unsigned int a3,
    unsigned int b0, unsigned int b1)
{
    asm("mma.sync.aligned.m16n8k16.row.col.f32.bf16.bf16.f32 "
        "{%0,%1,%2,%3}, {%4,%5,%6,%7}, {%8,%9}, {%0,%1,%2,%3};"
        : "+f"(c0), "+f"(c1), "+f"(c2), "+f"(c3)
        : "r"(a0), "r"(a1), "r"(a2), "r"(a3), "r"(b0), "r"(b1));
}
__device__ __forceinline__ void mma_tf32(
    float* c, unsigned int a0, unsigned int a1, unsigned int a2, unsigned int a3,
    unsigned int b0, unsigned int b1)
{
    asm("mma.sync.aligned.m16n8k8.row.col.f32.tf32.tf32.f32 "
        "{%0,%1,%2,%3}, {%4,%5,%6,%7}, {%8,%9}, {%0,%1,%2,%3};"
        : "+f"(c[0]), "+f"(c[1]), "+f"(c[2]), "+f"(c[3])
        : "r"(a0), "r"(a1), "r"(a2), "r"(a3), "r"(b0), "r"(b1));
}

// ---------------- K1: fused feat GEMM (both metapaths) + degree histogram ---
// grid (NGB + 2*NHB, 2 types). GEMM blocks: x < NGB; hist blocks: rest.
#define HS_STRIDE 68
#define K1F_SMEM ((128 * HS_STRIDE + 2 * 4096 + 512) * 4)

__global__ void __launch_bounds__(256) k_fused1(
    const float* __restrict__ h_u, const float* __restrict__ h_i,
    const float* __restrict__ W_u, const float* __restrict__ W_i,
    const float* __restrict__ al_u, const float* __restrict__ al_i,
    const float* __restrict__ ar_u, const float* __restrict__ ar_i,
    const int* __restrict__ u_dst, const int* __restrict__ i_dst)
{
    int type = blockIdx.y;
    int tid  = threadIdx.x;

    // ---- histogram role ----
    if (blockIdx.x >= NGB) {
        int hb = blockIdx.x - NGB;           // 0 .. 2*NHB-1
        int m  = hb >= NHB;
        int b  = hb - m * NHB;
        int slot = 2 * type + m;
        const int* dst = (type ? i_dst : u_dst) + (size_t)m * EE;
        int e0 = b * 512 + tid;
        if (e0 < EE) atomicAdd(&g_cnt[slot][dst[e0]], 1);
        int e1 = e0 + 256;
        if (e1 < EE) atomicAdd(&g_cnt[slot][dst[e1]], 1);
        return;
    }

    // ---- gemm role: both metapaths of this type from one staged h tile ----
    extern __shared__ unsigned int smemu[];
    unsigned int* hsU = smemu;                  // 128 x 68 (tf32 bits)
    unsigned int* WsU = hsU + 128 * HS_STRIDE;  // 2 x 64 x 64 (tf32 bits)
    float* el_s = (float*)(WsU + 2 * 4096);     // 2 x 128
    float* er_s = el_s + 256;                   // 2 x 128

    const float* h  = type ? h_i : h_u;
    const float* W  = type ? W_i : W_u;          // both metapaths
    const float* al = type ? al_i : al_u;
    const float* ar = type ? ar_i : ar_u;

    int row0 = blockIdx.x * 128;

    if (blockIdx.x == 0 && type == 0 && tid < 4) g_w[tid] = 0.0f;

    for (int i = tid; i < 8192; i += 256) WsU[i] = to_tf32(W[i]);

    {
        int r  = tid >> 1;
        int kq = (tid & 1) * 32;
        int grow = row0 + r;
        unsigned int* dst = &hsU[r * HS_STRIDE + kq];
        if (grow < NN) {
            const float4* hp = (const float4*)&h[(size_t)grow * 64 + kq];
#pragma unroll
            for (int j = 0; j < 8; j++) {
                float4 v = hp[j];
                dst[4 * j + 0] = to_tf32(v.x);
                dst[4 * j + 1] = to_tf32(v.y);
                dst[4 * j + 2] = to_tf32(v.z);
                dst[4 * j + 3] = to_tf32(v.w);
            }
        } else {
#pragma unroll
            for (int j = 0; j < 32; j++) dst[j] = 0u;
        }
    }
    el_s[tid] = 0.0f;
    er_s[tid] = 0.0f;
    __syncthreads();

    int lane = tid & 31, warp = tid >> 5;
    int g = lane >> 2, tig = lane & 3;
    int mq = warp & 1, nq = warp >> 1;

#pragma unroll
    for (int m2 = 0; m2 < 2; m2++) {
        int slot = 2 * type + m2;
        const unsigned int* Wm = WsU + m2 * 4096;

        unsigned int bfr[8][2][2];
#pragma unroll
        for (int kt = 0; kt < 8; kt++)
#pragma unroll
            for (int nt = 0; nt < 2; nt++) {
                int n = nq * 16 + nt * 8 + g;
                bfr[kt][nt][0] = Wm[(kt * 8 + tig) * 64 + n];
                bfr[kt][nt][1] = Wm[(kt * 8 + tig + 4) * 64 + n];
            }

        float alv[2][2], arv[2][2];
#pragma unroll
        for (int nt = 0; nt < 2; nt++) {
            int c = m2 * 64 + nq * 16 + nt * 8 + 2 * tig;
            alv[nt][0] = al[c]; alv[nt][1] = al[c + 1];
            arv[nt][0] = ar[c]; arv[nt][1] = ar[c + 1];
        }

        __half* fbase = g_feat_h[slot];

#pragma unroll
        for (int mt = 0; mt < 4; mt++) {
            int rb = mq * 64 + mt * 16;
            float acc[2][4];
#pragma unroll
            for (int nt = 0; nt < 2; nt++)
#pragma unroll
                for (int i = 0; i < 4; i++) acc[nt][i] = 0.0f;

#pragma unroll
            for (int kt = 0; kt < 8; kt++) {
                int cb = kt * 8;
                unsigned int a0 = hsU[(rb + g) * HS_STRIDE + cb + tig];
                unsigned int a1 = hsU[(rb + g + 8) * HS_STRIDE + cb + tig];
                unsigned int a2 = hsU[(rb + g) * HS_STRIDE + cb + tig + 4];
                unsigned int a3 = hsU[(rb + g + 8) * HS_STRIDE + cb + tig + 4];
                mma_tf32(acc[0], a0, a1, a2, a3, bfr[kt][0][0], bfr[kt][0][1]);
                mma_tf32(acc[1], a0, a1, a2, a3, bfr[kt][1][0], bfr[kt][1][1]);
            }

            int r0 = row0 + rb + g, r1 = r0 + 8;
            float pel0 = 0.f, pel1 = 0.f, per0 = 0.f, per1 = 0.f;
#pragma unroll
            for (int nt = 0; nt < 2; nt++) {
                int c0 = nq * 16 + nt * 8 + 2 * tig;
                if (r0 < NN)
                    *(__half2*)&fbase[(size_t)r0 * 64 + c0] =
                        __floats2half2_rn(acc[nt][0], acc[nt][1]);
                if (r1 < NN)
                    *(__half2*)&fbase[(size_t)r1 * 64 + c0] =
                        __floats2half2_rn(acc[nt][2], acc[nt][3]);
                pel0 += acc[nt][0] * alv[nt][0] + acc[nt][1] * alv[nt][1];
                pel1 += acc[nt][2] * alv[nt][0] + acc[nt][3] * alv[nt][1];
                per0 += acc[nt][0] * arv[nt][0] + acc[nt][1] * arv[nt][1];
                per1 += acc[nt][2] * arv[nt][0] + acc[nt][3] * arv[nt][1];
            }
            pel0 += __shfl_xor_sync(~0u, pel0, 1); pel0 += __shfl_xor_sync(~0u, pel0, 2);
            pel1 += __shfl_xor_sync(~0u, pel1, 1); pel1 += __shfl_xor_sync(~0u, pel1, 2);
            per0 += __shfl_xor_sync(~0u, per0, 1); per0 += __shfl_xor_sync(~0u, per0, 2);
            per1 += __shfl_xor_sync(~0u, per1, 1); per1 += __shfl_xor_sync(~0u, per1, 2);
            if (tig == 0) {
                atomicAdd(&el_s[m2 * 128 + rb + g], pel0);
                atomicAdd(&el_s[m2 * 128 + rb + g + 8], pel1);
                atomicAdd(&er_s[m2 * 128 + rb + g], per0);
                atomicAdd(&er_s[m2 * 128 + rb + g + 8], per1);
            }
        }
    }

    __syncthreads();
    {
        int m2 = tid >> 7;            // 0/1
        int r  = tid & 127;
        int row = row0 + r;
        if (row < NN) {
            int slot = 2 * type + m2;
            g_el[slot][row] = el_s[m2 * 128 + r];
            g_er[slot][row] = er_s[m2 * 128 + r];
        }
    }
}

// ---------------- K2b: per-block sums ----------------------------------------
__global__ void __launch_bounds__(256) k_scanA()
{
    __shared__ int ws[8];
    int slot = blockIdx.y;
    int i = blockIdx.x * 256 + threadIdx.x;
    int v = (i < NN) ? g_cnt[slot][i] : 0;
#pragma unroll
    for (int off = 16; off > 0; off >>= 1) v += __shfl_xor_sync(~0u, v, off);
    if ((threadIdx.x & 31) == 0) ws[threadIdx.x >> 5] = v;
    __syncthreads();
    if (threadIdx.x == 0) {
        int s = 0;
#pragma unroll
        for (int w = 0; w < 8; w++) s += ws[w];
        g_bsum[slot][blockIdx.x] = s;
    }
}

// ---------------- K2d: rowptr = prefix(bsum[0..bx-1]) + local scan ----------
// Also zeroes g_cnt (restores call-entry invariant) and g_cur (scatter cursor).
__global__ void __launch_bounds__(256) k_scanC()
{
    __shared__ int buf[256];
    __shared__ int wred[8];
    __shared__ int base_sh;
    int slot = blockIdx.y;
    int bx = blockIdx.x;
    int tid = threadIdx.x;

    // sum of bsum[0 .. bx-1]
    int pre = 0;
    for (int j = tid; j < bx; j += 256) pre += g_bsum[slot][j];
#pragma unroll
    for (int off = 16; off > 0; off >>= 1) pre += __shfl_xor_sync(~0u, pre, off);
    if ((tid & 31) == 0) wred[tid >> 5] = pre;
    __syncthreads();
    if (tid == 0) {
        int s = 0;
#pragma unroll
        for (int w = 0; w < 8; w++) s += wred[w];
        base_sh = s;
    }

    int i = bx * 256 + tid;
    int v = (i < NN) ? g_cnt[slot][i] : 0;
    buf[tid] = v;
    __syncthreads();
    for (int off = 1; off < 256; off <<= 1) {
        int x = (tid >= off) ? buf[tid - off] : 0;
        __syncthreads();
        buf[tid] += x;
        __syncthreads();
    }
    if (i < NN) {
        g_rowptr[slot][i] = base_sh + buf[tid] - v;
        g_cnt[slot][i] = 0;      // restore invariant for next call
        g_cur[slot][i] = 0;      // scatter cursor
    }
    if (bx == NBLK - 1 && tid == 0) g_rowptr[slot][NN] = EE;
}

// ---------------- K2e: scatter (src, exp(score)) into CSR --------------------
__global__ void k_scatter(
    const int* __restrict__ u_src, const int* __restrict__ u_dst,
    const int* __restrict__ i_src, const int* __restrict__ i_dst)
{
    int slot = 2 * blockIdx.z + blockIdx.y;
    const int* src = (blockIdx.z ? i_src : u_src) + (size_t)blockIdx.y * EE;
    const int* dst = (blockIdx.z ? i_dst : u_dst) + (size_t)blockIdx.y * EE;
    int i = blockIdx.x * 256 + threadIdx.x;
    if (i >= EE) return;
    int s = src[i], d = dst[i];
    float e = g_el[slot][s] + g_er[slot][d];
    e = (e >= 0.0f) ? e : 0.2f * e;          // leaky_relu 0.2
    float ex = __expf(e);
    int pos = g_rowptr[slot][d] + atomicAdd(&g_cur[slot][d], 1);
    g_csr[slot][pos] =
        ((unsigned long long)__float_as_uint(ex) << 32) | (unsigned int)s;
}

// ---------------- K2f: node-parallel aggregate, write normalized z ----------
__global__ void __launch_bounds__(256) k_aggr()
{
    int slot = blockIdx.y;
    int t = blockIdx.x * 256 + threadIdx.x;
    int node = t >> 3;
    int lane = t & 7;
    if (node >= NN) return;

    int start = g_rowptr[slot][node];
    int end   = g_rowptr[slot][node + 1];

    float acc[8] = {0.f, 0.f, 0.f, 0.f, 0.f, 0.f, 0.f, 0.f};
    float den = 0.0f;
    const __half* fb = g_feat_h[slot];
    const unsigned long long* csr = g_csr[slot];

    for (int p = start; p < end; p++) {
        unsigned long long pk = csr[p];
        int s = (int)(unsigned int)pk;
        float ex = __uint_as_float((unsigned int)(pk >> 32));
        den += ex;
        uint4 hv = *(const uint4*)&fb[(size_t)s * 64 + lane * 8];
        float2 f0 = __half22float2(*(__half2*)&hv.x);
        float2 f1 = __half22float2(*(__half2*)&hv.y);
        float2 f2 = __half22float2(*(__half2*)&hv.z);
        float2 f3 = __half22float2(*(__half2*)&hv.w);
        acc[0] += ex * f0.x; acc[1] += ex * f0.y;
        acc[2] += ex * f1.x; acc[3] += ex * f1.y;
        acc[4] += ex * f2.x; acc[5] += ex * f2.y;
        acc[6] += ex * f3.x; acc[7] += ex * f3.y;
    }

    float inv = __fdividef(1.0f, den + 1e-9f);
    float* zp = &g_z[slot][(size_t)node * 64 + lane * 8];
    *(float4*)zp       = make_float4(acc[0] * inv, acc[1] * inv,
                                     acc[2] * inv, acc[3] * inv);
    *(float4*)(zp + 4) = make_float4(acc[4] * inv, acc[5] * inv,
                                     acc[6] * inv, acc[7] * inv);
}

// ---------------- K4: semantic logits via mma.sync bf16 ---------------------
#define SEM_TILE_STRIDE 72

__global__ void __launch_bounds__(256) k_sem_mma(
    const float* __restrict__ uW1, const float* __restrict__ ub1,
    const float* __restrict__ uW2, const float* __restrict__ ugb,
    const float* __restrict__ iW1, const float* __restrict__ ib1,
    const float* __restrict__ iW2, const float* __restrict__ igb)
{
    __shared__ __align__(16) __nv_bfloat16 tile[2][32][SEM_TILE_STRIDE];
    __shared__ float gbs[128];
    __shared__ float wsum[8];

    int t = blockIdx.y;
    const float* W1 = t ? iW1 : uW1;
    const float* b1 = t ? ib1 : ub1;
    const float* W2 = t ? iW2 : uW2;
    const float* gb = t ? igb : ugb;

    int tid  = threadIdx.x;
    int warp = tid >> 5;
    int lane = tid & 31;
    int slot = warp >> 2;
    int nq   = warp & 3;

    if (tid < 128) gbs[tid] = gb[tid];

    unsigned int bfr[4][4][2];
    {
        int n = nq * 32 + (lane >> 2);
        int k0 = (lane & 3) * 2;
#pragma unroll
        for (int kt = 0; kt < 4; kt++) {
            int k = kt * 16 + k0;
#pragma unroll
            for (int nt = 0; nt < 4; nt++) {
                int nn = n + nt * 8;
                bfr[kt][nt][0] = bf2(W1[(size_t)k * 128 + nn],
                                     W1[(size_t)(k + 1) * 128 + nn]);
                bfr[kt][nt][1] = bf2(W1[(size_t)(k + 8) * 128 + nn],
                                     W1[(size_t)(k + 9) * 128 + nn]);
            }
        }
    }
    float w2v[4][2], bsv[4][2];
#pragma unroll
    for (int nt = 0; nt < 4; nt++) {
        int c = nq * 32 + nt * 8 + (lane & 3) * 2;
        w2v[nt][0] = W2[c];     w2v[nt][1] = W2[c + 1];
        bsv[nt][0] = b1[c];     bsv[nt][1] = b1[c + 1];
    }

    int s_slot = tid >> 7;
    int tid2   = tid & 127;
    int s_row  = tid2 >> 2;
    int s_colq = (tid2 & 3) * 16;

    int ld_row = lane & 15;
    int ld_off = (lane >> 4) * 16;

    float s = 0.0f;

    const int NITER = NN / 32;
    __syncthreads();
    for (int it = blockIdx.x; it < NITER; it += gridDim.x) {
        int row = it * 32 + s_row;
        const float* zrow = g_z[2 * t + s_slot] + (size_t)row * 64 + s_colq;
        unsigned int* drow = (unsigned int*)&tile[s_slot][s_row][0];
#pragma unroll
        for (int i = 0; i < 4; i++) {
            float4 v = *(const float4*)(zrow + 4 * i);
            int c = s_colq + 4 * i;
            unsigned int lo = bf2(elu_fast(v.x + gbs[s_slot * 64 + c]),
                                  elu_fast(v.y + gbs[s_slot * 64 + c + 1]));
            unsigned int hi = bf2(elu_fast(v.z + gbs[s_slot * 64 + c + 2]),
                                  elu_fast(v.w + gbs[s_slot * 64 + c + 3]));
            drow[(s_colq >> 1) + 2 * i]     = lo;
            drow[(s_colq >> 1) + 2 * i + 1] = hi;
        }
        __syncthreads();

#pragma unroll
        for (int mt = 0; mt < 2; mt++) {
            unsigned int a[4][4];
            const __nv_bfloat16* ap = &tile[slot][mt * 16 + ld_row][0];
            unsigned int abase = (unsigned int)__cvta_generic_to_shared(ap) + ld_off;
#pragma unroll
            for (int kt = 0; kt < 4; kt++) {
                asm volatile(
                    "ldmatrix.sync.aligned.m8n8.x4.shared.b16 {%0,%1,%2,%3}, [%4];"
                    : "=r"(a[kt][0]), "=r"(a[kt][1]), "=r"(a[kt][2]), "=r"(a[kt][3])
                    : "r"(abase + kt * 32));
            }
#pragma unroll
            for (int nt = 0; nt < 4; nt++) {
                float c0 = 0.f, c1 = 0.f, c2 = 0.f, c3 = 0.f;
#pragma unroll
                for (int kt = 0; kt < 4; kt++)
                    mma_bf16(c0, c1, c2, c3,
                             a[kt][0], a[kt][1], a[kt][2], a[kt][3],
                             bfr[kt][nt][0], bfr[kt][nt][1]);
                s += tanh_fast(c0 + bsv[nt][0]) * w2v[nt][0];
                s += tanh_fast(c1 + bsv[nt][1]) * w2v[nt][1];
                s += tanh_fast(c2 + bsv[nt][0]) * w2v[nt][0];
                s += tanh_fast(c3 + bsv[nt][1]) * w2v[nt][1];
            }
        }
        __syncthreads();
    }

#pragma unroll
    for (int off = 16; off > 0; off >>= 1)
        s += __shfl_xor_sync(0xffffffffu, s, off);
    if (lane == 0) wsum[warp] = s;
    __syncthreads();
    if (tid < 2) {
        float tot = wsum[tid * 4] + wsum[tid * 4 + 1]
                  + wsum[tid * 4 + 2] + wsum[tid * 4 + 3];
        atomicAdd(&g_w[2 * t + tid], tot);
    }
}

// ---------------- K6: gather + bias/ELU + beta + GEMM + ReLU + LN ------------
__global__ void __launch_bounds__(256) k_final(
    const int* __restrict__ user_idx, const int* __restrict__ item_idx,
    const int* __restrict__ neg_idx,
    const float* __restrict__ u_gb, const float* __restrict__ i_gb,
    const float* __restrict__ userW, const float* __restrict__ userb,
    const float* __restrict__ itemW, const float* __restrict__ itemb,
    const float* __restrict__ ln_g, const float* __restrict__ ln_b,
    float* __restrict__ out)
{
    __shared__ float Ws[4096];
    __shared__ float bs[64], gs[64], lbs[64];
    __shared__ float gb0[64], gb1[64];
    __shared__ float embs[4][64];
    __shared__ float red[4][2];

    int tid = threadIdx.x;
    int tx = tid & 63, ty = tid >> 6;
    int r0 = blockIdx.x * 4;
    bool isUser = (r0 < BB);
    const float* W    = isUser ? userW : itemW;
    const float* bias = isUser ? userb : itemb;
    const float* gbm  = isUser ? u_gb : i_gb;

    for (int i = tid; i < 4096; i += 256) Ws[i] = W[i];
    if (tid < 64) {
        bs[tid] = bias[tid]; gs[tid] = ln_g[tid]; lbs[tid] = ln_b[tid];
        gb0[tid] = gbm[tid]; gb1[tid] = gbm[64 + tid];
    }

    int r = r0 + ty;
    int type, idx;
    if (r < BB)            { type = 0; idx = user_idx[r]; }
    else if (r < 2 * BB)   { type = 1; idx = item_idx[r - BB]; }
    else                   { type = 1; idx = neg_idx[r - 2 * BB]; }

    float w0 = g_w[2 * type] * (1.0f / NN);
    float w1 = g_w[2 * type + 1] * (1.0f / NN);
    float mx = fmaxf(w0, w1);
    float e0 = __expf(w0 - mx), e1 = __expf(w1 - mx);
    float binv = 1.0f / (e0 + e1);
    float b0 = e0 * binv, b1 = e1 * binv;

    __syncthreads();
    float zr0 = g_z[2 * type][(size_t)idx * 64 + tx] + gb0[tx];
    float zr1 = g_z[2 * type + 1][(size_t)idx * 64 + tx] + gb1[tx];
    float emb = b0 * elu_fast(zr0) + b1 * elu_fast(zr1);
    embs[ty][tx] = emb;
    __syncthreads();

    float y = bs[tx];
#pragma unroll 16
    for (int k = 0; k < 64; k++) y += embs[ty][k] * Ws[k * 64 + tx];
    y = fmaxf(y, 0.0f);

    float s = y;
#pragma unroll
    for (int off = 16; off > 0; off >>= 1) s += __shfl_xor_sync(0xffffffffu, s, off);
    int half = tx >> 5;
    if ((tx & 31) == 0) red[ty][half] = s;
    __syncthreads();
    float mu = (red[ty][0] + red[ty][1]) * (1.0f / 64.0f);
    float dv = y - mu;
    float s2 = dv * dv;
#pragma unroll
    for (int off = 16; off > 0; off >>= 1) s2 += __shfl_xor_sync(0xffffffffu, s2, off);
    __syncthreads();
    if ((tx & 31) == 0) red[ty][half] = s2;
    __syncthreads();
    float var = (red[ty][0] + red[ty][1]) * (1.0f / 64.0f);
    float o = gs[tx] * dv * rsqrtf(var + 1e-5f) + lbs[tx];
    out[(size_t)r * 64 + tx] = o;
}

// ---------------- host ------------------------------------------------------
extern "C" void kernel_launch(void* const* d_in, const int* in_sizes, int n_in,
                              void* d_out, int out_size)
{
    const int*   user_idx  = (const int*)d_in[0];
    const int*   item_idx  = (const int*)d_in[1];
    const int*   neg_idx   = (const int*)d_in[2];
    const float* user_feat = (const float*)d_in[3];
    const float* item_feat = (const float*)d_in[4];
    const int*   u_src = (const int*)d_in[5];
    const int*   u_dst = (const int*)d_in[6];
    const int*   i_src = (const int*)d_in[7];
    const int*   i_dst = (const int*)d_in[8];
    const float* u_W  = (const float*)d_in[9];
    const float* u_al = (const float*)d_in[10];
    const float* u_ar = (const float*)d_in[11];
    const float* u_b  = (const float*)d_in[12];
    const float* i_W  = (const float*)d_in[13];
    const float* i_al = (const float*)d_in[14];
    const float* i_ar = (const float*)d_in[15];
    const float* i_b  = (const float*)d_in[16];
    const float* u_saW1 = (const float*)d_in[17];
    const float* u_sab1 = (const float*)d_in[18];
    const float* u_saW2 = (const float*)d_in[19];
    const float* i_saW1 = (const float*)d_in[20];
    const float* i_sab1 = (const float*)d_in[21];
    const float* i_saW2 = (const float*)d_in[22];
    const float* userW = (const float*)d_in[23];
    const float* userb = (const float*)d_in[24];
    const float* itemW = (const float*)d_in[25];
    const float* itemb = (const float*)d_in[26];
    const float* ln_g  = (const float*)d_in[27];
    const float* ln_b  = (const float*)d_in[28];
    float* out = (float*)d_out;

    cudaFuncSetAttribute(k_fused1,
                         cudaFuncAttributeMaxDynamicSharedMemorySize, K1F_SMEM);

    dim3 gridF(NGB + 2 * NHB, 2);                // 2736 x type
    dim3 gridS(NBLK, 4);                         // 391 x slot
    dim3 gridE((EE + 255) / 256, 2, 2);          // 1954 x m x type
    dim3 gridG((NN * 8 + 255) / 256, 4);         // 3125 x slot

    k_fused1<<<gridF, 256, K1F_SMEM>>>(user_feat, item_feat, u_W, i_W,
                                       u_al, i_al, u_ar, i_ar, u_dst, i_dst);
    k_scanA<<<gridS, 256>>>();
    k_scanC<<<gridS, 256>>>();
    k_scatter<<<gridE, 256>>>(u_src, u_dst, i_src, i_dst);
    k_aggr<<<gridG, 256>>>();

    dim3 semGrid(256, 2);
    k_sem_mma<<<semGrid, 256>>>(u_saW1, u_sab1, u_saW2, u_b,
                                i_saW1, i_sab1, i_saW2, i_b);
    k_final<<<(3 * BB) / 4, 256>>>(user_idx, item_idx, neg_idx, u_b, i_b,
                                   userW, userb, itemW, itemb, ln_g, ln_b, out);
}

// round 11
// speedup vs baseline: 2.3869x; 1.0058x over previous
#include <cuda_runtime.h>
#include <cuda_bf16.h>
#include <cuda_fp16.h>
#include <math.h>

#define NN 100000
#define EE 500000
#define BB 8192
#define NBLK 391                     // ceil(NN/256)
#define NGB 782                      // gemm blocks per type (ceil(NN/128))
#define NHB 977                      // hist blocks per metapath (512 edges each)

// ---------------- scratch (device globals) ----------------------------------
__device__ __half g_feat_h[4][NN * 64];        // fp16 feat per slot
__device__ __half g_z_h[4][NN * 64];           // fp16 normalized GAT output
__device__ float g_el[4][NN];
__device__ float g_er[4][NN];
__device__ int   g_cnt[4][NN];                 // histogram (zero at call entry)
__device__ int   g_cur[4][NN];                 // scatter cursor
__device__ int   g_rowptr[4][NN + 1];
__device__ unsigned long long g_scan_st[4][NBLK];  // lookback state (zeroed by scatter)
__device__ unsigned long long g_csr[4][EE];    // (exp(score) << 32) | src
__device__ float g_w[4];

// ---------------- helpers ----------------------------------------------------
__device__ __forceinline__ float tanh_fast(float x) {
    float y; asm("tanh.approx.f32 %0, %1;" : "=f"(y) : "f"(x)); return y;
}
__device__ __forceinline__ float elu_fast(float x) {
    return x > 0.f ? x : (__expf(x) - 1.f);
}
__device__ __forceinline__ unsigned int bf2(float lo, float hi) {
    __nv_bfloat162 v = __floats2bfloat162_rn(lo, hi);
    return *reinterpret_cast<unsigned int*>(&v);
}
__device__ __forceinline__ unsigned int to_tf32(float f) {
    unsigned int u; asm("cvt.rna.tf32.f32 %0, %1;" : "=r"(u) : "f"(f)); return u;
}
__device__ __forceinline__ void mma_bf16(
    float& c0, float& c1, float& c2, float& c3,
    unsigned int a0, unsigned int a1, unsigned int a2, unsigned int a3,
    unsigned int b0, unsigned int b1)
{
    asm("mma.sync.aligned.m16n8k16.row.col.f32.bf16.bf16.f32 "
        "{%0,%1,%2,%3}, {%4,%5,%6,%7}, {%8,%9}, {%0,%1,%2,%3};"
        : "+f"(c0), "+f"(c1), "+f"(c2), "+f"(c3)
        : "r"(a0), "r"(a1), "r"(a2), "r"(a3), "r"(b0), "r"(b1));
}
__device__ __forceinline__ void mma_tf32(
    float* c, unsigned int a0, unsigned int a1, unsigned int a2, unsigned int a3,
    unsigned int b0, unsigned int b1)
{
    asm("mma.sync.aligned.m16n8k8.row.col.f32.tf32.tf32.f32 "
        "{%0,%1,%2,%3}, {%4,%5,%6,%7}, {%8,%9}, {%0,%1,%2,%3};"
        : "+f"(c[0]), "+f"(c[1]), "+f"(c[2]), "+f"(c[3])
        : "r"(a0), "r"(a1), "r"(a2), "r"(a3), "r"(b0), "r"(b1));
}

// ---------------- K1: fused feat GEMM (both metapaths) + degree histogram ---
#define HS_STRIDE 68
#define K1F_SMEM ((128 * HS_STRIDE + 2 * 4096 + 512) * 4)

__global__ void __launch_bounds__(256) k_fused1(
    const float* __restrict__ h_u, const float* __restrict__ h_i,
    const float* __restrict__ W_u, const float* __restrict__ W_i,
    const float* __restrict__ al_u, const float* __restrict__ al_i,
    const float* __restrict__ ar_u, const float* __restrict__ ar_i,
    const int* __restrict__ u_dst, const int* __restrict__ i_dst)
{
    int type = blockIdx.y;
    int tid  = threadIdx.x;

    // ---- histogram role ----
    if (blockIdx.x >= NGB) {
        int hb = blockIdx.x - NGB;           // 0 .. 2*NHB-1
        int m  = hb >= NHB;
        int b  = hb - m * NHB;
        int slot = 2 * type + m;
        const int* dst = (type ? i_dst : u_dst) + (size_t)m * EE;
        int e0 = b * 512 + tid;
        if (e0 < EE) atomicAdd(&g_cnt[slot][dst[e0]], 1);
        int e1 = e0 + 256;
        if (e1 < EE) atomicAdd(&g_cnt[slot][dst[e1]], 1);
        return;
    }

    // ---- gemm role ----
    extern __shared__ unsigned int smemu[];
    unsigned int* hsU = smemu;                  // 128 x 68 (tf32 bits)
    unsigned int* WsU = hsU + 128 * HS_STRIDE;  // 2 x 64 x 64 (tf32 bits)
    float* el_s = (float*)(WsU + 2 * 4096);     // 2 x 128
    float* er_s = el_s + 256;                   // 2 x 128

    const float* h  = type ? h_i : h_u;
    const float* W  = type ? W_i : W_u;
    const float* al = type ? al_i : al_u;
    const float* ar = type ? ar_i : ar_u;

    int row0 = blockIdx.x * 128;

    if (blockIdx.x == 0 && type == 0 && tid < 4) g_w[tid] = 0.0f;

    for (int i = tid; i < 8192; i += 256) WsU[i] = to_tf32(W[i]);

    {
        int r  = tid >> 1;
        int kq = (tid & 1) * 32;
        int grow = row0 + r;
        unsigned int* dst = &hsU[r * HS_STRIDE + kq];
        if (grow < NN) {
            const float4* hp = (const float4*)&h[(size_t)grow * 64 + kq];
#pragma unroll
            for (int j = 0; j < 8; j++) {
                float4 v = hp[j];
                dst[4 * j + 0] = to_tf32(v.x);
                dst[4 * j + 1] = to_tf32(v.y);
                dst[4 * j + 2] = to_tf32(v.z);
                dst[4 * j + 3] = to_tf32(v.w);
            }
        } else {
#pragma unroll
            for (int j = 0; j < 32; j++) dst[j] = 0u;
        }
    }
    el_s[tid] = 0.0f;
    er_s[tid] = 0.0f;
    __syncthreads();

    int lane = tid & 31, warp = tid >> 5;
    int g = lane >> 2, tig = lane & 3;
    int mq = warp & 1, nq = warp >> 1;

#pragma unroll
    for (int m2 = 0; m2 < 2; m2++) {
        int slot = 2 * type + m2;
        const unsigned int* Wm = WsU + m2 * 4096;

        unsigned int bfr[8][2][2];
#pragma unroll
        for (int kt = 0; kt < 8; kt++)
#pragma unroll
            for (int nt = 0; nt < 2; nt++) {
                int n = nq * 16 + nt * 8 + g;
                bfr[kt][nt][0] = Wm[(kt * 8 + tig) * 64 + n];
                bfr[kt][nt][1] = Wm[(kt * 8 + tig + 4) * 64 + n];
            }

        float alv[2][2], arv[2][2];
#pragma unroll
        for (int nt = 0; nt < 2; nt++) {
            int c = m2 * 64 + nq * 16 + nt * 8 + 2 * tig;
            alv[nt][0] = al[c]; alv[nt][1] = al[c + 1];
            arv[nt][0] = ar[c]; arv[nt][1] = ar[c + 1];
        }

        __half* fbase = g_feat_h[slot];

#pragma unroll
        for (int mt = 0; mt < 4; mt++) {
            int rb = mq * 64 + mt * 16;
            float acc[2][4];
#pragma unroll
            for (int nt = 0; nt < 2; nt++)
#pragma unroll
                for (int i = 0; i < 4; i++) acc[nt][i] = 0.0f;

#pragma unroll
            for (int kt = 0; kt < 8; kt++) {
                int cb = kt * 8;
                unsigned int a0 = hsU[(rb + g) * HS_STRIDE + cb + tig];
                unsigned int a1 = hsU[(rb + g + 8) * HS_STRIDE + cb + tig];
                unsigned int a2 = hsU[(rb + g) * HS_STRIDE + cb + tig + 4];
                unsigned int a3 = hsU[(rb + g + 8) * HS_STRIDE + cb + tig + 4];
                mma_tf32(acc[0], a0, a1, a2, a3, bfr[kt][0][0], bfr[kt][0][1]);
                mma_tf32(acc[1], a0, a1, a2, a3, bfr[kt][1][0], bfr[kt][1][1]);
            }

            int r0 = row0 + rb + g, r1 = r0 + 8;
            float pel0 = 0.f, pel1 = 0.f, per0 = 0.f, per1 = 0.f;
#pragma unroll
            for (int nt = 0; nt < 2; nt++) {
                int c0 = nq * 16 + nt * 8 + 2 * tig;
                if (r0 < NN)
                    *(__half2*)&fbase[(size_t)r0 * 64 + c0] =
                        __floats2half2_rn(acc[nt][0], acc[nt][1]);
                if (r1 < NN)
                    *(__half2*)&fbase[(size_t)r1 * 64 + c0] =
                        __floats2half2_rn(acc[nt][2], acc[nt][3]);
                pel0 += acc[nt][0] * alv[nt][0] + acc[nt][1] * alv[nt][1];
                pel1 += acc[nt][2] * alv[nt][0] + acc[nt][3] * alv[nt][1];
                per0 += acc[nt][0] * arv[nt][0] + acc[nt][1] * arv[nt][1];
                per1 += acc[nt][2] * arv[nt][0] + acc[nt][3] * arv[nt][1];
            }
            pel0 += __shfl_xor_sync(~0u, pel0, 1); pel0 += __shfl_xor_sync(~0u, pel0, 2);
            pel1 += __shfl_xor_sync(~0u, pel1, 1); pel1 += __shfl_xor_sync(~0u, pel1, 2);
            per0 += __shfl_xor_sync(~0u, per0, 1); per0 += __shfl_xor_sync(~0u, per0, 2);
            per1 += __shfl_xor_sync(~0u, per1, 1); per1 += __shfl_xor_sync(~0u, per1, 2);
            if (tig == 0) {
                atomicAdd(&el_s[m2 * 128 + rb + g], pel0);
                atomicAdd(&el_s[m2 * 128 + rb + g + 8], pel1);
                atomicAdd(&er_s[m2 * 128 + rb + g], per0);
                atomicAdd(&er_s[m2 * 128 + rb + g + 8], per1);
            }
        }
    }

    __syncthreads();
    {
        int m2 = tid >> 7;            // 0/1
        int r  = tid & 127;
        int row = row0 + r;
        if (row < NN) {
            int slot = 2 * type + m2;
            g_el[slot][row] = el_s[m2 * 128 + r];
            g_er[slot][row] = er_s[m2 * 128 + r];
        }
    }
}

// ---------------- K2: single-pass scan (decoupled lookback) -----------------
// grid (NBLK, 4 slots). Computes rowptr, zeroes cnt/cur.
__global__ void __launch_bounds__(256) k_scan()
{
    __shared__ int buf[256];
    __shared__ int base_sh;
    int slot = blockIdx.y;
    int bx = blockIdx.x;
    int tid = threadIdx.x;

    int i = bx * 256 + tid;
    int v = (i < NN) ? g_cnt[slot][i] : 0;
    buf[tid] = v;
    __syncthreads();
    for (int off = 1; off < 256; off <<= 1) {
        int x = (tid >= off) ? buf[tid - off] : 0;
        __syncthreads();
        buf[tid] += x;
        __syncthreads();
    }
    int agg = buf[255];

    if (tid == 0) {
        if (bx == 0) {
            atomicExch(&g_scan_st[slot][0],
                       (2ull << 62) | (unsigned long long)(unsigned int)agg);
            base_sh = 0;
        } else {
            atomicExch(&g_scan_st[slot][bx],
                       (1ull << 62) | (unsigned long long)(unsigned int)agg);
            long long prefix = 0;
            int j = bx - 1;
            while (j >= 0) {
                unsigned long long st = atomicAdd(&g_scan_st[slot][j], 0ull);
                unsigned long long flag = st >> 62;
                if (flag == 0) continue;                     // not ready, poll
                prefix += (long long)(unsigned int)(st & 0xFFFFFFFFull);
                if (flag == 2) break;
                j--;
            }
            atomicExch(&g_scan_st[slot][bx],
                       (2ull << 62) | (unsigned long long)(unsigned int)(prefix + agg));
            base_sh = (int)prefix;
        }
    }
    __syncthreads();

    if (i < NN) {
        g_rowptr[slot][i] = base_sh + buf[tid] - v;
        g_cnt[slot][i] = 0;      // restore invariant for next call
        g_cur[slot][i] = 0;      // scatter cursor
    }
    if (bx == NBLK - 1 && tid == 0) g_rowptr[slot][NN] = EE;
}

// ---------------- K3: scatter (src, exp(score)) into CSR --------------------
// Also re-zeroes the lookback state for the next graph replay.
__global__ void k_scatter(
    const int* __restrict__ u_src, const int* __restrict__ u_dst,
    const int* __restrict__ i_src, const int* __restrict__ i_dst)
{
    int slot = 2 * blockIdx.z + blockIdx.y;
    if (blockIdx.x < NBLK && threadIdx.x == 0)
        g_scan_st[slot][blockIdx.x] = 0ull;
    const int* src = (blockIdx.z ? i_src : u_src) + (size_t)blockIdx.y * EE;
    const int* dst = (blockIdx.z ? i_dst : u_dst) + (size_t)blockIdx.y * EE;
    int i = blockIdx.x * 256 + threadIdx.x;
    if (i >= EE) return;
    int s = src[i], d = dst[i];
    float e = g_el[slot][s] + g_er[slot][d];
    e = (e >= 0.0f) ? e : 0.2f * e;          // leaky_relu 0.2
    float ex = __expf(e);
    int pos = g_rowptr[slot][d] + atomicAdd(&g_cur[slot][d], 1);
    g_csr[slot][pos] =
        ((unsigned long long)__float_as_uint(ex) << 32) | (unsigned int)s;
}

// ---------------- K4: node-parallel aggregate, write normalized z (fp16) ----
__global__ void __launch_bounds__(256) k_aggr()
{
    int slot = blockIdx.y;
    int t = blockIdx.x * 256 + threadIdx.x;
    int node = t >> 3;
    int lane = t & 7;
    if (node >= NN) return;

    int start = g_rowptr[slot][node];
    int end   = g_rowptr[slot][node + 1];

    float acc[8] = {0.f, 0.f, 0.f, 0.f, 0.f, 0.f, 0.f, 0.f};
    float den = 0.0f;
    const __half* fb = g_feat_h[slot];
    const unsigned long long* csr = g_csr[slot];

    for (int p = start; p < end; p++) {
        unsigned long long pk = csr[p];
        int s = (int)(unsigned int)pk;
        float ex = __uint_as_float((unsigned int)(pk >> 32));
        den += ex;
        uint4 hv = *(const uint4*)&fb[(size_t)s * 64 + lane * 8];
        float2 f0 = __half22float2(*(__half2*)&hv.x);
        float2 f1 = __half22float2(*(__half2*)&hv.y);
        float2 f2 = __half22float2(*(__half2*)&hv.z);
        float2 f3 = __half22float2(*(__half2*)&hv.w);
        acc[0] += ex * f0.x; acc[1] += ex * f0.y;
        acc[2] += ex * f1.x; acc[3] += ex * f1.y;
        acc[4] += ex * f2.x; acc[5] += ex * f2.y;
        acc[6] += ex * f3.x; acc[7] += ex * f3.y;
    }

    float inv = __fdividef(1.0f, den + 1e-9f);
    __half2 h0 = __floats2half2_rn(acc[0] * inv, acc[1] * inv);
    __half2 h1 = __floats2half2_rn(acc[2] * inv, acc[3] * inv);
    __half2 h2 = __floats2half2_rn(acc[4] * inv, acc[5] * inv);
    __half2 h3 = __floats2half2_rn(acc[6] * inv, acc[7] * inv);
    uint4 pk = make_uint4(*(unsigned int*)&h0, *(unsigned int*)&h1,
                          *(unsigned int*)&h2, *(unsigned int*)&h3);
    *(uint4*)&g_z_h[slot][(size_t)node * 64 + lane * 8] = pk;
}

// ---------------- K5: semantic logits via mma.sync bf16 ---------------------
#define SEM_TILE_STRIDE 72

__global__ void __launch_bounds__(256) k_sem_mma(
    const float* __restrict__ uW1, const float* __restrict__ ub1,
    const float* __restrict__ uW2, const float* __restrict__ ugb,
    const float* __restrict__ iW1, const float* __restrict__ ib1,
    const float* __restrict__ iW2, const float* __restrict__ igb)
{
    __shared__ __align__(16) __nv_bfloat16 tile[2][32][SEM_TILE_STRIDE];
    __shared__ float gbs[128];
    __shared__ float wsum[8];

    int t = blockIdx.y;
    const float* W1 = t ? iW1 : uW1;
    const float* b1 = t ? ib1 : ub1;
    const float* W2 = t ? iW2 : uW2;
    const float* gb = t ? igb : ugb;

    int tid  = threadIdx.x;
    int warp = tid >> 5;
    int lane = tid & 31;
    int slot = warp >> 2;
    int nq   = warp & 3;

    if (tid < 128) gbs[tid] = gb[tid];

    unsigned int bfr[4][4][2];
    {
        int n = nq * 32 + (lane >> 2);
        int k0 = (lane & 3) * 2;
#pragma unroll
        for (int kt = 0; kt < 4; kt++) {
            int k = kt * 16 + k0;
#pragma unroll
            for (int nt = 0; nt < 4; nt++) {
                int nn = n + nt * 8;
                bfr[kt][nt][0] = bf2(W1[(size_t)k * 128 + nn],
                                     W1[(size_t)(k + 1) * 128 + nn]);
                bfr[kt][nt][1] = bf2(W1[(size_t)(k + 8) * 128 + nn],
                                     W1[(size_t)(k + 9) * 128 + nn]);
            }
        }
    }
    float w2v[4][2], bsv[4][2];
#pragma unroll
    for (int nt = 0; nt < 4; nt++) {
        int c = nq * 32 + nt * 8 + (lane & 3) * 2;
        w2v[nt][0] = W2[c];     w2v[nt][1] = W2[c + 1];
        bsv[nt][0] = b1[c];     bsv[nt][1] = b1[c + 1];
    }

    int s_slot = tid >> 7;
    int tid2   = tid & 127;
    int s_row  = tid2 >> 2;
    int s_colq = (tid2 & 3) * 16;

    int ld_row = lane & 15;
    int ld_off = (lane >> 4) * 16;

    float s = 0.0f;

    const int NITER = NN / 32;
    __syncthreads();
    for (int it = blockIdx.x; it < NITER; it += gridDim.x) {
        int row = it * 32 + s_row;
        const __half* zrow = g_z_h[2 * t + s_slot] + (size_t)row * 64 + s_colq;
        uint4 va = *(const uint4*)zrow;
        uint4 vb = *(const uint4*)(zrow + 8);
        unsigned int wv[8] = {va.x, va.y, va.z, va.w, vb.x, vb.y, vb.z, vb.w};
        unsigned int* drow = (unsigned int*)&tile[s_slot][s_row][0];
#pragma unroll
        for (int j = 0; j < 8; j++) {
            float2 f = __half22float2(*(__half2*)&wv[j]);
            int c = s_colq + 2 * j;
            drow[(s_colq >> 1) + j] =
                bf2(elu_fast(f.x + gbs[s_slot * 64 + c]),
                    elu_fast(f.y + gbs[s_slot * 64 + c + 1]));
        }
        __syncthreads();

#pragma unroll
        for (int mt = 0; mt < 2; mt++) {
            unsigned int a[4][4];
            const __nv_bfloat16* ap = &tile[slot][mt * 16 + ld_row][0];
            unsigned int abase = (unsigned int)__cvta_generic_to_shared(ap) + ld_off;
#pragma unroll
            for (int kt = 0; kt < 4; kt++) {
                asm volatile(
                    "ldmatrix.sync.aligned.m8n8.x4.shared.b16 {%0,%1,%2,%3}, [%4];"
                    : "=r"(a[kt][0]), "=r"(a[kt][1]), "=r"(a[kt][2]), "=r"(a[kt][3])
                    : "r"(abase + kt * 32));
            }
#pragma unroll
            for (int nt = 0; nt < 4; nt++) {
                float c0 = 0.f, c1 = 0.f, c2 = 0.f, c3 = 0.f;
#pragma unroll
                for (int kt = 0; kt < 4; kt++)
                    mma_bf16(c0, c1, c2, c3,
                             a[kt][0], a[kt][1], a[kt][2], a[kt][3],
                             bfr[kt][nt][0], bfr[kt][nt][1]);
                s += tanh_fast(c0 + bsv[nt][0]) * w2v[nt][0];
                s += tanh_fast(c1 + bsv[nt][1]) * w2v[nt][1];
                s += tanh_fast(c2 + bsv[nt][0]) * w2v[nt][0];
                s += tanh_fast(c3 + bsv[nt][1]) * w2v[nt][1];
            }
        }
        __syncthreads();
    }

#pragma unroll
    for (int off = 16; off > 0; off >>= 1)
        s += __shfl_xor_sync(0xffffffffu, s, off);
    if (lane == 0) wsum[warp] = s;
    __syncthreads();
    if (tid < 2) {
        float tot = wsum[tid * 4] + wsum[tid * 4 + 1]
                  + wsum[tid * 4 + 2] + wsum[tid * 4 + 3];
        atomicAdd(&g_w[2 * t + tid], tot);
    }
}

// ---------------- K6: gather + bias/ELU + beta + GEMM + ReLU + LN ------------
__global__ void __launch_bounds__(256) k_final(
    const int* __restrict__ user_idx, const int* __restrict__ item_idx,
    const int* __restrict__ neg_idx,
    const float* __restrict__ u_gb, const float* __restrict__ i_gb,
    const float* __restrict__ userW, const float* __restrict__ userb,
    const float* __restrict__ itemW, const float* __restrict__ itemb,
    const float* __restrict__ ln_g, const float* __restrict__ ln_b,
    float* __restrict__ out)
{
    __shared__ float Ws[4096];
    __shared__ float bs[64], gs[64], lbs[64];
    __shared__ float gb0[64], gb1[64];
    __shared__ float embs[4][64];
    __shared__ float red[4][2];

    int tid = threadIdx.x;
    int tx = tid & 63, ty = tid >> 6;
    int r0 = blockIdx.x * 4;
    bool isUser = (r0 < BB);
    const float* W    = isUser ? userW : itemW;
    const float* bias = isUser ? userb : itemb;
    const float* gbm  = isUser ? u_gb : i_gb;

    for (int i = tid; i < 4096; i += 256) Ws[i] = W[i];
    if (tid < 64) {
        bs[tid] = bias[tid]; gs[tid] = ln_g[tid]; lbs[tid] = ln_b[tid];
        gb0[tid] = gbm[tid]; gb1[tid] = gbm[64 + tid];
    }

    int r = r0 + ty;
    int type, idx;
    if (r < BB)            { type = 0; idx = user_idx[r]; }
    else if (r < 2 * BB)   { type = 1; idx = item_idx[r - BB]; }
    else                   { type = 1; idx = neg_idx[r - 2 * BB]; }

    float w0 = g_w[2 * type] * (1.0f / NN);
    float w1 = g_w[2 * type + 1] * (1.0f / NN);
    float mx = fmaxf(w0, w1);
    float e0 = __expf(w0 - mx), e1 = __expf(w1 - mx);
    float binv = 1.0f / (e0 + e1);
    float b0 = e0 * binv, b1 = e1 * binv;

    __syncthreads();
    float zr0 = __half2float(g_z_h[2 * type][(size_t)idx * 64 + tx]) + gb0[tx];
    float zr1 = __half2float(g_z_h[2 * type + 1][(size_t)idx * 64 + tx]) + gb1[tx];
    float emb = b0 * elu_fast(zr0) + b1 * elu_fast(zr1);
    embs[ty][tx] = emb;
    __syncthreads();

    float y = bs[tx];
#pragma unroll 16
    for (int k = 0; k < 64; k++) y += embs[ty][k] * Ws[k * 64 + tx];
    y = fmaxf(y, 0.0f);

    float s = y;
#pragma unroll
    for (int off = 16; off > 0; off >>= 1) s += __shfl_xor_sync(0xffffffffu, s, off);
    int half = tx >> 5;
    if ((tx & 31) == 0) red[ty][half] = s;
    __syncthreads();
    float mu = (red[ty][0] + red[ty][1]) * (1.0f / 64.0f);
    float dv = y - mu;
    float s2 = dv * dv;
#pragma unroll
    for (int off = 16; off > 0; off >>= 1) s2 += __shfl_xor_sync(0xffffffffu, s2, off);
    __syncthreads();
    if ((tx & 31) == 0) red[ty][half] = s2;
    __syncthreads();
    float var = (red[ty][0] + red[ty][1]) * (1.0f / 64.0f);
    float o = gs[tx] * dv * rsqrtf(var + 1e-5f) + lbs[tx];
    out[(size_t)r * 64 + tx] = o;
}

// ---------------- host ------------------------------------------------------
extern "C" void kernel_launch(void* const* d_in, const int* in_sizes, int n_in,
                              void* d_out, int out_size)
{
    const int*   user_idx  = (const int*)d_in[0];
    const int*   item_idx  = (const int*)d_in[1];
    const int*   neg_idx   = (const int*)d_in[2];
    const float* user_feat = (const float*)d_in[3];
    const float* item_feat = (const float*)d_in[4];
    const int*   u_src = (const int*)d_in[5];
    const int*   u_dst = (const int*)d_in[6];
    const int*   i_src = (const int*)d_in[7];
    const int*   i_dst = (const int*)d_in[8];
    const float* u_W  = (const float*)d_in[9];
    const float* u_al = (const float*)d_in[10];
    const float* u_ar = (const float*)d_in[11];
    const float* u_b  = (const float*)d_in[12];
    const float* i_W  = (const float*)d_in[13];
    const float* i_al = (const float*)d_in[14];
    const float* i_ar = (const float*)d_in[15];
    const float* i_b  = (const float*)d_in[16];
    const float* u_saW1 = (const float*)d_in[17];
    const float* u_sab1 = (const float*)d_in[18];
    const float* u_saW2 = (const float*)d_in[19];
    const float* i_saW1 = (const float*)d_in[20];
    const float* i_sab1 = (const float*)d_in[21];
    const float* i_saW2 = (const float*)d_in[22];
    const float* userW = (const float*)d_in[23];
    const float* userb = (const float*)d_in[24];
    const float* itemW = (const float*)d_in[25];
    const float* itemb = (const float*)d_in[26];
    const float* ln_g  = (const float*)d_in[27];
    const float* ln_b  = (const float*)d_in[28];
    float* out = (float*)d_out;

    cudaFuncSetAttribute(k_fused1,
                         cudaFuncAttributeMaxDynamicSharedMemorySize, K1F_SMEM);

    dim3 gridF(NGB + 2 * NHB, 2);                // 2736 x type
    dim3 gridS(NBLK, 4);                         // 391 x slot
    dim3 gridE((EE + 255) / 256, 2, 2);          // 1954 x m x type
    dim3 gridG((NN * 8 + 255) / 256, 4);         // 3125 x slot

    k_fused1<<<gridF, 256, K1F_SMEM>>>(user_feat, item_feat, u_W, i_W,
                                       u_al, i_al, u_ar, i_ar, u_dst, i_dst);
    k_scan<<<gridS, 256>>>();
    k_scatter<<<gridE, 256>>>(u_src, u_dst, i_src, i_dst);
    k_aggr<<<gridG, 256>>>();

    dim3 semGrid(256, 2);
    k_sem_mma<<<semGrid, 256>>>(u_saW1, u_sab1, u_saW2, u_b,
                                i_saW1, i_sab1, i_saW2, i_b);
    k_final<<<(3 * BB) / 4, 256>>>(user_idx, item_idx, neg_idx, u_b, i_b,
                                   userW, userb, itemW, itemb, ln_g, ln_b, out);
}

// round 12
// speedup vs baseline: 2.4861x; 1.0416x over previous
#include <cuda_runtime.h>
#include <cuda_bf16.h>
#include <cuda_fp16.h>
#include <math.h>

#define NN 100000
#define EE 500000
#define BB 8192
#define NBLK 391                     // ceil(NN/256)
#define NGB 782                      // gemm blocks per type (ceil(NN/128))
#define NHB 977                      // hist blocks per metapath (512 edges each)

// ---------------- scratch (device globals) ----------------------------------
__device__ __half g_feat_h[4][NN * 64];        // fp16 feat per slot
__device__ __half g_z_h[4][NN * 64];           // fp16 normalized GAT output
__device__ float g_el[4][NN];
__device__ float g_er[4][NN];
__device__ int   g_cnt[4][NN];                 // histogram (zero at call entry)
__device__ int   g_cur[4][NN];                 // scatter cursor
__device__ int   g_rowptr[4][NN + 1];
__device__ unsigned long long g_scan_st[4][NBLK];  // lookback state (zeroed by scatter)
__device__ __align__(16) unsigned long long g_csr[4][EE];  // (exp << 32) | src
__device__ float g_w[4];

// ---------------- helpers ----------------------------------------------------
__device__ __forceinline__ float tanh_fast(float x) {
    float y; asm("tanh.approx.f32 %0, %1;" : "=f"(y) : "f"(x)); return y;
}
__device__ __forceinline__ float elu_fast(float x) {
    return x > 0.f ? x : (__expf(x) - 1.f);
}
__device__ __forceinline__ unsigned int bf2(float lo, float hi) {
    __nv_bfloat162 v = __floats2bfloat162_rn(lo, hi);
    return *reinterpret_cast<unsigned int*>(&v);
}
__device__ __forceinline__ unsigned int to_tf32(float f) {
    unsigned int u; asm("cvt.rna.tf32.f32 %0, %1;" : "=r"(u) : "f"(f)); return u;
}
__device__ __forceinline__ void mma_bf16(
    float& c0, float& c1, float& c2, float& c3,
    unsigned int a0, unsigned int a1, unsigned int a2, unsigned int a3,
    unsigned int b0, unsigned int b1)
{
    asm("mma.sync.aligned.m16n8k16.row.col.f32.bf16.bf16.f32 "
        "{%0,%1,%2,%3}, {%4,%5,%6,%7}, {%8,%9}, {%0,%1,%2,%3};"
        : "+f"(c0), "+f"(c1), "+f"(c2), "+f"(c3)
        : "r"(a0), "r"(a1), "r"(a2), "r"(a3), "r"(b0), "r"(b1));
}
__device__ __forceinline__ void mma_tf32(
    float* c, unsigned int a0, unsigned int a1, unsigned int a2, unsigned int a3,
    unsigned int b0, unsigned int b1)
{
    asm("mma.sync.aligned.m16n8k8.row.col.f32.tf32.tf32.f32 "
        "{%0,%1,%2,%3}, {%4,%5,%6,%7}, {%8,%9}, {%0,%1,%2,%3};"
        : "+f"(c[0]), "+f"(c[1]), "+f"(c[2]), "+f"(c[3])
        : "r"(a0), "r"(a1), "r"(a2), "r"(a3), "r"(b0), "r"(b1));
}

// ---------------- K1: fused feat GEMM (both metapaths) + degree histogram ---
#define HS_STRIDE 68
#define K1F_SMEM ((128 * HS_STRIDE + 2 * 4096 + 512) * 4)

__global__ void __launch_bounds__(256) k_fused1(
    const float* __restrict__ h_u, const float* __restrict__ h_i,
    const float* __restrict__ W_u, const float* __restrict__ W_i,
    const float* __restrict__ al_u, const float* __restrict__ al_i,
    const float* __restrict__ ar_u, const float* __restrict__ ar_i,
    const int* __restrict__ u_dst, const int* __restrict__ i_dst)
{
    int type = blockIdx.y;
    int tid  = threadIdx.x;

    // ---- histogram role ----
    if (blockIdx.x >= NGB) {
        int hb = blockIdx.x - NGB;           // 0 .. 2*NHB-1
        int m  = hb >= NHB;
        int b  = hb - m * NHB;
        int slot = 2 * type + m;
        const int* dst = (type ? i_dst : u_dst) + (size_t)m * EE;
        int e0 = b * 512 + tid;
        if (e0 < EE) atomicAdd(&g_cnt[slot][dst[e0]], 1);
        int e1 = e0 + 256;
        if (e1 < EE) atomicAdd(&g_cnt[slot][dst[e1]], 1);
        return;
    }

    // ---- gemm role ----
    extern __shared__ unsigned int smemu[];
    unsigned int* hsU = smemu;                  // 128 x 68 (tf32 bits)
    unsigned int* WsU = hsU + 128 * HS_STRIDE;  // 2 x 64 x 64 (tf32 bits)
    float* el_s = (float*)(WsU + 2 * 4096);     // 2 x 128
    float* er_s = el_s + 256;                   // 2 x 128

    const float* h  = type ? h_i : h_u;
    const float* W  = type ? W_i : W_u;
    const float* al = type ? al_i : al_u;
    const float* ar = type ? ar_i : ar_u;

    int row0 = blockIdx.x * 128;

    if (blockIdx.x == 0 && type == 0 && tid < 4) g_w[tid] = 0.0f;

    for (int i = tid; i < 8192; i += 256) WsU[i] = to_tf32(W[i]);

    {
        int r  = tid >> 1;
        int kq = (tid & 1) * 32;
        int grow = row0 + r;
        unsigned int* dst = &hsU[r * HS_STRIDE + kq];
        if (grow < NN) {
            const float4* hp = (const float4*)&h[(size_t)grow * 64 + kq];
#pragma unroll
            for (int j = 0; j < 8; j++) {
                float4 v = hp[j];
                dst[4 * j + 0] = to_tf32(v.x);
                dst[4 * j + 1] = to_tf32(v.y);
                dst[4 * j + 2] = to_tf32(v.z);
                dst[4 * j + 3] = to_tf32(v.w);
            }
        } else {
#pragma unroll
            for (int j = 0; j < 32; j++) dst[j] = 0u;
        }
    }
    el_s[tid] = 0.0f;
    er_s[tid] = 0.0f;
    __syncthreads();

    int lane = tid & 31, warp = tid >> 5;
    int g = lane >> 2, tig = lane & 3;
    int mq = warp & 1, nq = warp >> 1;

#pragma unroll
    for (int m2 = 0; m2 < 2; m2++) {
        int slot = 2 * type + m2;
        const unsigned int* Wm = WsU + m2 * 4096;

        unsigned int bfr[8][2][2];
#pragma unroll
        for (int kt = 0; kt < 8; kt++)
#pragma unroll
            for (int nt = 0; nt < 2; nt++) {
                int n = nq * 16 + nt * 8 + g;
                bfr[kt][nt][0] = Wm[(kt * 8 + tig) * 64 + n];
                bfr[kt][nt][1] = Wm[(kt * 8 + tig + 4) * 64 + n];
            }

        float alv[2][2], arv[2][2];
#pragma unroll
        for (int nt = 0; nt < 2; nt++) {
            int c = m2 * 64 + nq * 16 + nt * 8 + 2 * tig;
            alv[nt][0] = al[c]; alv[nt][1] = al[c + 1];
            arv[nt][0] = ar[c]; arv[nt][1] = ar[c + 1];
        }

        __half* fbase = g_feat_h[slot];

#pragma unroll
        for (int mt = 0; mt < 4; mt++) {
            int rb = mq * 64 + mt * 16;
            float acc[2][4];
#pragma unroll
            for (int nt = 0; nt < 2; nt++)
#pragma unroll
                for (int i = 0; i < 4; i++) acc[nt][i] = 0.0f;

#pragma unroll
            for (int kt = 0; kt < 8; kt++) {
                int cb = kt * 8;
                unsigned int a0 = hsU[(rb + g) * HS_STRIDE + cb + tig];
                unsigned int a1 = hsU[(rb + g + 8) * HS_STRIDE + cb + tig];
                unsigned int a2 = hsU[(rb + g) * HS_STRIDE + cb + tig + 4];
                unsigned int a3 = hsU[(rb + g + 8) * HS_STRIDE + cb + tig + 4];
                mma_tf32(acc[0], a0, a1, a2, a3, bfr[kt][0][0], bfr[kt][0][1]);
                mma_tf32(acc[1], a0, a1, a2, a3, bfr[kt][1][0], bfr[kt][1][1]);
            }

            int r0 = row0 + rb + g, r1 = r0 + 8;
            float pel0 = 0.f, pel1 = 0.f, per0 = 0.f, per1 = 0.f;
#pragma unroll
            for (int nt = 0; nt < 2; nt++) {
                int c0 = nq * 16 + nt * 8 + 2 * tig;
                if (r0 < NN)
                    *(__half2*)&fbase[(size_t)r0 * 64 + c0] =
                        __floats2half2_rn(acc[nt][0], acc[nt][1]);
                if (r1 < NN)
                    *(__half2*)&fbase[(size_t)r1 * 64 + c0] =
                        __floats2half2_rn(acc[nt][2], acc[nt][3]);
                pel0 += acc[nt][0] * alv[nt][0] + acc[nt][1] * alv[nt][1];
                pel1 += acc[nt][2] * alv[nt][0] + acc[nt][3] * alv[nt][1];
                per0 += acc[nt][0] * arv[nt][0] + acc[nt][1] * arv[nt][1];
                per1 += acc[nt][2] * arv[nt][0] + acc[nt][3] * arv[nt][1];
            }
            pel0 += __shfl_xor_sync(~0u, pel0, 1); pel0 += __shfl_xor_sync(~0u, pel0, 2);
            pel1 += __shfl_xor_sync(~0u, pel1, 1); pel1 += __shfl_xor_sync(~0u, pel1, 2);
            per0 += __shfl_xor_sync(~0u, per0, 1); per0 += __shfl_xor_sync(~0u, per0, 2);
            per1 += __shfl_xor_sync(~0u, per1, 1); per1 += __shfl_xor_sync(~0u, per1, 2);
            if (tig == 0) {
                atomicAdd(&el_s[m2 * 128 + rb + g], pel0);
                atomicAdd(&el_s[m2 * 128 + rb + g + 8], pel1);
                atomicAdd(&er_s[m2 * 128 + rb + g], per0);
                atomicAdd(&er_s[m2 * 128 + rb + g + 8], per1);
            }
        }
    }

    __syncthreads();
    {
        int m2 = tid >> 7;            // 0/1
        int r  = tid & 127;
        int row = row0 + r;
        if (row < NN) {
            int slot = 2 * type + m2;
            g_el[slot][row] = el_s[m2 * 128 + r];
            g_er[slot][row] = er_s[m2 * 128 + r];
        }
    }
}

// ---------------- K2: single-pass scan (decoupled lookback) -----------------
__global__ void __launch_bounds__(256) k_scan()
{
    __shared__ int buf[256];
    __shared__ int base_sh;
    int slot = blockIdx.y;
    int bx = blockIdx.x;
    int tid = threadIdx.x;

    int i = bx * 256 + tid;
    int v = (i < NN) ? g_cnt[slot][i] : 0;
    buf[tid] = v;
    __syncthreads();
    for (int off = 1; off < 256; off <<= 1) {
        int x = (tid >= off) ? buf[tid - off] : 0;
        __syncthreads();
        buf[tid] += x;
        __syncthreads();
    }
    int agg = buf[255];

    if (tid == 0) {
        if (bx == 0) {
            atomicExch(&g_scan_st[slot][0],
                       (2ull << 62) | (unsigned long long)(unsigned int)agg);
            base_sh = 0;
        } else {
            atomicExch(&g_scan_st[slot][bx],
                       (1ull << 62) | (unsigned long long)(unsigned int)agg);
            long long prefix = 0;
            int j = bx - 1;
            while (j >= 0) {
                unsigned long long st = atomicAdd(&g_scan_st[slot][j], 0ull);
                unsigned long long flag = st >> 62;
                if (flag == 0) continue;                     // not ready, poll
                prefix += (long long)(unsigned int)(st & 0xFFFFFFFFull);
                if (flag == 2) break;
                j--;
            }
            atomicExch(&g_scan_st[slot][bx],
                       (2ull << 62) | (unsigned long long)(unsigned int)(prefix + agg));
            base_sh = (int)prefix;
        }
    }
    __syncthreads();

    if (i < NN) {
        g_rowptr[slot][i] = base_sh + buf[tid] - v;
        g_cnt[slot][i] = 0;      // restore invariant for next call
        g_cur[slot][i] = 0;      // scatter cursor
    }
    if (bx == NBLK - 1 && tid == 0) g_rowptr[slot][NN] = EE;
}

// ---------------- K3: scatter (src, exp(score)) into CSR --------------------
__global__ void k_scatter(
    const int* __restrict__ u_src, const int* __restrict__ u_dst,
    const int* __restrict__ i_src, const int* __restrict__ i_dst)
{
    int slot = 2 * blockIdx.z + blockIdx.y;
    if (blockIdx.x < NBLK && threadIdx.x == 0)
        g_scan_st[slot][blockIdx.x] = 0ull;
    const int* src = (blockIdx.z ? i_src : u_src) + (size_t)blockIdx.y * EE;
    const int* dst = (blockIdx.z ? i_dst : u_dst) + (size_t)blockIdx.y * EE;
    int i = blockIdx.x * 256 + threadIdx.x;
    if (i >= EE) return;
    int s = src[i], d = dst[i];
    float e = g_el[slot][s] + g_er[slot][d];
    e = (e >= 0.0f) ? e : 0.2f * e;          // leaky_relu 0.2
    float ex = __expf(e);
    int pos = g_rowptr[slot][d] + atomicAdd(&g_cur[slot][d], 1);
    g_csr[slot][pos] =
        ((unsigned long long)__float_as_uint(ex) << 32) | (unsigned int)s;
}

// ---------------- K4: node-parallel aggregate (pipelined pairs) -------------
__global__ void __launch_bounds__(256) k_aggr()
{
    int slot = blockIdx.y;
    int t = blockIdx.x * 256 + threadIdx.x;
    int node = t >> 3;
    int lane = t & 7;
    if (node >= NN) return;

    int start = g_rowptr[slot][node];
    int end   = g_rowptr[slot][node + 1];

    float acc[8] = {0.f, 0.f, 0.f, 0.f, 0.f, 0.f, 0.f, 0.f};
    float den = 0.0f;
    const __half* fb = g_feat_h[slot];
    const unsigned long long* csr = g_csr[slot];

    int p = start;
    // head: align p to even for 16B csr pair loads
    if (p < end && (p & 1)) {
        unsigned long long pk = csr[p];
        int s = (int)(unsigned int)pk;
        float ex = __uint_as_float((unsigned int)(pk >> 32));
        den += ex;
        uint4 hv = *(const uint4*)&fb[(size_t)s * 64 + lane * 8];
        float2 f0 = __half22float2(*(__half2*)&hv.x);
        float2 f1 = __half22float2(*(__half2*)&hv.y);
        float2 f2 = __half22float2(*(__half2*)&hv.z);
        float2 f3 = __half22float2(*(__half2*)&hv.w);
        acc[0] += ex * f0.x; acc[1] += ex * f0.y;
        acc[2] += ex * f1.x; acc[3] += ex * f1.y;
        acc[4] += ex * f2.x; acc[5] += ex * f2.y;
        acc[6] += ex * f3.x; acc[7] += ex * f3.y;
        p++;
    }
    // main: process edge pairs; both gathers in flight before FMAs (MLP 3)
    for (; p + 2 <= end; p += 2) {
        ulonglong2 pk2 = *(const ulonglong2*)&csr[p];
        int s0 = (int)(unsigned int)pk2.x;
        int s1 = (int)(unsigned int)pk2.y;
        float ex0 = __uint_as_float((unsigned int)(pk2.x >> 32));
        float ex1 = __uint_as_float((unsigned int)(pk2.y >> 32));
        uint4 hva = *(const uint4*)&fb[(size_t)s0 * 64 + lane * 8];
        uint4 hvb = *(const uint4*)&fb[(size_t)s1 * 64 + lane * 8];
        den += ex0 + ex1;
        float2 a0 = __half22float2(*(__half2*)&hva.x);
        float2 a1 = __half22float2(*(__half2*)&hva.y);
        float2 a2 = __half22float2(*(__half2*)&hva.z);
        float2 a3 = __half22float2(*(__half2*)&hva.w);
        float2 b0 = __half22float2(*(__half2*)&hvb.x);
        float2 b1 = __half22float2(*(__half2*)&hvb.y);
        float2 b2 = __half22float2(*(__half2*)&hvb.z);
        float2 b3 = __half22float2(*(__half2*)&hvb.w);
        acc[0] += ex0 * a0.x + ex1 * b0.x;
        acc[1] += ex0 * a0.y + ex1 * b0.y;
        acc[2] += ex0 * a1.x + ex1 * b1.x;
        acc[3] += ex0 * a1.y + ex1 * b1.y;
        acc[4] += ex0 * a2.x + ex1 * b2.x;
        acc[5] += ex0 * a2.y + ex1 * b2.y;
        acc[6] += ex0 * a3.x + ex1 * b3.x;
        acc[7] += ex0 * a3.y + ex1 * b3.y;
    }
    // tail
    if (p < end) {
        unsigned long long pk = csr[p];
        int s = (int)(unsigned int)pk;
        float ex = __uint_as_float((unsigned int)(pk >> 32));
        den += ex;
        uint4 hv = *(const uint4*)&fb[(size_t)s * 64 + lane * 8];
        float2 f0 = __half22float2(*(__half2*)&hv.x);
        float2 f1 = __half22float2(*(__half2*)&hv.y);
        float2 f2 = __half22float2(*(__half2*)&hv.z);
        float2 f3 = __half22float2(*(__half2*)&hv.w);
        acc[0] += ex * f0.x; acc[1] += ex * f0.y;
        acc[2] += ex * f1.x; acc[3] += ex * f1.y;
        acc[4] += ex * f2.x; acc[5] += ex * f2.y;
        acc[6] += ex * f3.x; acc[7] += ex * f3.y;
    }

    float inv = __fdividef(1.0f, den + 1e-9f);
    __half2 h0 = __floats2half2_rn(acc[0] * inv, acc[1] * inv);
    __half2 h1 = __floats2half2_rn(acc[2] * inv, acc[3] * inv);
    __half2 h2 = __floats2half2_rn(acc[4] * inv, acc[5] * inv);
    __half2 h3 = __floats2half2_rn(acc[6] * inv, acc[7] * inv);
    uint4 pk = make_uint4(*(unsigned int*)&h0, *(unsigned int*)&h1,
                          *(unsigned int*)&h2, *(unsigned int*)&h3);
    *(uint4*)&g_z_h[slot][(size_t)node * 64 + lane * 8] = pk;
}

// ---------------- K5: semantic logits via mma.sync bf16 ---------------------
#define SEM_TILE_STRIDE 72

__global__ void __launch_bounds__(256) k_sem_mma(
    const float* __restrict__ uW1, const float* __restrict__ ub1,
    const float* __restrict__ uW2, const float* __restrict__ ugb,
    const float* __restrict__ iW1, const float* __restrict__ ib1,
    const float* __restrict__ iW2, const float* __restrict__ igb)
{
    __shared__ __align__(16) __nv_bfloat16 tile[2][32][SEM_TILE_STRIDE];
    __shared__ float gbs[128];
    __shared__ float wsum[8];

    int t = blockIdx.y;
    const float* W1 = t ? iW1 : uW1;
    const float* b1 = t ? ib1 : ub1;
    const float* W2 = t ? iW2 : uW2;
    const float* gb = t ? igb : ugb;

    int tid  = threadIdx.x;
    int warp = tid >> 5;
    int lane = tid & 31;
    int slot = warp >> 2;
    int nq   = warp & 3;

    if (tid < 128) gbs[tid] = gb[tid];

    unsigned int bfr[4][4][2];
    {
        int n = nq * 32 + (lane >> 2);
        int k0 = (lane & 3) * 2;
#pragma unroll
        for (int kt = 0; kt < 4; kt++) {
            int k = kt * 16 + k0;
#pragma unroll
            for (int nt = 0; nt < 4; nt++) {
                int nn = n + nt * 8;
                bfr[kt][nt][0] = bf2(W1[(size_t)k * 128 + nn],
                                     W1[(size_t)(k + 1) * 128 + nn]);
                bfr[kt][nt][1] = bf2(W1[(size_t)(k + 8) * 128 + nn],
                                     W1[(size_t)(k + 9) * 128 + nn]);
            }
        }
    }
    float w2v[4][2], bsv[4][2];
#pragma unroll
    for (int nt = 0; nt < 4; nt++) {
        int c = nq * 32 + nt * 8 + (lane & 3) * 2;
        w2v[nt][0] = W2[c];     w2v[nt][1] = W2[c + 1];
        bsv[nt][0] = b1[c];     bsv[nt][1] = b1[c + 1];
    }

    int s_slot = tid >> 7;
    int tid2   = tid & 127;
    int s_row  = tid2 >> 2;
    int s_colq = (tid2 & 3) * 16;

    int ld_row = lane & 15;
    int ld_off = (lane >> 4) * 16;

    float s = 0.0f;

    const int NITER = NN / 32;
    __syncthreads();
    for (int it = blockIdx.x; it < NITER; it += gridDim.x) {
        int row = it * 32 + s_row;
        const __half* zrow = g_z_h[2 * t + s_slot] + (size_t)row * 64 + s_colq;
        uint4 va = *(const uint4*)zrow;
        uint4 vb = *(const uint4*)(zrow + 8);
        unsigned int wv[8] = {va.x, va.y, va.z, va.w, vb.x, vb.y, vb.z, vb.w};
        unsigned int* drow = (unsigned int*)&tile[s_slot][s_row][0];
#pragma unroll
        for (int j = 0; j < 8; j++) {
            float2 f = __half22float2(*(__half2*)&wv[j]);
            int c = s_colq + 2 * j;
            drow[(s_colq >> 1) + j] =
                bf2(elu_fast(f.x + gbs[s_slot * 64 + c]),
                    elu_fast(f.y + gbs[s_slot * 64 + c + 1]));
        }
        __syncthreads();

#pragma unroll
        for (int mt = 0; mt < 2; mt++) {
            unsigned int a[4][4];
            const __nv_bfloat16* ap = &tile[slot][mt * 16 + ld_row][0];
            unsigned int abase = (unsigned int)__cvta_generic_to_shared(ap) + ld_off;
#pragma unroll
            for (int kt = 0; kt < 4; kt++) {
                asm volatile(
                    "ldmatrix.sync.aligned.m8n8.x4.shared.b16 {%0,%1,%2,%3}, [%4];"
                    : "=r"(a[kt][0]), "=r"(a[kt][1]), "=r"(a[kt][2]), "=r"(a[kt][3])
                    : "r"(abase + kt * 32));
            }
#pragma unroll
            for (int nt = 0; nt < 4; nt++) {
                float c0 = 0.f, c1 = 0.f, c2 = 0.f, c3 = 0.f;
#pragma unroll
                for (int kt = 0; kt < 4; kt++)
                    mma_bf16(c0, c1, c2, c3,
                             a[kt][0], a[kt][1], a[kt][2], a[kt][3],
                             bfr[kt][nt][0], bfr[kt][nt][1]);
                s += tanh_fast(c0 + bsv[nt][0]) * w2v[nt][0];
                s += tanh_fast(c1 + bsv[nt][1]) * w2v[nt][1];
                s += tanh_fast(c2 + bsv[nt][0]) * w2v[nt][0];
                s += tanh_fast(c3 + bsv[nt][1]) * w2v[nt][1];
            }
        }
        __syncthreads();
    }

#pragma unroll
    for (int off = 16; off > 0; off >>= 1)
        s += __shfl_xor_sync(0xffffffffu, s, off);
    if (lane == 0) wsum[warp] = s;
    __syncthreads();
    if (tid < 2) {
        float tot = wsum[tid * 4] + wsum[tid * 4 + 1]
                  + wsum[tid * 4 + 2] + wsum[tid * 4 + 3];
        atomicAdd(&g_w[2 * t + tid], tot);
    }
}

// ---------------- K6: gather + bias/ELU + beta + GEMM + ReLU + LN ------------
__global__ void __launch_bounds__(256) k_final(
    const int* __restrict__ user_idx, const int* __restrict__ item_idx,
    const int* __restrict__ neg_idx,
    const float* __restrict__ u_gb, const float* __restrict__ i_gb,
    const float* __restrict__ userW, const float* __restrict__ userb,
    const float* __restrict__ itemW, const float* __restrict__ itemb,
    const float* __restrict__ ln_g, const float* __restrict__ ln_b,
    float* __restrict__ out)
{
    __shared__ float Ws[4096];
    __shared__ float bs[64], gs[64], lbs[64];
    __shared__ float gb0[64], gb1[64];
    __shared__ float embs[4][64];
    __shared__ float red[4][2];

    int tid = threadIdx.x;
    int tx = tid & 63, ty = tid >> 6;
    int r0 = blockIdx.x * 4;
    bool isUser = (r0 < BB);
    const float* W    = isUser ? userW : itemW;
    const float* bias = isUser ? userb : itemb;
    const float* gbm  = isUser ? u_gb : i_gb;

    for (int i = tid; i < 4096; i += 256) Ws[i] = W[i];
    if (tid < 64) {
        bs[tid] = bias[tid]; gs[tid] = ln_g[tid]; lbs[tid] = ln_b[tid];
        gb0[tid] = gbm[tid]; gb1[tid] = gbm[64 + tid];
    }

    int r = r0 + ty;
    int type, idx;
    if (r < BB)            { type = 0; idx = user_idx[r]; }
    else if (r < 2 * BB)   { type = 1; idx = item_idx[r - BB]; }
    else                   { type = 1; idx = neg_idx[r - 2 * BB]; }

    float w0 = g_w[2 * type] * (1.0f / NN);
    float w1 = g_w[2 * type + 1] * (1.0f / NN);
    float mx = fmaxf(w0, w1);
    float e0 = __expf(w0 - mx), e1 = __expf(w1 - mx);
    float binv = 1.0f / (e0 + e1);
    float b0 = e0 * binv, b1 = e1 * binv;

    __syncthreads();
    float zr0 = __half2float(g_z_h[2 * type][(size_t)idx * 64 + tx]) + gb0[tx];
    float zr1 = __half2float(g_z_h[2 * type + 1][(size_t)idx * 64 + tx]) + gb1[tx];
    float emb = b0 * elu_fast(zr0) + b1 * elu_fast(zr1);
    embs[ty][tx] = emb;
    __syncthreads();

    float y = bs[tx];
#pragma unroll 16
    for (int k = 0; k < 64; k++) y += embs[ty][k] * Ws[k * 64 + tx];
    y = fmaxf(y, 0.0f);

    float s = y;
#pragma unroll
    for (int off = 16; off > 0; off >>= 1) s += __shfl_xor_sync(0xffffffffu, s, off);
    int half = tx >> 5;
    if ((tx & 31) == 0) red[ty][half] = s;
    __syncthreads();
    float mu = (red[ty][0] + red[ty][1]) * (1.0f / 64.0f);
    float dv = y - mu;
    float s2 = dv * dv;
#pragma unroll
    for (int off = 16; off > 0; off >>= 1) s2 += __shfl_xor_sync(0xffffffffu, s2, off);
    __syncthreads();
    if ((tx & 31) == 0) red[ty][half] = s2;
    __syncthreads();
    float var = (red[ty][0] + red[ty][1]) * (1.0f / 64.0f);
    float o = gs[tx] * dv * rsqrtf(var + 1e-5f) + lbs[tx];
    out[(size_t)r * 64 + tx] = o;
}

// ---------------- host ------------------------------------------------------
extern "C" void kernel_launch(void* const* d_in, const int* in_sizes, int n_in,
                              void* d_out, int out_size)
{
    const int*   user_idx  = (const int*)d_in[0];
    const int*   item_idx  = (const int*)d_in[1];
    const int*   neg_idx   = (const int*)d_in[2];
    const float* user_feat = (const float*)d_in[3];
    const float* item_feat = (const float*)d_in[4];
    const int*   u_src = (const int*)d_in[5];
    const int*   u_dst = (const int*)d_in[6];
    const int*   i_src = (const int*)d_in[7];
    const int*   i_dst = (const int*)d_in[8];
    const float* u_W  = (const float*)d_in[9];
    const float* u_al = (const float*)d_in[10];
    const float* u_ar = (const float*)d_in[11];
    const float* u_b  = (const float*)d_in[12];
    const float* i_W  = (const float*)d_in[13];
    const float* i_al = (const float*)d_in[14];
    const float* i_ar = (const float*)d_in[15];
    const float* i_b  = (const float*)d_in[16];
    const float* u_saW1 = (const float*)d_in[17];
    const float* u_sab1 = (const float*)d_in[18];
    const float* u_saW2 = (const float*)d_in[19];
    const float* i_saW1 = (const float*)d_in[20];
    const float* i_sab1 = (const float*)d_in[21];
    const float* i_saW2 = (const float*)d_in[22];
    const float* userW = (const float*)d_in[23];
    const float* userb = (const float*)d_in[24];
    const float* itemW = (const float*)d_in[25];
    const float* itemb = (const float*)d_in[26];
    const float* ln_g  = (const float*)d_in[27];
    const float* ln_b  = (const float*)d_in[28];
    float* out = (float*)d_out;

    cudaFuncSetAttribute(k_fused1,
                         cudaFuncAttributeMaxDynamicSharedMemorySize, K1F_SMEM);

    dim3 gridF(NGB + 2 * NHB, 2);                // 2736 x type
    dim3 gridS(NBLK, 4);                         // 391 x slot
    dim3 gridE((EE + 255) / 256, 2, 2);          // 1954 x m x type
    dim3 gridG((NN * 8 + 255) / 256, 4);         // 3125 x slot

    k_fused1<<<gridF, 256, K1F_SMEM>>>(user_feat, item_feat, u_W, i_W,
                                       u_al, i_al, u_ar, i_ar, u_dst, i_dst);
    k_scan<<<gridS, 256>>>();
    k_scatter<<<gridE, 256>>>(u_src, u_dst, i_src, i_dst);
    k_aggr<<<gridG, 256>>>();

    dim3 semGrid(256, 2);
    k_sem_mma<<<semGrid, 256>>>(u_saW1, u_sab1, u_saW2, u_b,
                                i_saW1, i_sab1, i_saW2, i_b);
    k_final<<<(3 * BB) / 4, 256>>>(user_idx, item_idx, neg_idx, u_b, i_b,
                                   userW, userb, itemW, itemb, ln_g, ln_b, out);
}